// round 1
// baseline (speedup 1.0000x reference)
#include <cuda_runtime.h>
#include <math.h>

#define T_SEQ 4096
#define C_DIM 2048
#define H_Q   16
#define KVH_  4
#define D_HEAD 128
#define QD (H_Q * D_HEAD)    // 2048
#define KD (KVH_ * D_HEAD)   // 512

// Scratch (allocation-free rule: device globals)
__device__ float g_q[T_SEQ * QD];
__device__ float g_k[T_SEQ * KD];
__device__ float g_v[T_SEQ * KD];
__device__ float g_att[T_SEQ * QD];

// ---------------------------------------------------------------------------
// Classic fp32 SGEMM: C[M,N] = A[M,K] @ B[K,N], all row-major.
// BM=BN=128, BK=8, 256 threads, 8x8 microtile, float4 everywhere.
// Requires M%128==0, N%128==0, K%8==0 (true for all our shapes).
// ---------------------------------------------------------------------------
__global__ __launch_bounds__(256) void sgemm_kernel(
    int M, int N, int K,
    const float* __restrict__ A, const float* __restrict__ B,
    float* __restrict__ C)
{
    const int BM = 128, BN = 128, BK = 8, TM = 8, TN = 8;
    __shared__ float As[BK][BM];
    __shared__ float Bs[BK][BN];

    const int tid  = threadIdx.x;
    const int tcol = tid & 15;        // 0..15
    const int trow = tid >> 4;        // 0..15
    const int arow = tid >> 1;        // 0..127
    const int acol = (tid & 1) * 4;   // 0 or 4
    const int brow = tid >> 5;        // 0..7
    const int bcol = (tid & 31) * 4;  // 0..124

    const float* Ag = A + (size_t)blockIdx.y * BM * K;
    const float* Bg = B + (size_t)blockIdx.x * BN;

    float acc[TM][TN];
    #pragma unroll
    for (int i = 0; i < TM; i++)
        #pragma unroll
        for (int j = 0; j < TN; j++) acc[i][j] = 0.f;

    for (int k0 = 0; k0 < K; k0 += BK) {
        float4 a4 = *(const float4*)(Ag + (size_t)arow * K + k0 + acol);
        As[acol + 0][arow] = a4.x;
        As[acol + 1][arow] = a4.y;
        As[acol + 2][arow] = a4.z;
        As[acol + 3][arow] = a4.w;
        *(float4*)&Bs[brow][bcol] =
            *(const float4*)(Bg + (size_t)(k0 + brow) * N + bcol);
        __syncthreads();

        #pragma unroll
        for (int kk = 0; kk < BK; kk++) {
            float4 ra0 = *(float4*)&As[kk][trow * TM];
            float4 ra1 = *(float4*)&As[kk][trow * TM + 4];
            float4 rb0 = *(float4*)&Bs[kk][tcol * TN];
            float4 rb1 = *(float4*)&Bs[kk][tcol * TN + 4];
            float ra[8] = {ra0.x, ra0.y, ra0.z, ra0.w, ra1.x, ra1.y, ra1.z, ra1.w};
            float rb[8] = {rb0.x, rb0.y, rb0.z, rb0.w, rb1.x, rb1.y, rb1.z, rb1.w};
            #pragma unroll
            for (int i = 0; i < TM; i++)
                #pragma unroll
                for (int j = 0; j < TN; j++)
                    acc[i][j] += ra[i] * rb[j];
        }
        __syncthreads();
    }

    float* Cg = C + (size_t)(blockIdx.y * BM + trow * TM) * N + blockIdx.x * BN + tcol * TN;
    #pragma unroll
    for (int i = 0; i < TM; i++) {
        *(float4*)(Cg + (size_t)i * N + 0) =
            make_float4(acc[i][0], acc[i][1], acc[i][2], acc[i][3]);
        *(float4*)(Cg + (size_t)i * N + 4) =
            make_float4(acc[i][4], acc[i][5], acc[i][6], acc[i][7]);
    }
}

// ---------------------------------------------------------------------------
// RoPE (interleaved pairs), in place. heads = H_Q for q, KVH_ for k.
// inv-freq computed in fp64 then rounded to f32; angle = t * inv in f32
// (matching the reference's f32 pipeline), cosf/sinf do full range reduction.
// ---------------------------------------------------------------------------
__global__ void rope_kernel(float* __restrict__ buf, int heads)
{
    int i = blockIdx.x * blockDim.x + threadIdx.x;
    int total = T_SEQ * heads * (D_HEAD / 2);
    if (i >= total) return;
    int d2 = i & 63;
    int hh = (i >> 6) % heads;
    int t  = i / (64 * heads);

    // log(10000)/64
    double inv_d = exp(-(double)d2 * 0.14391156831212787);
    float inv = (float)inv_d;
    float ang = (float)t * inv;
    float c = cosf(ang), s = sinf(ang);

    float* p = buf + ((size_t)t * heads + hh) * D_HEAD + 2 * d2;
    float x0 = p[0], x1 = p[1];
    p[0] = x0 * c - x1 * s;
    p[1] = x0 * s + x1 * c;
}

// ---------------------------------------------------------------------------
// Flash attention, fp32, causal, GQA (kv head = h/4).
// Block = (64 q-rows, one q-head). 256 threads. Online softmax.
// Smem: Q[64x132] K[64x132] V[64x128] S[64x68] + m/l/alpha.
// ---------------------------------------------------------------------------
#define BQ 64
#define BKV 64
#define QKPAD 132
#define SPAD 68

__global__ __launch_bounds__(256) void flash_kernel(
    const float* __restrict__ q, const float* __restrict__ k,
    const float* __restrict__ v, float* __restrict__ o)
{
    extern __shared__ float sm[];
    float* Qs   = sm;                       // BQ * QKPAD
    float* Ks   = Qs + BQ * QKPAD;          // BKV * QKPAD
    float* Vs   = Ks + BKV * QKPAD;         // BKV * 128
    float* Ss   = Vs + BKV * 128;           // BQ * SPAD
    float* mrow = Ss + BQ * SPAD;           // BQ
    float* lrow = mrow + BQ;                // BQ
    float* arow = lrow + BQ;                // BQ

    const int tid = threadIdx.x;
    const int qb  = blockIdx.x;
    const int h   = blockIdx.y;
    const int kvh = h / (H_Q / KVH_);
    const int q0  = qb * BQ;
    const float scale = 0.08838834764831845f;  // 1/sqrt(128)

    // load Q tile once
    for (int i = tid; i < BQ * 32; i += 256) {
        int r = i >> 5, c = (i & 31) * 4;
        *(float4*)&Qs[r * QKPAD + c] =
            *(const float4*)(q + (size_t)(q0 + r) * QD + h * D_HEAD + c);
    }
    if (tid < BQ) { mrow[tid] = -1e30f; lrow[tid] = 0.f; }

    const int ty = tid >> 4, tx = tid & 15;
    float acc[4][8];
    #pragma unroll
    for (int i = 0; i < 4; i++)
        #pragma unroll
        for (int j = 0; j < 8; j++) acc[i][j] = 0.f;

    const int nkb = qb + 1;  // causal: only j <= qb
    for (int jb = 0; jb < nkb; jb++) {
        __syncthreads();  // protects Ks/Vs/Ss reuse and first-iter Q/m init
        const int k0 = jb * BKV;
        for (int i = tid; i < BKV * 32; i += 256) {
            int r = i >> 5, c = (i & 31) * 4;
            const float* kp = k + (size_t)(k0 + r) * KD + kvh * D_HEAD + c;
            const float* vp = v + (size_t)(k0 + r) * KD + kvh * D_HEAD + c;
            *(float4*)&Ks[r * QKPAD + c] = *(const float4*)kp;
            *(float4*)&Vs[r * 128 + c]   = *(const float4*)vp;
        }
        __syncthreads();

        // S = scale * Q K^T  (thread: 4x4 microtile)
        float s[4][4];
        #pragma unroll
        for (int i = 0; i < 4; i++)
            #pragma unroll
            for (int j = 0; j < 4; j++) s[i][j] = 0.f;
        #pragma unroll 4
        for (int kk = 0; kk < D_HEAD; kk++) {
            float qa[4], kb[4];
            #pragma unroll
            for (int i = 0; i < 4; i++) qa[i] = Qs[(ty * 4 + i) * QKPAD + kk];
            #pragma unroll
            for (int j = 0; j < 4; j++) kb[j] = Ks[(tx * 4 + j) * QKPAD + kk];
            #pragma unroll
            for (int i = 0; i < 4; i++)
                #pragma unroll
                for (int j = 0; j < 4; j++)
                    s[i][j] += qa[i] * kb[j];
        }
        const bool diag = (jb == qb);
        #pragma unroll
        for (int i = 0; i < 4; i++)
            #pragma unroll
            for (int j = 0; j < 4; j++) {
                float val = s[i][j] * scale;
                if (diag && (k0 + tx * 4 + j) > (q0 + ty * 4 + i)) val = -1e30f;
                Ss[(ty * 4 + i) * SPAD + tx * 4 + j] = val;
            }
        __syncthreads();

        // online softmax, one thread per row
        if (tid < BQ) {
            const int r = tid;
            float m_old = mrow[r];
            float m_new = m_old;
            #pragma unroll 8
            for (int c = 0; c < BKV; c++) m_new = fmaxf(m_new, Ss[r * SPAD + c]);
            float alpha = __expf(m_old - m_new);
            float rs = 0.f;
            #pragma unroll 8
            for (int c = 0; c < BKV; c++) {
                float p = __expf(Ss[r * SPAD + c] - m_new);
                Ss[r * SPAD + c] = p;
                rs += p;
            }
            mrow[r] = m_new;
            lrow[r] = lrow[r] * alpha + rs;
            arow[r] = alpha;
        }
        __syncthreads();

        // O = O*alpha + P @ V   (thread: 4 rows x 8 cols)
        float al[4];
        #pragma unroll
        for (int i = 0; i < 4; i++) al[i] = arow[ty * 4 + i];
        #pragma unroll
        for (int i = 0; i < 4; i++)
            #pragma unroll
            for (int j = 0; j < 8; j++) acc[i][j] *= al[i];
        #pragma unroll 2
        for (int kk = 0; kk < BKV; kk++) {
            float pv[4];
            #pragma unroll
            for (int i = 0; i < 4; i++) pv[i] = Ss[(ty * 4 + i) * SPAD + kk];
            float4 v0 = *(float4*)&Vs[kk * 128 + tx * 8];
            float4 v1 = *(float4*)&Vs[kk * 128 + tx * 8 + 4];
            float vb[8] = {v0.x, v0.y, v0.z, v0.w, v1.x, v1.y, v1.z, v1.w};
            #pragma unroll
            for (int i = 0; i < 4; i++)
                #pragma unroll
                for (int j = 0; j < 8; j++)
                    acc[i][j] += pv[i] * vb[j];
        }
    }

    // final normalize + store
    #pragma unroll
    for (int i = 0; i < 4; i++) {
        float invl = 1.0f / lrow[ty * 4 + i];
        int r = q0 + ty * 4 + i;
        float* op = o + (size_t)r * QD + h * D_HEAD + tx * 8;
        *(float4*)(op + 0) = make_float4(acc[i][0] * invl, acc[i][1] * invl,
                                         acc[i][2] * invl, acc[i][3] * invl);
        *(float4*)(op + 4) = make_float4(acc[i][4] * invl, acc[i][5] * invl,
                                         acc[i][6] * invl, acc[i][7] * invl);
    }
}

// ---------------------------------------------------------------------------
extern "C" void kernel_launch(void* const* d_in, const int* in_sizes, int n_in,
                              void* d_out, int out_size)
{
    const float* x  = (const float*)d_in[0];
    // d_in[1] = mask (tril) — causality hardcoded, ignored.
    const float* Wq = (const float*)d_in[2];
    const float* Wk = (const float*)d_in[3];
    const float* Wv = (const float*)d_in[4];
    const float* Wo = (const float*)d_in[5];
    float* out = (float*)d_out;

    float *q, *k, *v, *att;
    cudaGetSymbolAddress((void**)&q,   g_q);
    cudaGetSymbolAddress((void**)&k,   g_k);
    cudaGetSymbolAddress((void**)&v,   g_v);
    cudaGetSymbolAddress((void**)&att, g_att);

    // 1. projections
    sgemm_kernel<<<dim3(QD / 128, T_SEQ / 128), 256>>>(T_SEQ, QD, C_DIM, x, Wq, q);
    sgemm_kernel<<<dim3(KD / 128, T_SEQ / 128), 256>>>(T_SEQ, KD, C_DIM, x, Wk, k);
    sgemm_kernel<<<dim3(KD / 128, T_SEQ / 128), 256>>>(T_SEQ, KD, C_DIM, x, Wv, v);

    // 2. RoPE on q and k
    {
        int tq = T_SEQ * H_Q * (D_HEAD / 2);
        rope_kernel<<<(tq + 255) / 256, 256>>>(q, H_Q);
        int tk = T_SEQ * KVH_ * (D_HEAD / 2);
        rope_kernel<<<(tk + 255) / 256, 256>>>(k, KVH_);
    }

    // 3. flash attention
    {
        int smem = (BQ * QKPAD + BKV * QKPAD + BKV * 128 + BQ * SPAD + 3 * BQ)
                   * (int)sizeof(float);
        cudaFuncSetAttribute(flash_kernel,
                             cudaFuncAttributeMaxDynamicSharedMemorySize, smem);
        flash_kernel<<<dim3(T_SEQ / BQ, H_Q), 256, smem>>>(q, k, v, att);
    }

    // 4. output projection
    sgemm_kernel<<<dim3(C_DIM / 128, T_SEQ / 128), 256>>>(T_SEQ, C_DIM, QD, att, Wo, out);
}

// round 2
// speedup vs baseline: 1.2781x; 1.2781x over previous
#include <cuda_runtime.h>
#include <cuda_bf16.h>
#include <math.h>

#define T_SEQ 4096
#define C_DIM 2048
#define H_Q   16
#define KVH_  4
#define D_HEAD 128
#define QD (H_Q * D_HEAD)    // 2048
#define KD (KVH_ * D_HEAD)   // 512

// Scratch (allocation-free rule: device globals)
__device__ float g_q[T_SEQ * QD];
__device__ float g_k[T_SEQ * KD];
__device__ float g_v[T_SEQ * KD];
__device__ float g_att[T_SEQ * QD];

// ===========================================================================
// bf16x3 tensor-core GEMM:  C[M,N] = A[M,K] @ B[K,N], row-major, fp32 in/out.
// Each fp32 value is split a = hi + lo (both bf16); product accumulated as
// hi*hi + hi*lo + lo*hi in fp32 accumulators (mma.sync.m16n8k16).
// Block tile 128x128x32, 256 threads (8 warps, 2x4 warp grid, 64x32 per warp).
// Requires M%128==0, N%128==0, K%32==0.
// ===========================================================================
#define AS_STRIDE 40    // halfs per A row (32 + 8 pad) -> 80B, ldmatrix conflict-free
#define BS_STRIDE 136   // halfs per B row (128 + 8 pad) -> 272B, conflict-free

__device__ __forceinline__ unsigned smem_u32(const void* p) {
    return (unsigned)__cvta_generic_to_shared(p);
}

__device__ __forceinline__ void ldsm_x4(unsigned addr, unsigned* r) {
    asm volatile("ldmatrix.sync.aligned.m8n8.x4.shared.b16 {%0,%1,%2,%3}, [%4];\n"
                 : "=r"(r[0]), "=r"(r[1]), "=r"(r[2]), "=r"(r[3]) : "r"(addr));
}
__device__ __forceinline__ void ldsm_x4_t(unsigned addr, unsigned* r) {
    asm volatile("ldmatrix.sync.aligned.m8n8.x4.trans.shared.b16 {%0,%1,%2,%3}, [%4];\n"
                 : "=r"(r[0]), "=r"(r[1]), "=r"(r[2]), "=r"(r[3]) : "r"(addr));
}
__device__ __forceinline__ void mma_bf16(float* d, const unsigned* a, const unsigned* b) {
    asm volatile("mma.sync.aligned.m16n8k16.row.col.f32.bf16.bf16.f32 "
                 "{%0,%1,%2,%3}, {%4,%5,%6,%7}, {%8,%9}, {%0,%1,%2,%3};\n"
                 : "+f"(d[0]), "+f"(d[1]), "+f"(d[2]), "+f"(d[3])
                 : "r"(a[0]), "r"(a[1]), "r"(a[2]), "r"(a[3]),
                   "r"(b[0]), "r"(b[1]));
}

// split 4 consecutive fp32 into bf16 hi/lo planes (2x bf16x2 stores each)
__device__ __forceinline__ void split_store4(float4 v, __nv_bfloat16* hi, __nv_bfloat16* lo) {
    __nv_bfloat16 h0 = __float2bfloat16_rn(v.x);
    __nv_bfloat16 h1 = __float2bfloat16_rn(v.y);
    __nv_bfloat16 h2 = __float2bfloat16_rn(v.z);
    __nv_bfloat16 h3 = __float2bfloat16_rn(v.w);
    __nv_bfloat16 l0 = __float2bfloat16_rn(v.x - __bfloat162float(h0));
    __nv_bfloat16 l1 = __float2bfloat16_rn(v.y - __bfloat162float(h1));
    __nv_bfloat16 l2 = __float2bfloat16_rn(v.z - __bfloat162float(h2));
    __nv_bfloat16 l3 = __float2bfloat16_rn(v.w - __bfloat162float(h3));
    *(__nv_bfloat162*)(hi)     = __halves2bfloat162(h0, h1);
    *(__nv_bfloat162*)(hi + 2) = __halves2bfloat162(h2, h3);
    *(__nv_bfloat162*)(lo)     = __halves2bfloat162(l0, l1);
    *(__nv_bfloat162*)(lo + 2) = __halves2bfloat162(l2, l3);
}

__global__ __launch_bounds__(256) void gemm_bf16x3_kernel(
    int M, int N, int K,
    const float* __restrict__ A, const float* __restrict__ B,
    float* __restrict__ C)
{
    __shared__ __nv_bfloat16 As_hi[128 * AS_STRIDE];
    __shared__ __nv_bfloat16 As_lo[128 * AS_STRIDE];
    __shared__ __nv_bfloat16 Bs_hi[32 * BS_STRIDE];
    __shared__ __nv_bfloat16 Bs_lo[32 * BS_STRIDE];

    const int tid  = threadIdx.x;
    const int lane = tid & 31;
    const int wid  = tid >> 5;
    const int wm   = wid >> 2;   // 0..1
    const int wn   = wid & 3;    // 0..3
    const int bm0  = blockIdx.y * 128;
    const int bn0  = blockIdx.x * 128;

    // staging thread mapping
    const int ar = tid >> 3;            // A row 0..31 (+32 per i)
    const int ac = (tid & 7) * 4;       // A col 0..28
    const int br = tid >> 5;            // B row 0..7  (+8 per i)
    const int bc = (tid & 31) * 4;      // B col 0..124

    float acc[4][4][4];
    #pragma unroll
    for (int mi = 0; mi < 4; mi++)
        #pragma unroll
        for (int ni = 0; ni < 4; ni++)
            #pragma unroll
            for (int e = 0; e < 4; e++) acc[mi][ni][e] = 0.f;

    const int ktiles = K >> 5;

    // prologue: stage first k-tile into registers
    float4 ra[4], rb[4];
    #pragma unroll
    for (int i = 0; i < 4; i++) {
        ra[i] = *(const float4*)(A + (size_t)(bm0 + ar + i * 32) * K + ac);
        rb[i] = *(const float4*)(B + (size_t)(br + i * 8) * N + bn0 + bc);
    }

    for (int kt = 0; kt < ktiles; kt++) {
        // commit staged registers to smem (split into hi/lo planes)
        #pragma unroll
        for (int i = 0; i < 4; i++) {
            int r = ar + i * 32;
            split_store4(ra[i], &As_hi[r * AS_STRIDE + ac], &As_lo[r * AS_STRIDE + ac]);
            int rB = br + i * 8;
            split_store4(rb[i], &Bs_hi[rB * BS_STRIDE + bc], &Bs_lo[rB * BS_STRIDE + bc]);
        }
        __syncthreads();

        // prefetch next k-tile
        if (kt + 1 < ktiles) {
            int k0 = (kt + 1) << 5;
            #pragma unroll
            for (int i = 0; i < 4; i++) {
                ra[i] = *(const float4*)(A + (size_t)(bm0 + ar + i * 32) * K + k0 + ac);
                rb[i] = *(const float4*)(B + (size_t)(k0 + br + i * 8) * N + bn0 + bc);
            }
        }

        #pragma unroll
        for (int ks = 0; ks < 2; ks++) {
            const int k = ks * 16;
            unsigned ah[4][4], al[4][4], bh[4][2], bl[4][2];

            const int arl = wm * 64 + (lane & 15);
            const int kcl = k + (lane >> 4) * 8;
            #pragma unroll
            for (int mi = 0; mi < 4; mi++) {
                ldsm_x4(smem_u32(&As_hi[(arl + mi * 16) * AS_STRIDE + kcl]), ah[mi]);
                ldsm_x4(smem_u32(&As_lo[(arl + mi * 16) * AS_STRIDE + kcl]), al[mi]);
            }
            const int krw = k + ((lane >> 3) & 1) * 8 + (lane & 7);
            #pragma unroll
            for (int nb = 0; nb < 2; nb++) {
                const int ncl = wn * 32 + nb * 16 + (lane >> 4) * 8;
                unsigned r[4];
                ldsm_x4_t(smem_u32(&Bs_hi[krw * BS_STRIDE + ncl]), r);
                bh[2 * nb][0] = r[0]; bh[2 * nb][1] = r[1];
                bh[2 * nb + 1][0] = r[2]; bh[2 * nb + 1][1] = r[3];
                ldsm_x4_t(smem_u32(&Bs_lo[krw * BS_STRIDE + ncl]), r);
                bl[2 * nb][0] = r[0]; bl[2 * nb][1] = r[1];
                bl[2 * nb + 1][0] = r[2]; bl[2 * nb + 1][1] = r[3];
            }

            #pragma unroll
            for (int mi = 0; mi < 4; mi++)
                #pragma unroll
                for (int ni = 0; ni < 4; ni++) {
                    mma_bf16(acc[mi][ni], ah[mi], bh[ni]);
                    mma_bf16(acc[mi][ni], ah[mi], bl[ni]);
                    mma_bf16(acc[mi][ni], al[mi], bh[ni]);
                }
        }
        __syncthreads();
    }

    // epilogue
    const int gid = lane >> 2, tig = lane & 3;
    #pragma unroll
    for (int mi = 0; mi < 4; mi++)
        #pragma unroll
        for (int ni = 0; ni < 4; ni++) {
            int r0 = bm0 + wm * 64 + mi * 16 + gid;
            int c0 = bn0 + wn * 32 + ni * 8 + tig * 2;
            *(float2*)(C + (size_t)r0 * N + c0) =
                make_float2(acc[mi][ni][0], acc[mi][ni][1]);
            *(float2*)(C + (size_t)(r0 + 8) * N + c0) =
                make_float2(acc[mi][ni][2], acc[mi][ni][3]);
        }
}

// ---------------------------------------------------------------------------
// RoPE (interleaved pairs), in place.
// ---------------------------------------------------------------------------
__global__ void rope_kernel(float* __restrict__ buf, int heads)
{
    int i = blockIdx.x * blockDim.x + threadIdx.x;
    int total = T_SEQ * heads * (D_HEAD / 2);
    if (i >= total) return;
    int d2 = i & 63;
    int hh = (i >> 6) % heads;
    int t  = i / (64 * heads);

    double inv_d = exp(-(double)d2 * 0.14391156831212787);  // ln(10000)/64
    float inv = (float)inv_d;
    float ang = (float)t * inv;
    float c = cosf(ang), s = sinf(ang);

    float* p = buf + ((size_t)t * heads + hh) * D_HEAD + 2 * d2;
    float x0 = p[0], x1 = p[1];
    p[0] = x0 * c - x1 * s;
    p[1] = x0 * s + x1 * c;
}

// ---------------------------------------------------------------------------
// Flash attention, fp32, causal, GQA (kv head = h/4). (unchanged this round)
// ---------------------------------------------------------------------------
#define BQ 64
#define BKV 64
#define QKPAD 132
#define SPAD 68

__global__ __launch_bounds__(256) void flash_kernel(
    const float* __restrict__ q, const float* __restrict__ k,
    const float* __restrict__ v, float* __restrict__ o)
{
    extern __shared__ float sm[];
    float* Qs   = sm;
    float* Ks   = Qs + BQ * QKPAD;
    float* Vs   = Ks + BKV * QKPAD;
    float* Ss   = Vs + BKV * 128;
    float* mrow = Ss + BQ * SPAD;
    float* lrow = mrow + BQ;
    float* arow = lrow + BQ;

    const int tid = threadIdx.x;
    const int qb  = blockIdx.x;
    const int h   = blockIdx.y;
    const int kvh = h / (H_Q / KVH_);
    const int q0  = qb * BQ;
    const float scale = 0.08838834764831845f;

    for (int i = tid; i < BQ * 32; i += 256) {
        int r = i >> 5, c = (i & 31) * 4;
        *(float4*)&Qs[r * QKPAD + c] =
            *(const float4*)(q + (size_t)(q0 + r) * QD + h * D_HEAD + c);
    }
    if (tid < BQ) { mrow[tid] = -1e30f; lrow[tid] = 0.f; }

    const int ty = tid >> 4, tx = tid & 15;
    float acc[4][8];
    #pragma unroll
    for (int i = 0; i < 4; i++)
        #pragma unroll
        for (int j = 0; j < 8; j++) acc[i][j] = 0.f;

    const int nkb = qb + 1;
    for (int jb = 0; jb < nkb; jb++) {
        __syncthreads();
        const int k0 = jb * BKV;
        for (int i = tid; i < BKV * 32; i += 256) {
            int r = i >> 5, c = (i & 31) * 4;
            const float* kp = k + (size_t)(k0 + r) * KD + kvh * D_HEAD + c;
            const float* vp = v + (size_t)(k0 + r) * KD + kvh * D_HEAD + c;
            *(float4*)&Ks[r * QKPAD + c] = *(const float4*)kp;
            *(float4*)&Vs[r * 128 + c]   = *(const float4*)vp;
        }
        __syncthreads();

        float s[4][4];
        #pragma unroll
        for (int i = 0; i < 4; i++)
            #pragma unroll
            for (int j = 0; j < 4; j++) s[i][j] = 0.f;
        #pragma unroll 4
        for (int kk = 0; kk < D_HEAD; kk++) {
            float qa[4], kb[4];
            #pragma unroll
            for (int i = 0; i < 4; i++) qa[i] = Qs[(ty * 4 + i) * QKPAD + kk];
            #pragma unroll
            for (int j = 0; j < 4; j++) kb[j] = Ks[(tx * 4 + j) * QKPAD + kk];
            #pragma unroll
            for (int i = 0; i < 4; i++)
                #pragma unroll
                for (int j = 0; j < 4; j++)
                    s[i][j] += qa[i] * kb[j];
        }
        const bool diag = (jb == qb);
        #pragma unroll
        for (int i = 0; i < 4; i++)
            #pragma unroll
            for (int j = 0; j < 4; j++) {
                float val = s[i][j] * scale;
                if (diag && (k0 + tx * 4 + j) > (q0 + ty * 4 + i)) val = -1e30f;
                Ss[(ty * 4 + i) * SPAD + tx * 4 + j] = val;
            }
        __syncthreads();

        if (tid < BQ) {
            const int r = tid;
            float m_old = mrow[r];
            float m_new = m_old;
            #pragma unroll 8
            for (int c = 0; c < BKV; c++) m_new = fmaxf(m_new, Ss[r * SPAD + c]);
            float alpha = __expf(m_old - m_new);
            float rs = 0.f;
            #pragma unroll 8
            for (int c = 0; c < BKV; c++) {
                float p = __expf(Ss[r * SPAD + c] - m_new);
                Ss[r * SPAD + c] = p;
                rs += p;
            }
            mrow[r] = m_new;
            lrow[r] = lrow[r] * alpha + rs;
            arow[r] = alpha;
        }
        __syncthreads();

        float al[4];
        #pragma unroll
        for (int i = 0; i < 4; i++) al[i] = arow[ty * 4 + i];
        #pragma unroll
        for (int i = 0; i < 4; i++)
            #pragma unroll
            for (int j = 0; j < 8; j++) acc[i][j] *= al[i];
        #pragma unroll 2
        for (int kk = 0; kk < BKV; kk++) {
            float pv[4];
            #pragma unroll
            for (int i = 0; i < 4; i++) pv[i] = Ss[(ty * 4 + i) * SPAD + kk];
            float4 v0 = *(float4*)&Vs[kk * 128 + tx * 8];
            float4 v1 = *(float4*)&Vs[kk * 128 + tx * 8 + 4];
            float vb[8] = {v0.x, v0.y, v0.z, v0.w, v1.x, v1.y, v1.z, v1.w};
            #pragma unroll
            for (int i = 0; i < 4; i++)
                #pragma unroll
                for (int j = 0; j < 8; j++)
                    acc[i][j] += pv[i] * vb[j];
        }
    }

    #pragma unroll
    for (int i = 0; i < 4; i++) {
        float invl = 1.0f / lrow[ty * 4 + i];
        int r = q0 + ty * 4 + i;
        float* op = o + (size_t)r * QD + h * D_HEAD + tx * 8;
        *(float4*)(op + 0) = make_float4(acc[i][0] * invl, acc[i][1] * invl,
                                         acc[i][2] * invl, acc[i][3] * invl);
        *(float4*)(op + 4) = make_float4(acc[i][4] * invl, acc[i][5] * invl,
                                         acc[i][6] * invl, acc[i][7] * invl);
    }
}

// ---------------------------------------------------------------------------
extern "C" void kernel_launch(void* const* d_in, const int* in_sizes, int n_in,
                              void* d_out, int out_size)
{
    const float* x  = (const float*)d_in[0];
    // d_in[1] = mask (tril) — causality hardcoded, ignored.
    const float* Wq = (const float*)d_in[2];
    const float* Wk = (const float*)d_in[3];
    const float* Wv = (const float*)d_in[4];
    const float* Wo = (const float*)d_in[5];
    float* out = (float*)d_out;

    float *q, *k, *v, *att;
    cudaGetSymbolAddress((void**)&q,   g_q);
    cudaGetSymbolAddress((void**)&k,   g_k);
    cudaGetSymbolAddress((void**)&v,   g_v);
    cudaGetSymbolAddress((void**)&att, g_att);

    // 1. projections (tensor cores, bf16x3)
    gemm_bf16x3_kernel<<<dim3(QD / 128, T_SEQ / 128), 256>>>(T_SEQ, QD, C_DIM, x, Wq, q);
    gemm_bf16x3_kernel<<<dim3(KD / 128, T_SEQ / 128), 256>>>(T_SEQ, KD, C_DIM, x, Wk, k);
    gemm_bf16x3_kernel<<<dim3(KD / 128, T_SEQ / 128), 256>>>(T_SEQ, KD, C_DIM, x, Wv, v);

    // 2. RoPE on q and k
    {
        int tq = T_SEQ * H_Q * (D_HEAD / 2);
        rope_kernel<<<(tq + 255) / 256, 256>>>(q, H_Q);
        int tk = T_SEQ * KVH_ * (D_HEAD / 2);
        rope_kernel<<<(tk + 255) / 256, 256>>>(k, KVH_);
    }

    // 3. flash attention
    {
        int smem = (BQ * QKPAD + BKV * QKPAD + BKV * 128 + BQ * SPAD + 3 * BQ)
                   * (int)sizeof(float);
        cudaFuncSetAttribute(flash_kernel,
                             cudaFuncAttributeMaxDynamicSharedMemorySize, smem);
        flash_kernel<<<dim3(T_SEQ / BQ, H_Q), 256, smem>>>(q, k, v, att);
    }

    // 4. output projection (tensor cores, bf16x3)
    gemm_bf16x3_kernel<<<dim3(C_DIM / 128, T_SEQ / 128), 256>>>(T_SEQ, C_DIM, QD, att, Wo, out);
}

// round 4
// speedup vs baseline: 3.2514x; 2.5440x over previous
#include <cuda_runtime.h>
#include <cuda_bf16.h>
#include <math.h>

#define T_SEQ 4096
#define C_DIM 2048
#define H_Q   16
#define KVH_  4
#define D_HEAD 128
#define QD (H_Q * D_HEAD)    // 2048
#define KD (KVH_ * D_HEAD)   // 512

// Scratch (allocation-free rule: device globals)
__device__ float g_q[T_SEQ * QD];
__device__ float g_k[T_SEQ * KD];
__device__ float g_v[T_SEQ * KD];
__device__ float g_att[T_SEQ * QD];

__device__ __forceinline__ unsigned smem_u32(const void* p) {
    return (unsigned)__cvta_generic_to_shared(p);
}
__device__ __forceinline__ void ldsm_x4(unsigned addr, unsigned* r) {
    asm volatile("ldmatrix.sync.aligned.m8n8.x4.shared.b16 {%0,%1,%2,%3}, [%4];\n"
                 : "=r"(r[0]), "=r"(r[1]), "=r"(r[2]), "=r"(r[3]) : "r"(addr));
}
__device__ __forceinline__ void ldsm_x4_t(unsigned addr, unsigned* r) {
    asm volatile("ldmatrix.sync.aligned.m8n8.x4.trans.shared.b16 {%0,%1,%2,%3}, [%4];\n"
                 : "=r"(r[0]), "=r"(r[1]), "=r"(r[2]), "=r"(r[3]) : "r"(addr));
}
__device__ __forceinline__ void mma_bf16(float* d, const unsigned* a, const unsigned* b) {
    asm volatile("mma.sync.aligned.m16n8k16.row.col.f32.bf16.bf16.f32 "
                 "{%0,%1,%2,%3}, {%4,%5,%6,%7}, {%8,%9}, {%0,%1,%2,%3};\n"
                 : "+f"(d[0]), "+f"(d[1]), "+f"(d[2]), "+f"(d[3])
                 : "r"(a[0]), "r"(a[1]), "r"(a[2]), "r"(a[3]),
                   "r"(b[0]), "r"(b[1]));
}
__device__ __forceinline__ void split_store4(float4 v, __nv_bfloat16* hi, __nv_bfloat16* lo) {
    __nv_bfloat16 h0 = __float2bfloat16_rn(v.x);
    __nv_bfloat16 h1 = __float2bfloat16_rn(v.y);
    __nv_bfloat16 h2 = __float2bfloat16_rn(v.z);
    __nv_bfloat16 h3 = __float2bfloat16_rn(v.w);
    __nv_bfloat16 l0 = __float2bfloat16_rn(v.x - __bfloat162float(h0));
    __nv_bfloat16 l1 = __float2bfloat16_rn(v.y - __bfloat162float(h1));
    __nv_bfloat16 l2 = __float2bfloat16_rn(v.z - __bfloat162float(h2));
    __nv_bfloat16 l3 = __float2bfloat16_rn(v.w - __bfloat162float(h3));
    *(__nv_bfloat162*)(hi)     = __halves2bfloat162(h0, h1);
    *(__nv_bfloat162*)(hi + 2) = __halves2bfloat162(h2, h3);
    *(__nv_bfloat162*)(lo)     = __halves2bfloat162(l0, l1);
    *(__nv_bfloat162*)(lo + 2) = __halves2bfloat162(l2, l3);
}

// ===========================================================================
// bf16x3 tensor-core GEMM:  C[M,N] = A[M,K] @ B[K,N], row-major, fp32 in/out.
// Block tile 128x128x32, 256 threads (8 warps, 2x4 warp grid, 64x32 per warp).
// ===========================================================================
#define AS_STRIDE 40
#define BS_STRIDE 136

__global__ __launch_bounds__(256) void gemm_bf16x3_kernel(
    int M, int N, int K,
    const float* __restrict__ A, const float* __restrict__ B,
    float* __restrict__ C)
{
    __shared__ __nv_bfloat16 As_hi[128 * AS_STRIDE];
    __shared__ __nv_bfloat16 As_lo[128 * AS_STRIDE];
    __shared__ __nv_bfloat16 Bs_hi[32 * BS_STRIDE];
    __shared__ __nv_bfloat16 Bs_lo[32 * BS_STRIDE];

    const int tid  = threadIdx.x;
    const int lane = tid & 31;
    const int wid  = tid >> 5;
    const int wm   = wid >> 2;
    const int wn   = wid & 3;
    const int bm0  = blockIdx.y * 128;
    const int bn0  = blockIdx.x * 128;

    const int ar = tid >> 3;
    const int ac = (tid & 7) * 4;
    const int br = tid >> 5;
    const int bc = (tid & 31) * 4;

    float acc[4][4][4];
    #pragma unroll
    for (int mi = 0; mi < 4; mi++)
        #pragma unroll
        for (int ni = 0; ni < 4; ni++)
            #pragma unroll
            for (int e = 0; e < 4; e++) acc[mi][ni][e] = 0.f;

    const int ktiles = K >> 5;

    float4 ra[4], rb[4];
    #pragma unroll
    for (int i = 0; i < 4; i++) {
        ra[i] = *(const float4*)(A + (size_t)(bm0 + ar + i * 32) * K + ac);
        rb[i] = *(const float4*)(B + (size_t)(br + i * 8) * N + bn0 + bc);
    }

    for (int kt = 0; kt < ktiles; kt++) {
        #pragma unroll
        for (int i = 0; i < 4; i++) {
            int r = ar + i * 32;
            split_store4(ra[i], &As_hi[r * AS_STRIDE + ac], &As_lo[r * AS_STRIDE + ac]);
            int rB = br + i * 8;
            split_store4(rb[i], &Bs_hi[rB * BS_STRIDE + bc], &Bs_lo[rB * BS_STRIDE + bc]);
        }
        __syncthreads();

        if (kt + 1 < ktiles) {
            int k0 = (kt + 1) << 5;
            #pragma unroll
            for (int i = 0; i < 4; i++) {
                ra[i] = *(const float4*)(A + (size_t)(bm0 + ar + i * 32) * K + k0 + ac);
                rb[i] = *(const float4*)(B + (size_t)(k0 + br + i * 8) * N + bn0 + bc);
            }
        }

        #pragma unroll
        for (int ks = 0; ks < 2; ks++) {
            const int k = ks * 16;
            unsigned ah[4][4], al[4][4], bh[4][2], bl[4][2];

            const int arl = wm * 64 + (lane & 15);
            const int kcl = k + (lane >> 4) * 8;
            #pragma unroll
            for (int mi = 0; mi < 4; mi++) {
                ldsm_x4(smem_u32(&As_hi[(arl + mi * 16) * AS_STRIDE + kcl]), ah[mi]);
                ldsm_x4(smem_u32(&As_lo[(arl + mi * 16) * AS_STRIDE + kcl]), al[mi]);
            }
            const int krw = k + ((lane >> 3) & 1) * 8 + (lane & 7);
            #pragma unroll
            for (int nb = 0; nb < 2; nb++) {
                const int ncl = wn * 32 + nb * 16 + (lane >> 4) * 8;
                unsigned r[4];
                ldsm_x4_t(smem_u32(&Bs_hi[krw * BS_STRIDE + ncl]), r);
                bh[2 * nb][0] = r[0]; bh[2 * nb][1] = r[1];
                bh[2 * nb + 1][0] = r[2]; bh[2 * nb + 1][1] = r[3];
                ldsm_x4_t(smem_u32(&Bs_lo[krw * BS_STRIDE + ncl]), r);
                bl[2 * nb][0] = r[0]; bl[2 * nb][1] = r[1];
                bl[2 * nb + 1][0] = r[2]; bl[2 * nb + 1][1] = r[3];
            }

            #pragma unroll
            for (int mi = 0; mi < 4; mi++)
                #pragma unroll
                for (int ni = 0; ni < 4; ni++) {
                    mma_bf16(acc[mi][ni], ah[mi], bh[ni]);
                    mma_bf16(acc[mi][ni], ah[mi], bl[ni]);
                    mma_bf16(acc[mi][ni], al[mi], bh[ni]);
                }
        }
        __syncthreads();
    }

    const int gid = lane >> 2, tig = lane & 3;
    #pragma unroll
    for (int mi = 0; mi < 4; mi++)
        #pragma unroll
        for (int ni = 0; ni < 4; ni++) {
            int r0 = bm0 + wm * 64 + mi * 16 + gid;
            int c0 = bn0 + wn * 32 + ni * 8 + tig * 2;
            *(float2*)(C + (size_t)r0 * N + c0) =
                make_float2(acc[mi][ni][0], acc[mi][ni][1]);
            *(float2*)(C + (size_t)(r0 + 8) * N + c0) =
                make_float2(acc[mi][ni][2], acc[mi][ni][3]);
        }
}

// ---------------------------------------------------------------------------
// RoPE (interleaved pairs), in place.
// ---------------------------------------------------------------------------
__global__ void rope_kernel(float* __restrict__ buf, int heads)
{
    int i = blockIdx.x * blockDim.x + threadIdx.x;
    int total = T_SEQ * heads * (D_HEAD / 2);
    if (i >= total) return;
    int d2 = i & 63;
    int hh = (i >> 6) % heads;
    int t  = i / (64 * heads);

    double inv_d = exp(-(double)d2 * 0.14391156831212787);  // ln(10000)/64
    float inv = (float)inv_d;
    float ang = (float)t * inv;
    float c = cosf(ang), s = sinf(ang);

    float* p = buf + ((size_t)t * heads + hh) * D_HEAD + 2 * d2;
    float x0 = p[0], x1 = p[1];
    p[0] = x0 * c - x1 * s;
    p[1] = x0 * s + x1 * c;
}

// ===========================================================================
// Flash attention with bf16x3 tensor-core MMA.
// Block = 64 q-rows x 1 head, 256 threads (8 warps).
// S warps: 2(q) x 4(kv) over 64x64.  O warps: 2(q) x 4(d) over 64x128.
// ===========================================================================
#define BQ 64
#define BKV 64
#define QVSTR 136   // bf16 stride for Q/K/V tiles (272B, conflict-free ldsm)
#define SSTR  68    // fp32 stride for S
#define PSTR  72    // bf16 stride for P (144B, conflict-free ldsm)

#define TILE_BF (BQ * QVSTR)                  // 8704 bf16 = 17408 B
#define SM_QHI  0
#define SM_QLO  (SM_QHI + TILE_BF)
#define SM_KHI  (SM_QLO + TILE_BF)
#define SM_KLO  (SM_KHI + TILE_BF)
#define SM_VHI  (SM_KLO + TILE_BF)
#define SM_VLO  (SM_VHI + TILE_BF)
#define SM_PHI  (SM_VLO + TILE_BF)
#define SM_PLO  (SM_PHI + BQ * PSTR)
#define SM_BF_END (SM_PLO + BQ * PSTR)
#define SMF_S   0
#define SMF_M   (SMF_S + BQ * SSTR)
#define SMF_L   (SMF_M + BQ)
#define SMF_A   (SMF_L + BQ)
#define SMF_END (SMF_A + BQ)
#define FLASH_SMEM_BYTES (SM_BF_END * 2 + SMF_END * 4)

__global__ __launch_bounds__(256) void flash_mma_kernel(
    const float* __restrict__ q, const float* __restrict__ k,
    const float* __restrict__ v, float* __restrict__ o)
{
    extern __shared__ char smraw[];
    __nv_bfloat16* bf = (__nv_bfloat16*)smraw;
    float* fp = (float*)(smraw + SM_BF_END * 2);

    __nv_bfloat16* Qhi = bf + SM_QHI;
    __nv_bfloat16* Qlo = bf + SM_QLO;
    __nv_bfloat16* Khi = bf + SM_KHI;
    __nv_bfloat16* Klo = bf + SM_KLO;
    __nv_bfloat16* Vhi = bf + SM_VHI;
    __nv_bfloat16* Vlo = bf + SM_VLO;
    __nv_bfloat16* Phi = bf + SM_PHI;
    __nv_bfloat16* Plo = bf + SM_PLO;
    float* S    = fp + SMF_S;
    float* mrow = fp + SMF_M;
    float* lrow = fp + SMF_L;
    float* arow = fp + SMF_A;

    const int tid  = threadIdx.x;
    const int lane = tid & 31;
    const int wid  = tid >> 5;
    const int wq   = wid >> 2;   // 0..1 (32 q rows each)
    const int wn   = wid & 3;    // 0..3 (16 S cols / 32 O cols each)
    const int qb   = gridDim.x - 1 - blockIdx.x;  // heavy blocks first
    const int h    = blockIdx.y;
    const int kvh  = h / (H_Q / KVH_);
    const int q0   = qb * BQ;
    const float scale = 0.08838834764831845f;  // 1/sqrt(128)

    // load + split Q tile
    for (int i = tid; i < BQ * 32; i += 256) {
        int r = i >> 5, c = (i & 31) * 4;
        float4 a4 = *(const float4*)(q + (size_t)(q0 + r) * QD + h * D_HEAD + c);
        split_store4(a4, &Qhi[r * QVSTR + c], &Qlo[r * QVSTR + c]);
    }
    if (tid < BQ) { mrow[tid] = -1e30f; lrow[tid] = 0.f; }

    float accO[2][4][4];
    #pragma unroll
    for (int mi = 0; mi < 2; mi++)
        #pragma unroll
        for (int ni = 0; ni < 4; ni++)
            #pragma unroll
            for (int e = 0; e < 4; e++) accO[mi][ni][e] = 0.f;

    for (int jb = 0; jb <= qb; jb++) {
        __syncthreads();  // K/V/S/P reuse; also covers Q/m/l init on iter 0
        const int k0 = jb * BKV;
        for (int i = tid; i < BKV * 32; i += 256) {
            int r = i >> 5, c = (i & 31) * 4;
            float4 k4 = *(const float4*)(k + (size_t)(k0 + r) * KD + kvh * D_HEAD + c);
            float4 v4 = *(const float4*)(v + (size_t)(k0 + r) * KD + kvh * D_HEAD + c);
            split_store4(k4, &Khi[r * QVSTR + c], &Klo[r * QVSTR + c]);
            split_store4(v4, &Vhi[r * QVSTR + c], &Vlo[r * QVSTR + c]);
        }
        __syncthreads();

        // ---- S = Q K^T (bf16x3), warp tile 32x16 ----
        float accS[2][2][4];
        #pragma unroll
        for (int mi = 0; mi < 2; mi++)
            #pragma unroll
            for (int ni = 0; ni < 2; ni++)
                #pragma unroll
                for (int e = 0; e < 4; e++) accS[mi][ni][e] = 0.f;

        #pragma unroll
        for (int kk = 0; kk < 8; kk++) {
            unsigned ah[2][4], al[2][4], bh[2][2], bl[2][2];
            const int arl = wq * 32 + (lane & 15);
            const int kcl = kk * 16 + (lane >> 4) * 8;
            ldsm_x4(smem_u32(&Qhi[arl * QVSTR + kcl]), ah[0]);
            ldsm_x4(smem_u32(&Qhi[(arl + 16) * QVSTR + kcl]), ah[1]);
            ldsm_x4(smem_u32(&Qlo[arl * QVSTR + kcl]), al[0]);
            ldsm_x4(smem_u32(&Qlo[(arl + 16) * QVSTR + kcl]), al[1]);
            const int brl = wn * 16 + (lane & 15);
            {
                unsigned r[4];
                ldsm_x4(smem_u32(&Khi[brl * QVSTR + kcl]), r);
                bh[0][0] = r[0]; bh[0][1] = r[2];
                bh[1][0] = r[1]; bh[1][1] = r[3];
                ldsm_x4(smem_u32(&Klo[brl * QVSTR + kcl]), r);
                bl[0][0] = r[0]; bl[0][1] = r[2];
                bl[1][0] = r[1]; bl[1][1] = r[3];
            }
            #pragma unroll
            for (int mi = 0; mi < 2; mi++)
                #pragma unroll
                for (int ni = 0; ni < 2; ni++) {
                    mma_bf16(accS[mi][ni], ah[mi], bh[ni]);
                    mma_bf16(accS[mi][ni], ah[mi], bl[ni]);
                    mma_bf16(accS[mi][ni], al[mi], bh[ni]);
                }
        }
        // write scaled S to smem
        #pragma unroll
        for (int mi = 0; mi < 2; mi++)
            #pragma unroll
            for (int ni = 0; ni < 2; ni++) {
                int r0 = wq * 32 + mi * 16 + (lane >> 2);
                int c0 = wn * 16 + ni * 8 + 2 * (lane & 3);
                *(float2*)&S[r0 * SSTR + c0] =
                    make_float2(accS[mi][ni][0] * scale, accS[mi][ni][1] * scale);
                *(float2*)&S[(r0 + 8) * SSTR + c0] =
                    make_float2(accS[mi][ni][2] * scale, accS[mi][ni][3] * scale);
            }
        __syncthreads();

        // ---- online softmax: 4 threads per row ----
        {
            const int r  = tid >> 2;
            const int c0 = (tid & 3) * 16;
            const bool diag = (jb == qb);
            float sv[16];
            float vmax = -1e30f;
            #pragma unroll
            for (int j = 0; j < 16; j++) {
                float x = S[r * SSTR + c0 + j];
                if (diag && (c0 + j) > r) x = -1e30f;
                sv[j] = x;
                vmax = fmaxf(vmax, x);
            }
            vmax = fmaxf(vmax, __shfl_xor_sync(0xffffffffu, vmax, 1));
            vmax = fmaxf(vmax, __shfl_xor_sync(0xffffffffu, vmax, 2));
            float m_old = mrow[r];
            float m_new = fmaxf(m_old, vmax);
            float rs = 0.f;
            #pragma unroll
            for (int j = 0; j < 16; j += 2) {
                float p0 = __expf(sv[j] - m_new);
                float p1 = __expf(sv[j + 1] - m_new);
                rs += p0 + p1;
                __nv_bfloat16 h0 = __float2bfloat16_rn(p0);
                __nv_bfloat16 h1 = __float2bfloat16_rn(p1);
                __nv_bfloat16 l0 = __float2bfloat16_rn(p0 - __bfloat162float(h0));
                __nv_bfloat16 l1 = __float2bfloat16_rn(p1 - __bfloat162float(h1));
                *(__nv_bfloat162*)&Phi[r * PSTR + c0 + j] = __halves2bfloat162(h0, h1);
                *(__nv_bfloat162*)&Plo[r * PSTR + c0 + j] = __halves2bfloat162(l0, l1);
            }
            rs += __shfl_xor_sync(0xffffffffu, rs, 1);
            rs += __shfl_xor_sync(0xffffffffu, rs, 2);
            if ((tid & 3) == 0) {
                float alpha = __expf(m_old - m_new);
                arow[r] = alpha;
                mrow[r] = m_new;
                lrow[r] = lrow[r] * alpha + rs;
            }
        }
        __syncthreads();

        // ---- rescale O accumulators by alpha ----
        {
            float alph[2][2];
            #pragma unroll
            for (int mi = 0; mi < 2; mi++) {
                int r0 = wq * 32 + mi * 16 + (lane >> 2);
                alph[mi][0] = arow[r0];
                alph[mi][1] = arow[r0 + 8];
            }
            #pragma unroll
            for (int mi = 0; mi < 2; mi++)
                #pragma unroll
                for (int ni = 0; ni < 4; ni++) {
                    accO[mi][ni][0] *= alph[mi][0];
                    accO[mi][ni][1] *= alph[mi][0];
                    accO[mi][ni][2] *= alph[mi][1];
                    accO[mi][ni][3] *= alph[mi][1];
                }
        }

        // ---- O += P V (bf16x3), warp tile 32x32 over 64x128 ----
        #pragma unroll
        for (int kk = 0; kk < 4; kk++) {
            unsigned ph[2][4], pl[2][4], vh[4][2], vl[4][2];
            const int arl = wq * 32 + (lane & 15);
            const int kcl = kk * 16 + (lane >> 4) * 8;
            ldsm_x4(smem_u32(&Phi[arl * PSTR + kcl]), ph[0]);
            ldsm_x4(smem_u32(&Phi[(arl + 16) * PSTR + kcl]), ph[1]);
            ldsm_x4(smem_u32(&Plo[arl * PSTR + kcl]), pl[0]);
            ldsm_x4(smem_u32(&Plo[(arl + 16) * PSTR + kcl]), pl[1]);
            const int krw = kk * 16 + ((lane >> 3) & 1) * 8 + (lane & 7);
            #pragma unroll
            for (int nb = 0; nb < 2; nb++) {
                const int ncl = wn * 32 + nb * 16 + (lane >> 4) * 8;
                unsigned r[4];
                ldsm_x4_t(smem_u32(&Vhi[krw * QVSTR + ncl]), r);
                vh[2 * nb][0] = r[0]; vh[2 * nb][1] = r[1];
                vh[2 * nb + 1][0] = r[2]; vh[2 * nb + 1][1] = r[3];
                ldsm_x4_t(smem_u32(&Vlo[krw * QVSTR + ncl]), r);
                vl[2 * nb][0] = r[0]; vl[2 * nb][1] = r[1];
                vl[2 * nb + 1][0] = r[2]; vl[2 * nb + 1][1] = r[3];
            }
            #pragma unroll
            for (int mi = 0; mi < 2; mi++)
                #pragma unroll
                for (int ni = 0; ni < 4; ni++) {
                    mma_bf16(accO[mi][ni], ph[mi], vh[ni]);
                    mma_bf16(accO[mi][ni], ph[mi], vl[ni]);
                    mma_bf16(accO[mi][ni], pl[mi], vh[ni]);
                }
        }
    }

    __syncthreads();
    // ---- epilogue: normalize and store ----
    #pragma unroll
    for (int mi = 0; mi < 2; mi++) {
        int r0 = wq * 32 + mi * 16 + (lane >> 2);
        float inv0 = 1.0f / lrow[r0];
        float inv1 = 1.0f / lrow[r0 + 8];
        #pragma unroll
        for (int ni = 0; ni < 4; ni++) {
            int c0 = h * D_HEAD + wn * 32 + ni * 8 + 2 * (lane & 3);
            *(float2*)(o + (size_t)(q0 + r0) * QD + c0) =
                make_float2(accO[mi][ni][0] * inv0, accO[mi][ni][1] * inv0);
            *(float2*)(o + (size_t)(q0 + r0 + 8) * QD + c0) =
                make_float2(accO[mi][ni][2] * inv1, accO[mi][ni][3] * inv1);
        }
    }
}

// ---------------------------------------------------------------------------
extern "C" void kernel_launch(void* const* d_in, const int* in_sizes, int n_in,
                              void* d_out, int out_size)
{
    const float* x  = (const float*)d_in[0];
    // d_in[1] = mask (tril) — causality hardcoded, ignored.
    const float* Wq = (const float*)d_in[2];
    const float* Wk = (const float*)d_in[3];
    const float* Wv = (const float*)d_in[4];
    const float* Wo = (const float*)d_in[5];
    float* out = (float*)d_out;

    float *q, *k, *v, *att;
    cudaGetSymbolAddress((void**)&q,   g_q);
    cudaGetSymbolAddress((void**)&k,   g_k);
    cudaGetSymbolAddress((void**)&v,   g_v);
    cudaGetSymbolAddress((void**)&att, g_att);

    // 1. projections (tensor cores, bf16x3)
    gemm_bf16x3_kernel<<<dim3(QD / 128, T_SEQ / 128), 256>>>(T_SEQ, QD, C_DIM, x, Wq, q);
    gemm_bf16x3_kernel<<<dim3(KD / 128, T_SEQ / 128), 256>>>(T_SEQ, KD, C_DIM, x, Wk, k);
    gemm_bf16x3_kernel<<<dim3(KD / 128, T_SEQ / 128), 256>>>(T_SEQ, KD, C_DIM, x, Wv, v);

    // 2. RoPE
    {
        int tq = T_SEQ * H_Q * (D_HEAD / 2);
        rope_kernel<<<(tq + 255) / 256, 256>>>(q, H_Q);
        int tk = T_SEQ * KVH_ * (D_HEAD / 2);
        rope_kernel<<<(tk + 255) / 256, 256>>>(k, KVH_);
    }

    // 3. flash attention (tensor cores, bf16x3)
    {
        cudaFuncSetAttribute(flash_mma_kernel,
                             cudaFuncAttributeMaxDynamicSharedMemorySize,
                             FLASH_SMEM_BYTES);
        flash_mma_kernel<<<dim3(T_SEQ / BQ, H_Q), 256, FLASH_SMEM_BYTES>>>(q, k, v, att);
    }

    // 4. output projection
    gemm_bf16x3_kernel<<<dim3(C_DIM / 128, T_SEQ / 128), 256>>>(T_SEQ, C_DIM, QD, att, Wo, out);
}

// round 5
// speedup vs baseline: 3.3263x; 1.0230x over previous
#include <cuda_runtime.h>
#include <cuda_bf16.h>
#include <math.h>

#define T_SEQ 4096
#define C_DIM 2048
#define H_Q   16
#define KVH_  4
#define D_HEAD 128
#define QD (H_Q * D_HEAD)    // 2048
#define KD (KVH_ * D_HEAD)   // 512

// Scratch (allocation-free rule: device globals)
__device__ float g_q[T_SEQ * QD];
__device__ float g_k[T_SEQ * KD];
__device__ float g_v[T_SEQ * KD];
__device__ float g_att[T_SEQ * QD];

__device__ __forceinline__ unsigned smem_u32(const void* p) {
    return (unsigned)__cvta_generic_to_shared(p);
}
__device__ __forceinline__ void ldsm_x4(unsigned addr, unsigned* r) {
    asm volatile("ldmatrix.sync.aligned.m8n8.x4.shared.b16 {%0,%1,%2,%3}, [%4];\n"
                 : "=r"(r[0]), "=r"(r[1]), "=r"(r[2]), "=r"(r[3]) : "r"(addr));
}
__device__ __forceinline__ void ldsm_x4_t(unsigned addr, unsigned* r) {
    asm volatile("ldmatrix.sync.aligned.m8n8.x4.trans.shared.b16 {%0,%1,%2,%3}, [%4];\n"
                 : "=r"(r[0]), "=r"(r[1]), "=r"(r[2]), "=r"(r[3]) : "r"(addr));
}
__device__ __forceinline__ void mma_bf16(float* d, const unsigned* a, const unsigned* b) {
    asm volatile("mma.sync.aligned.m16n8k16.row.col.f32.bf16.bf16.f32 "
                 "{%0,%1,%2,%3}, {%4,%5,%6,%7}, {%8,%9}, {%0,%1,%2,%3};\n"
                 : "+f"(d[0]), "+f"(d[1]), "+f"(d[2]), "+f"(d[3])
                 : "r"(a[0]), "r"(a[1]), "r"(a[2]), "r"(a[3]),
                   "r"(b[0]), "r"(b[1]));
}
__device__ __forceinline__ void split_store4(float4 v, __nv_bfloat16* hi, __nv_bfloat16* lo) {
    __nv_bfloat16 h0 = __float2bfloat16_rn(v.x);
    __nv_bfloat16 h1 = __float2bfloat16_rn(v.y);
    __nv_bfloat16 h2 = __float2bfloat16_rn(v.z);
    __nv_bfloat16 h3 = __float2bfloat16_rn(v.w);
    __nv_bfloat16 l0 = __float2bfloat16_rn(v.x - __bfloat162float(h0));
    __nv_bfloat16 l1 = __float2bfloat16_rn(v.y - __bfloat162float(h1));
    __nv_bfloat16 l2 = __float2bfloat16_rn(v.z - __bfloat162float(h2));
    __nv_bfloat16 l3 = __float2bfloat16_rn(v.w - __bfloat162float(h3));
    *(__nv_bfloat162*)(hi)     = __halves2bfloat162(h0, h1);
    *(__nv_bfloat162*)(hi + 2) = __halves2bfloat162(h2, h3);
    *(__nv_bfloat162*)(lo)     = __halves2bfloat162(l0, l1);
    *(__nv_bfloat162*)(lo + 2) = __halves2bfloat162(l2, l3);
}

// ===========================================================================
// bf16x3 tensor-core GEMM core, DOUBLE-BUFFERED dynamic smem.
// Block tile 128x128x32, 256 threads (8 warps, 2x4 warp grid, 64x32 per warp).
// smem layout per buffer: AsHi | AsLo | BsHi | BsLo
// ===========================================================================
#define AS_STRIDE 40
#define BS_STRIDE 136
#define APL (128 * AS_STRIDE)   // 5120 bf16
#define BPL (32 * BS_STRIDE)    // 4352 bf16
#define BUF_ELEMS (2 * APL + 2 * BPL)          // 18944 bf16
#define GEMM_SMEM_BYTES (2 * BUF_ELEMS * 2)    // 75776 B

__device__ __forceinline__ void gemm_core(
    int N, int K,
    const float* __restrict__ A, const float* __restrict__ B,
    float* __restrict__ C, int bm0, int bn0, char* smraw)
{
    __nv_bfloat16* bufs = (__nv_bfloat16*)smraw;

    const int tid  = threadIdx.x;
    const int lane = tid & 31;
    const int wid  = tid >> 5;
    const int wm   = wid >> 2;
    const int wn   = wid & 3;

    const int ar = tid >> 3;
    const int ac = (tid & 7) * 4;
    const int br = tid >> 5;
    const int bc = (tid & 31) * 4;

    float acc[4][4][4];
    #pragma unroll
    for (int mi = 0; mi < 4; mi++)
        #pragma unroll
        for (int ni = 0; ni < 4; ni++)
            #pragma unroll
            for (int e = 0; e < 4; e++) acc[mi][ni][e] = 0.f;

    const int ktiles = K >> 5;

    float4 ra[4], rb[4];
    #pragma unroll
    for (int i = 0; i < 4; i++) {
        ra[i] = *(const float4*)(A + (size_t)(bm0 + ar + i * 32) * K + ac);
        rb[i] = *(const float4*)(B + (size_t)(br + i * 8) * N + bn0 + bc);
    }
    // commit tile 0 into buffer 0
    {
        __nv_bfloat16* AsHi = bufs;
        __nv_bfloat16* AsLo = AsHi + APL;
        __nv_bfloat16* BsHi = AsLo + APL;
        __nv_bfloat16* BsLo = BsHi + BPL;
        #pragma unroll
        for (int i = 0; i < 4; i++) {
            int r = ar + i * 32;
            split_store4(ra[i], &AsHi[r * AS_STRIDE + ac], &AsLo[r * AS_STRIDE + ac]);
            int rB = br + i * 8;
            split_store4(rb[i], &BsHi[rB * BS_STRIDE + bc], &BsLo[rB * BS_STRIDE + bc]);
        }
    }
    __syncthreads();

    for (int kt = 0; kt < ktiles; kt++) {
        const bool has_next = (kt + 1 < ktiles);
        // prefetch next tile into registers (overlaps with MMA below)
        if (has_next) {
            int k0 = (kt + 1) << 5;
            #pragma unroll
            for (int i = 0; i < 4; i++) {
                ra[i] = *(const float4*)(A + (size_t)(bm0 + ar + i * 32) * K + k0 + ac);
                rb[i] = *(const float4*)(B + (size_t)(k0 + br + i * 8) * N + bn0 + bc);
            }
        }

        __nv_bfloat16* AsHi = bufs + (kt & 1) * BUF_ELEMS;
        __nv_bfloat16* AsLo = AsHi + APL;
        __nv_bfloat16* BsHi = AsLo + APL;
        __nv_bfloat16* BsLo = BsHi + BPL;

        #pragma unroll
        for (int ks = 0; ks < 2; ks++) {
            const int k = ks * 16;
            unsigned ah[4][4], al[4][4], bh[4][2], bl[4][2];

            const int arl = wm * 64 + (lane & 15);
            const int kcl = k + (lane >> 4) * 8;
            #pragma unroll
            for (int mi = 0; mi < 4; mi++) {
                ldsm_x4(smem_u32(&AsHi[(arl + mi * 16) * AS_STRIDE + kcl]), ah[mi]);
                ldsm_x4(smem_u32(&AsLo[(arl + mi * 16) * AS_STRIDE + kcl]), al[mi]);
            }
            const int krw = k + ((lane >> 3) & 1) * 8 + (lane & 7);
            #pragma unroll
            for (int nb = 0; nb < 2; nb++) {
                const int ncl = wn * 32 + nb * 16 + (lane >> 4) * 8;
                unsigned r[4];
                ldsm_x4_t(smem_u32(&BsHi[krw * BS_STRIDE + ncl]), r);
                bh[2 * nb][0] = r[0]; bh[2 * nb][1] = r[1];
                bh[2 * nb + 1][0] = r[2]; bh[2 * nb + 1][1] = r[3];
                ldsm_x4_t(smem_u32(&BsLo[krw * BS_STRIDE + ncl]), r);
                bl[2 * nb][0] = r[0]; bl[2 * nb][1] = r[1];
                bl[2 * nb + 1][0] = r[2]; bl[2 * nb + 1][1] = r[3];
            }

            #pragma unroll
            for (int mi = 0; mi < 4; mi++)
                #pragma unroll
                for (int ni = 0; ni < 4; ni++) {
                    mma_bf16(acc[mi][ni], ah[mi], bh[ni]);
                    mma_bf16(acc[mi][ni], ah[mi], bl[ni]);
                    mma_bf16(acc[mi][ni], al[mi], bh[ni]);
                }
        }

        // commit prefetched tile into the OTHER buffer (consumed last iter,
        // free since the sync that opened this iteration)
        if (has_next) {
            __nv_bfloat16* nAsHi = bufs + ((kt + 1) & 1) * BUF_ELEMS;
            __nv_bfloat16* nAsLo = nAsHi + APL;
            __nv_bfloat16* nBsHi = nAsLo + APL;
            __nv_bfloat16* nBsLo = nBsHi + BPL;
            #pragma unroll
            for (int i = 0; i < 4; i++) {
                int r = ar + i * 32;
                split_store4(ra[i], &nAsHi[r * AS_STRIDE + ac], &nAsLo[r * AS_STRIDE + ac]);
                int rB = br + i * 8;
                split_store4(rb[i], &nBsHi[rB * BS_STRIDE + bc], &nBsLo[rB * BS_STRIDE + bc]);
            }
        }
        __syncthreads();
    }

    const int gid = lane >> 2, tig = lane & 3;
    #pragma unroll
    for (int mi = 0; mi < 4; mi++)
        #pragma unroll
        for (int ni = 0; ni < 4; ni++) {
            int r0 = bm0 + wm * 64 + mi * 16 + gid;
            int c0 = bn0 + wn * 32 + ni * 8 + tig * 2;
            *(float2*)(C + (size_t)r0 * N + c0) =
                make_float2(acc[mi][ni][0], acc[mi][ni][1]);
            *(float2*)(C + (size_t)(r0 + 8) * N + c0) =
                make_float2(acc[mi][ni][2], acc[mi][ni][3]);
        }
}

// Fused QKV projection: grid (24, 32). bx<16 -> Q, <20 -> K, else V.
__global__ __launch_bounds__(256) void gemm_qkv_kernel(
    const float* __restrict__ x,
    const float* __restrict__ Wq, const float* __restrict__ Wk,
    const float* __restrict__ Wv,
    float* __restrict__ q, float* __restrict__ k, float* __restrict__ v)
{
    extern __shared__ char smraw[];
    const int bx = blockIdx.x;
    const int bm0 = blockIdx.y * 128;
    if (bx < 16) {
        gemm_core(QD, C_DIM, x, Wq, q, bm0, bx * 128, smraw);
    } else if (bx < 20) {
        gemm_core(KD, C_DIM, x, Wk, k, bm0, (bx - 16) * 128, smraw);
    } else {
        gemm_core(KD, C_DIM, x, Wv, v, bm0, (bx - 20) * 128, smraw);
    }
}

// Generic GEMM (used for output projection)
__global__ __launch_bounds__(256) void gemm_bf16x3_kernel(
    int M, int N, int K,
    const float* __restrict__ A, const float* __restrict__ B,
    float* __restrict__ C)
{
    extern __shared__ char smraw[];
    gemm_core(N, K, A, B, C, blockIdx.y * 128, blockIdx.x * 128, smraw);
}

// ---------------------------------------------------------------------------
// RoPE (interleaved pairs), in place.
// ---------------------------------------------------------------------------
__global__ void rope_kernel(float* __restrict__ buf, int heads)
{
    int i = blockIdx.x * blockDim.x + threadIdx.x;
    int total = T_SEQ * heads * (D_HEAD / 2);
    if (i >= total) return;
    int d2 = i & 63;
    int hh = (i >> 6) % heads;
    int t  = i / (64 * heads);

    double inv_d = exp(-(double)d2 * 0.14391156831212787);  // ln(10000)/64
    float inv = (float)inv_d;
    float ang = (float)t * inv;
    float c = cosf(ang), s = sinf(ang);

    float* p = buf + ((size_t)t * heads + hh) * D_HEAD + 2 * d2;
    float x0 = p[0], x1 = p[1];
    p[0] = x0 * c - x1 * s;
    p[1] = x0 * s + x1 * c;
}

// ===========================================================================
// Flash attention with bf16x3 tensor-core MMA (unchanged from R4).
// ===========================================================================
#define BQ 64
#define BKV 64
#define QVSTR 136
#define SSTR  68
#define PSTR  72

#define TILE_BF (BQ * QVSTR)
#define SM_QHI  0
#define SM_QLO  (SM_QHI + TILE_BF)
#define SM_KHI  (SM_QLO + TILE_BF)
#define SM_KLO  (SM_KHI + TILE_BF)
#define SM_VHI  (SM_KLO + TILE_BF)
#define SM_VLO  (SM_VHI + TILE_BF)
#define SM_PHI  (SM_VLO + TILE_BF)
#define SM_PLO  (SM_PHI + BQ * PSTR)
#define SM_BF_END (SM_PLO + BQ * PSTR)
#define SMF_S   0
#define SMF_M   (SMF_S + BQ * SSTR)
#define SMF_L   (SMF_M + BQ)
#define SMF_A   (SMF_L + BQ)
#define SMF_END (SMF_A + BQ)
#define FLASH_SMEM_BYTES (SM_BF_END * 2 + SMF_END * 4)

__global__ __launch_bounds__(256) void flash_mma_kernel(
    const float* __restrict__ q, const float* __restrict__ k,
    const float* __restrict__ v, float* __restrict__ o)
{
    extern __shared__ char smraw[];
    __nv_bfloat16* bf = (__nv_bfloat16*)smraw;
    float* fp = (float*)(smraw + SM_BF_END * 2);

    __nv_bfloat16* Qhi = bf + SM_QHI;
    __nv_bfloat16* Qlo = bf + SM_QLO;
    __nv_bfloat16* Khi = bf + SM_KHI;
    __nv_bfloat16* Klo = bf + SM_KLO;
    __nv_bfloat16* Vhi = bf + SM_VHI;
    __nv_bfloat16* Vlo = bf + SM_VLO;
    __nv_bfloat16* Phi = bf + SM_PHI;
    __nv_bfloat16* Plo = bf + SM_PLO;
    float* S    = fp + SMF_S;
    float* mrow = fp + SMF_M;
    float* lrow = fp + SMF_L;
    float* arow = fp + SMF_A;

    const int tid  = threadIdx.x;
    const int lane = tid & 31;
    const int wid  = tid >> 5;
    const int wq   = wid >> 2;
    const int wn   = wid & 3;
    const int qb   = gridDim.x - 1 - blockIdx.x;
    const int h    = blockIdx.y;
    const int kvh  = h / (H_Q / KVH_);
    const int q0   = qb * BQ;
    const float scale = 0.08838834764831845f;

    for (int i = tid; i < BQ * 32; i += 256) {
        int r = i >> 5, c = (i & 31) * 4;
        float4 a4 = *(const float4*)(q + (size_t)(q0 + r) * QD + h * D_HEAD + c);
        split_store4(a4, &Qhi[r * QVSTR + c], &Qlo[r * QVSTR + c]);
    }
    if (tid < BQ) { mrow[tid] = -1e30f; lrow[tid] = 0.f; }

    float accO[2][4][4];
    #pragma unroll
    for (int mi = 0; mi < 2; mi++)
        #pragma unroll
        for (int ni = 0; ni < 4; ni++)
            #pragma unroll
            for (int e = 0; e < 4; e++) accO[mi][ni][e] = 0.f;

    for (int jb = 0; jb <= qb; jb++) {
        __syncthreads();
        const int k0 = jb * BKV;
        for (int i = tid; i < BKV * 32; i += 256) {
            int r = i >> 5, c = (i & 31) * 4;
            float4 k4 = *(const float4*)(k + (size_t)(k0 + r) * KD + kvh * D_HEAD + c);
            float4 v4 = *(const float4*)(v + (size_t)(k0 + r) * KD + kvh * D_HEAD + c);
            split_store4(k4, &Khi[r * QVSTR + c], &Klo[r * QVSTR + c]);
            split_store4(v4, &Vhi[r * QVSTR + c], &Vlo[r * QVSTR + c]);
        }
        __syncthreads();

        float accS[2][2][4];
        #pragma unroll
        for (int mi = 0; mi < 2; mi++)
            #pragma unroll
            for (int ni = 0; ni < 2; ni++)
                #pragma unroll
                for (int e = 0; e < 4; e++) accS[mi][ni][e] = 0.f;

        #pragma unroll
        for (int kk = 0; kk < 8; kk++) {
            unsigned ah[2][4], al[2][4], bh[2][2], bl[2][2];
            const int arl = wq * 32 + (lane & 15);
            const int kcl = kk * 16 + (lane >> 4) * 8;
            ldsm_x4(smem_u32(&Qhi[arl * QVSTR + kcl]), ah[0]);
            ldsm_x4(smem_u32(&Qhi[(arl + 16) * QVSTR + kcl]), ah[1]);
            ldsm_x4(smem_u32(&Qlo[arl * QVSTR + kcl]), al[0]);
            ldsm_x4(smem_u32(&Qlo[(arl + 16) * QVSTR + kcl]), al[1]);
            const int brl = wn * 16 + (lane & 15);
            {
                unsigned r[4];
                ldsm_x4(smem_u32(&Khi[brl * QVSTR + kcl]), r);
                bh[0][0] = r[0]; bh[0][1] = r[2];
                bh[1][0] = r[1]; bh[1][1] = r[3];
                ldsm_x4(smem_u32(&Klo[brl * QVSTR + kcl]), r);
                bl[0][0] = r[0]; bl[0][1] = r[2];
                bl[1][0] = r[1]; bl[1][1] = r[3];
            }
            #pragma unroll
            for (int mi = 0; mi < 2; mi++)
                #pragma unroll
                for (int ni = 0; ni < 2; ni++) {
                    mma_bf16(accS[mi][ni], ah[mi], bh[ni]);
                    mma_bf16(accS[mi][ni], ah[mi], bl[ni]);
                    mma_bf16(accS[mi][ni], al[mi], bh[ni]);
                }
        }
        #pragma unroll
        for (int mi = 0; mi < 2; mi++)
            #pragma unroll
            for (int ni = 0; ni < 2; ni++) {
                int r0 = wq * 32 + mi * 16 + (lane >> 2);
                int c0 = wn * 16 + ni * 8 + 2 * (lane & 3);
                *(float2*)&S[r0 * SSTR + c0] =
                    make_float2(accS[mi][ni][0] * scale, accS[mi][ni][1] * scale);
                *(float2*)&S[(r0 + 8) * SSTR + c0] =
                    make_float2(accS[mi][ni][2] * scale, accS[mi][ni][3] * scale);
            }
        __syncthreads();

        {
            const int r  = tid >> 2;
            const int c0 = (tid & 3) * 16;
            const bool diag = (jb == qb);
            float sv[16];
            float vmax = -1e30f;
            #pragma unroll
            for (int j = 0; j < 16; j++) {
                float x = S[r * SSTR + c0 + j];
                if (diag && (c0 + j) > r) x = -1e30f;
                sv[j] = x;
                vmax = fmaxf(vmax, x);
            }
            vmax = fmaxf(vmax, __shfl_xor_sync(0xffffffffu, vmax, 1));
            vmax = fmaxf(vmax, __shfl_xor_sync(0xffffffffu, vmax, 2));
            float m_old = mrow[r];
            float m_new = fmaxf(m_old, vmax);
            float rs = 0.f;
            #pragma unroll
            for (int j = 0; j < 16; j += 2) {
                float p0 = __expf(sv[j] - m_new);
                float p1 = __expf(sv[j + 1] - m_new);
                rs += p0 + p1;
                __nv_bfloat16 h0 = __float2bfloat16_rn(p0);
                __nv_bfloat16 h1 = __float2bfloat16_rn(p1);
                __nv_bfloat16 l0 = __float2bfloat16_rn(p0 - __bfloat162float(h0));
                __nv_bfloat16 l1 = __float2bfloat16_rn(p1 - __bfloat162float(h1));
                *(__nv_bfloat162*)&Phi[r * PSTR + c0 + j] = __halves2bfloat162(h0, h1);
                *(__nv_bfloat162*)&Plo[r * PSTR + c0 + j] = __halves2bfloat162(l0, l1);
            }
            rs += __shfl_xor_sync(0xffffffffu, rs, 1);
            rs += __shfl_xor_sync(0xffffffffu, rs, 2);
            if ((tid & 3) == 0) {
                float alpha = __expf(m_old - m_new);
                arow[r] = alpha;
                mrow[r] = m_new;
                lrow[r] = lrow[r] * alpha + rs;
            }
        }
        __syncthreads();

        {
            float alph[2][2];
            #pragma unroll
            for (int mi = 0; mi < 2; mi++) {
                int r0 = wq * 32 + mi * 16 + (lane >> 2);
                alph[mi][0] = arow[r0];
                alph[mi][1] = arow[r0 + 8];
            }
            #pragma unroll
            for (int mi = 0; mi < 2; mi++)
                #pragma unroll
                for (int ni = 0; ni < 4; ni++) {
                    accO[mi][ni][0] *= alph[mi][0];
                    accO[mi][ni][1] *= alph[mi][0];
                    accO[mi][ni][2] *= alph[mi][1];
                    accO[mi][ni][3] *= alph[mi][1];
                }
        }

        #pragma unroll
        for (int kk = 0; kk < 4; kk++) {
            unsigned ph[2][4], pl[2][4], vh[4][2], vl[4][2];
            const int arl = wq * 32 + (lane & 15);
            const int kcl = kk * 16 + (lane >> 4) * 8;
            ldsm_x4(smem_u32(&Phi[arl * PSTR + kcl]), ph[0]);
            ldsm_x4(smem_u32(&Phi[(arl + 16) * PSTR + kcl]), ph[1]);
            ldsm_x4(smem_u32(&Plo[arl * PSTR + kcl]), pl[0]);
            ldsm_x4(smem_u32(&Plo[(arl + 16) * PSTR + kcl]), pl[1]);
            const int krw = kk * 16 + ((lane >> 3) & 1) * 8 + (lane & 7);
            #pragma unroll
            for (int nb = 0; nb < 2; nb++) {
                const int ncl = wn * 32 + nb * 16 + (lane >> 4) * 8;
                unsigned r[4];
                ldsm_x4_t(smem_u32(&Vhi[krw * QVSTR + ncl]), r);
                vh[2 * nb][0] = r[0]; vh[2 * nb][1] = r[1];
                vh[2 * nb + 1][0] = r[2]; vh[2 * nb + 1][1] = r[3];
                ldsm_x4_t(smem_u32(&Vlo[krw * QVSTR + ncl]), r);
                vl[2 * nb][0] = r[0]; vl[2 * nb][1] = r[1];
                vl[2 * nb + 1][0] = r[2]; vl[2 * nb + 1][1] = r[3];
            }
            #pragma unroll
            for (int mi = 0; mi < 2; mi++)
                #pragma unroll
                for (int ni = 0; ni < 4; ni++) {
                    mma_bf16(accO[mi][ni], ph[mi], vh[ni]);
                    mma_bf16(accO[mi][ni], ph[mi], vl[ni]);
                    mma_bf16(accO[mi][ni], pl[mi], vh[ni]);
                }
        }
    }

    __syncthreads();
    #pragma unroll
    for (int mi = 0; mi < 2; mi++) {
        int r0 = wq * 32 + mi * 16 + (lane >> 2);
        float inv0 = 1.0f / lrow[r0];
        float inv1 = 1.0f / lrow[r0 + 8];
        #pragma unroll
        for (int ni = 0; ni < 4; ni++) {
            int c0 = h * D_HEAD + wn * 32 + ni * 8 + 2 * (lane & 3);
            *(float2*)(o + (size_t)(q0 + r0) * QD + c0) =
                make_float2(accO[mi][ni][0] * inv0, accO[mi][ni][1] * inv0);
            *(float2*)(o + (size_t)(q0 + r0 + 8) * QD + c0) =
                make_float2(accO[mi][ni][2] * inv1, accO[mi][ni][3] * inv1);
        }
    }
}

// ---------------------------------------------------------------------------
extern "C" void kernel_launch(void* const* d_in, const int* in_sizes, int n_in,
                              void* d_out, int out_size)
{
    const float* x  = (const float*)d_in[0];
    // d_in[1] = mask (tril) — causality hardcoded, ignored.
    const float* Wq = (const float*)d_in[2];
    const float* Wk = (const float*)d_in[3];
    const float* Wv = (const float*)d_in[4];
    const float* Wo = (const float*)d_in[5];
    float* out = (float*)d_out;

    float *q, *k, *v, *att;
    cudaGetSymbolAddress((void**)&q,   g_q);
    cudaGetSymbolAddress((void**)&k,   g_k);
    cudaGetSymbolAddress((void**)&v,   g_v);
    cudaGetSymbolAddress((void**)&att, g_att);

    cudaFuncSetAttribute(gemm_qkv_kernel,
                         cudaFuncAttributeMaxDynamicSharedMemorySize, GEMM_SMEM_BYTES);
    cudaFuncSetAttribute(gemm_bf16x3_kernel,
                         cudaFuncAttributeMaxDynamicSharedMemorySize, GEMM_SMEM_BYTES);
    cudaFuncSetAttribute(flash_mma_kernel,
                         cudaFuncAttributeMaxDynamicSharedMemorySize, FLASH_SMEM_BYTES);

    // 1. fused QKV projection
    gemm_qkv_kernel<<<dim3(24, 32), 256, GEMM_SMEM_BYTES>>>(x, Wq, Wk, Wv, q, k, v);

    // 2. RoPE
    {
        int tq = T_SEQ * H_Q * (D_HEAD / 2);
        rope_kernel<<<(tq + 255) / 256, 256>>>(q, H_Q);
        int tk = T_SEQ * KVH_ * (D_HEAD / 2);
        rope_kernel<<<(tk + 255) / 256, 256>>>(k, KVH_);
    }

    // 3. flash attention (tensor cores, bf16x3)
    flash_mma_kernel<<<dim3(T_SEQ / BQ, H_Q), 256, FLASH_SMEM_BYTES>>>(q, k, v, att);

    // 4. output projection
    gemm_bf16x3_kernel<<<dim3(C_DIM / 128, T_SEQ / 128), 256, GEMM_SMEM_BYTES>>>(
        T_SEQ, C_DIM, QD, att, Wo, out);
}

// round 10
// speedup vs baseline: 5.3945x; 1.6218x over previous
#include <cuda_runtime.h>
#include <cuda_fp16.h>
#include <stdint.h>
#include <math.h>

#define T_SEQ 4096
#define C_DIM 2048
#define H_Q   16
#define KVH_  4
#define D_HEAD 128
#define QD (H_Q * D_HEAD)    // 2048
#define KD (KVH_ * D_HEAD)   // 512

// Scratch (allocation-free rule: device globals)
__device__ float g_q[T_SEQ * QD];
__device__ float g_k[T_SEQ * KD];
__device__ float g_v[T_SEQ * KD];
__device__ float g_att[T_SEQ * QD];

__device__ __forceinline__ unsigned smem_u32(const void* p) {
    return (unsigned)__cvta_generic_to_shared(p);
}
__device__ __forceinline__ void ldsm_x4(unsigned addr, unsigned* r) {
    asm volatile("ldmatrix.sync.aligned.m8n8.x4.shared.b16 {%0,%1,%2,%3}, [%4];\n"
                 : "=r"(r[0]), "=r"(r[1]), "=r"(r[2]), "=r"(r[3]) : "r"(addr));
}
__device__ __forceinline__ void ldsm_x4_t(unsigned addr, unsigned* r) {
    asm volatile("ldmatrix.sync.aligned.m8n8.x4.trans.shared.b16 {%0,%1,%2,%3}, [%4];\n"
                 : "=r"(r[0]), "=r"(r[1]), "=r"(r[2]), "=r"(r[3]) : "r"(addr));
}
__device__ __forceinline__ void mma_f16(float* d, const unsigned* a, const unsigned* b) {
    asm volatile("mma.sync.aligned.m16n8k16.row.col.f32.f16.f16.f32 "
                 "{%0,%1,%2,%3}, {%4,%5,%6,%7}, {%8,%9}, {%0,%1,%2,%3};\n"
                 : "+f"(d[0]), "+f"(d[1]), "+f"(d[2]), "+f"(d[3])
                 : "r"(a[0]), "r"(a[1]), "r"(a[2]), "r"(a[3]),
                   "r"(b[0]), "r"(b[1]));
}
// split 4 fp32 into fp16 hi/lo planes
__device__ __forceinline__ void split_store4h(float4 v, __half* hi, __half* lo) {
    __half h0 = __float2half_rn(v.x);
    __half h1 = __float2half_rn(v.y);
    __half h2 = __float2half_rn(v.z);
    __half h3 = __float2half_rn(v.w);
    __half l0 = __float2half_rn(v.x - __half2float(h0));
    __half l1 = __float2half_rn(v.y - __half2float(h1));
    __half l2 = __float2half_rn(v.z - __half2float(h2));
    __half l3 = __float2half_rn(v.w - __half2float(h3));
    *(__half2*)(hi)     = __halves2half2(h0, h1);
    *(__half2*)(hi + 2) = __halves2half2(h2, h3);
    *(__half2*)(lo)     = __halves2half2(l0, l1);
    *(__half2*)(lo + 2) = __halves2half2(l2, l3);
}
// pack 4 fp32 into single fp16 plane
__device__ __forceinline__ void pack_store4h(float4 v, __half* dst) {
    *(__half2*)(dst)     = __halves2half2(__float2half_rn(v.x), __float2half_rn(v.y));
    *(__half2*)(dst + 2) = __halves2half2(__float2half_rn(v.z), __float2half_rn(v.w));
}

// ===========================================================================
// fp16x2 tensor-core GEMM: C[M,N] = A[M,K] @ B[K,N], row-major, fp32 in/out.
// A split hi/lo, B single plane. Block tile 128x128x32, 256 threads,
// 8 warps (2x4), 64x32 per warp. Double-buffered smem.
// ===========================================================================
#define AS_STRIDE 40
#define BS_STRIDE 136
#define APL (128 * AS_STRIDE)   // 5120 halfs
#define BPL (32 * BS_STRIDE)    // 4352 halfs
#define BUF_ELEMS (2 * APL + BPL)              // 14592 halfs
#define GEMM_SMEM_BYTES (2 * BUF_ELEMS * 2)    // 58368 B

__device__ __forceinline__ void gemm_core(
    int N, int K,
    const float* __restrict__ A, const float* __restrict__ B,
    float* __restrict__ C, int bm0, int bn0, char* smraw)
{
    __half* bufs = (__half*)smraw;

    const int tid  = threadIdx.x;
    const int lane = tid & 31;
    const int wid  = tid >> 5;
    const int wm   = wid >> 2;
    const int wn   = wid & 3;

    const int ar = tid >> 3;
    const int ac = (tid & 7) * 4;
    const int br = tid >> 5;
    const int bc = (tid & 31) * 4;

    float acc[4][4][4];
    #pragma unroll
    for (int mi = 0; mi < 4; mi++)
        #pragma unroll
        for (int ni = 0; ni < 4; ni++)
            #pragma unroll
            for (int e = 0; e < 4; e++) acc[mi][ni][e] = 0.f;

    const int ktiles = K >> 5;

    float4 ra[4], rb[4];
    #pragma unroll
    for (int i = 0; i < 4; i++) {
        ra[i] = *(const float4*)(A + (size_t)(bm0 + ar + i * 32) * K + ac);
        rb[i] = *(const float4*)(B + (size_t)(br + i * 8) * N + bn0 + bc);
    }
    {
        __half* AsHi = bufs;
        __half* AsLo = AsHi + APL;
        __half* Bs   = AsLo + APL;
        #pragma unroll
        for (int i = 0; i < 4; i++) {
            int r = ar + i * 32;
            split_store4h(ra[i], &AsHi[r * AS_STRIDE + ac], &AsLo[r * AS_STRIDE + ac]);
            pack_store4h(rb[i], &Bs[(br + i * 8) * BS_STRIDE + bc]);
        }
    }
    __syncthreads();

    for (int kt = 0; kt < ktiles; kt++) {
        const bool has_next = (kt + 1 < ktiles);
        if (has_next) {
            int k0 = (kt + 1) << 5;
            #pragma unroll
            for (int i = 0; i < 4; i++) {
                ra[i] = *(const float4*)(A + (size_t)(bm0 + ar + i * 32) * K + k0 + ac);
                rb[i] = *(const float4*)(B + (size_t)(k0 + br + i * 8) * N + bn0 + bc);
            }
        }

        __half* AsHi = bufs + (kt & 1) * BUF_ELEMS;
        __half* AsLo = AsHi + APL;
        __half* Bs   = AsLo + APL;

        #pragma unroll
        for (int ks = 0; ks < 2; ks++) {
            const int k = ks * 16;
            unsigned ah[4][4], al[4][4], bh[4][2];

            const int arl = wm * 64 + (lane & 15);
            const int kcl = k + (lane >> 4) * 8;
            #pragma unroll
            for (int mi = 0; mi < 4; mi++) {
                ldsm_x4(smem_u32(&AsHi[(arl + mi * 16) * AS_STRIDE + kcl]), ah[mi]);
                ldsm_x4(smem_u32(&AsLo[(arl + mi * 16) * AS_STRIDE + kcl]), al[mi]);
            }
            const int krw = k + ((lane >> 3) & 1) * 8 + (lane & 7);
            #pragma unroll
            for (int nb = 0; nb < 2; nb++) {
                const int ncl = wn * 32 + nb * 16 + (lane >> 4) * 8;
                unsigned r[4];
                ldsm_x4_t(smem_u32(&Bs[krw * BS_STRIDE + ncl]), r);
                bh[2 * nb][0] = r[0]; bh[2 * nb][1] = r[1];
                bh[2 * nb + 1][0] = r[2]; bh[2 * nb + 1][1] = r[3];
            }

            #pragma unroll
            for (int mi = 0; mi < 4; mi++)
                #pragma unroll
                for (int ni = 0; ni < 4; ni++) {
                    mma_f16(acc[mi][ni], ah[mi], bh[ni]);
                    mma_f16(acc[mi][ni], al[mi], bh[ni]);
                }
        }

        if (has_next) {
            __half* nAsHi = bufs + ((kt + 1) & 1) * BUF_ELEMS;
            __half* nAsLo = nAsHi + APL;
            __half* nBs   = nAsLo + APL;
            #pragma unroll
            for (int i = 0; i < 4; i++) {
                int r = ar + i * 32;
                split_store4h(ra[i], &nAsHi[r * AS_STRIDE + ac], &nAsLo[r * AS_STRIDE + ac]);
                pack_store4h(rb[i], &nBs[(br + i * 8) * BS_STRIDE + bc]);
            }
        }
        __syncthreads();
    }

    const int gid = lane >> 2, tig = lane & 3;
    #pragma unroll
    for (int mi = 0; mi < 4; mi++)
        #pragma unroll
        for (int ni = 0; ni < 4; ni++) {
            int r0 = bm0 + wm * 64 + mi * 16 + gid;
            int c0 = bn0 + wn * 32 + ni * 8 + tig * 2;
            *(float2*)(C + (size_t)r0 * N + c0) =
                make_float2(acc[mi][ni][0], acc[mi][ni][1]);
            *(float2*)(C + (size_t)(r0 + 8) * N + c0) =
                make_float2(acc[mi][ni][2], acc[mi][ni][3]);
        }
}

// Fused QKV projection: grid (24, 32). bx<16 -> Q, <20 -> K, else V.
__global__ __launch_bounds__(256) void gemm_qkv_kernel(
    const float* __restrict__ x,
    const float* __restrict__ Wq, const float* __restrict__ Wk,
    const float* __restrict__ Wv,
    float* __restrict__ q, float* __restrict__ k, float* __restrict__ v)
{
    extern __shared__ char smraw[];
    const int bx = blockIdx.x;
    const int bm0 = blockIdx.y * 128;
    if (bx < 16) {
        gemm_core(QD, C_DIM, x, Wq, q, bm0, bx * 128, smraw);
    } else if (bx < 20) {
        gemm_core(KD, C_DIM, x, Wk, k, bm0, (bx - 16) * 128, smraw);
    } else {
        gemm_core(KD, C_DIM, x, Wv, v, bm0, (bx - 20) * 128, smraw);
    }
}

__global__ __launch_bounds__(256) void gemm_fp16x2_kernel(
    int M, int N, int K,
    const float* __restrict__ A, const float* __restrict__ B,
    float* __restrict__ C)
{
    extern __shared__ char smraw[];
    gemm_core(N, K, A, B, C, blockIdx.y * 128, blockIdx.x * 128, smraw);
}

// ---------------------------------------------------------------------------
// RoPE (unchanged)
// ---------------------------------------------------------------------------
__global__ void rope_kernel(float* __restrict__ buf, int heads)
{
    int i = blockIdx.x * blockDim.x + threadIdx.x;
    int total = T_SEQ * heads * (D_HEAD / 2);
    if (i >= total) return;
    int d2 = i & 63;
    int hh = (i >> 6) % heads;
    int t  = i / (64 * heads);

    double inv_d = exp(-(double)d2 * 0.14391156831212787);  // ln(10000)/64
    float inv = (float)inv_d;
    float ang = (float)t * inv;
    float c = cosf(ang), s = sinf(ang);

    float* p = buf + ((size_t)t * heads + hh) * D_HEAD + 2 * d2;
    float x0 = p[0], x1 = p[1];
    p[0] = x0 * c - x1 * s;
    p[1] = x0 * s + x1 * c;
}

// ===========================================================================
// Flash attention, fp16x2 MMA: Q split / K single, P split / V single.
// Block = 64 q-rows x 1 head, 256 threads (8 warps).
// ===========================================================================
#define BQ 64
#define BKV 64
#define QVSTR 136
#define SSTR  68
#define PSTR  72

#define TILE_HF (BQ * QVSTR)                 // 8704 halfs
#define SM_QHI  0
#define SM_QLO  (SM_QHI + TILE_HF)
#define SM_KHI  (SM_QLO + TILE_HF)
#define SM_VHI  (SM_KHI + TILE_HF)
#define SM_PHI  (SM_VHI + TILE_HF)
#define SM_PLO  (SM_PHI + BQ * PSTR)
#define SM_HF_END (SM_PLO + BQ * PSTR)
#define SMF_S   0
#define SMF_M   (SMF_S + BQ * SSTR)
#define SMF_L   (SMF_M + BQ)
#define SMF_A   (SMF_L + BQ)
#define SMF_END (SMF_A + BQ)
#define FLASH_SMEM_BYTES (SM_HF_END * 2 + SMF_END * 4)

__global__ __launch_bounds__(256) void flash_mma_kernel(
    const float* __restrict__ q, const float* __restrict__ k,
    const float* __restrict__ v, float* __restrict__ o)
{
    extern __shared__ char smraw[];
    __half* hf = (__half*)smraw;
    float* fp = (float*)(smraw + SM_HF_END * 2);

    __half* Qhi = hf + SM_QHI;
    __half* Qlo = hf + SM_QLO;
    __half* Khi = hf + SM_KHI;
    __half* Vhi = hf + SM_VHI;
    __half* Phi = hf + SM_PHI;
    __half* Plo = hf + SM_PLO;
    float* S    = fp + SMF_S;
    float* mrow = fp + SMF_M;
    float* lrow = fp + SMF_L;
    float* arow = fp + SMF_A;

    const int tid  = threadIdx.x;
    const int lane = tid & 31;
    const int wid  = tid >> 5;
    const int wq   = wid >> 2;
    const int wn   = wid & 3;
    const int qb   = gridDim.x - 1 - blockIdx.x;  // heavy blocks first
    const int h    = blockIdx.y;
    const int kvh  = h / (H_Q / KVH_);
    const int q0   = qb * BQ;
    const float scale = 0.08838834764831845f;

    for (int i = tid; i < BQ * 32; i += 256) {
        int r = i >> 5, c = (i & 31) * 4;
        float4 a4 = *(const float4*)(q + (size_t)(q0 + r) * QD + h * D_HEAD + c);
        split_store4h(a4, &Qhi[r * QVSTR + c], &Qlo[r * QVSTR + c]);
    }
    if (tid < BQ) { mrow[tid] = -1e30f; lrow[tid] = 0.f; }

    float accO[2][4][4];
    #pragma unroll
    for (int mi = 0; mi < 2; mi++)
        #pragma unroll
        for (int ni = 0; ni < 4; ni++)
            #pragma unroll
            for (int e = 0; e < 4; e++) accO[mi][ni][e] = 0.f;

    for (int jb = 0; jb <= qb; jb++) {
        __syncthreads();
        const int k0 = jb * BKV;
        for (int i = tid; i < BKV * 32; i += 256) {
            int r = i >> 5, c = (i & 31) * 4;
            float4 k4 = *(const float4*)(k + (size_t)(k0 + r) * KD + kvh * D_HEAD + c);
            float4 v4 = *(const float4*)(v + (size_t)(k0 + r) * KD + kvh * D_HEAD + c);
            pack_store4h(k4, &Khi[r * QVSTR + c]);
            pack_store4h(v4, &Vhi[r * QVSTR + c]);
        }
        __syncthreads();

        // ---- S = Q K^T (fp16x2) ----
        float accS[2][2][4];
        #pragma unroll
        for (int mi = 0; mi < 2; mi++)
            #pragma unroll
            for (int ni = 0; ni < 2; ni++)
                #pragma unroll
                for (int e = 0; e < 4; e++) accS[mi][ni][e] = 0.f;

        #pragma unroll
        for (int kk = 0; kk < 8; kk++) {
            unsigned ah[2][4], al[2][4], bh[2][2];
            const int arl = wq * 32 + (lane & 15);
            const int kcl = kk * 16 + (lane >> 4) * 8;
            ldsm_x4(smem_u32(&Qhi[arl * QVSTR + kcl]), ah[0]);
            ldsm_x4(smem_u32(&Qhi[(arl + 16) * QVSTR + kcl]), ah[1]);
            ldsm_x4(smem_u32(&Qlo[arl * QVSTR + kcl]), al[0]);
            ldsm_x4(smem_u32(&Qlo[(arl + 16) * QVSTR + kcl]), al[1]);
            const int brl = wn * 16 + (lane & 15);
            {
                unsigned r[4];
                ldsm_x4(smem_u32(&Khi[brl * QVSTR + kcl]), r);
                bh[0][0] = r[0]; bh[0][1] = r[2];
                bh[1][0] = r[1]; bh[1][1] = r[3];
            }
            #pragma unroll
            for (int mi = 0; mi < 2; mi++)
                #pragma unroll
                for (int ni = 0; ni < 2; ni++) {
                    mma_f16(accS[mi][ni], ah[mi], bh[ni]);
                    mma_f16(accS[mi][ni], al[mi], bh[ni]);
                }
        }
        #pragma unroll
        for (int mi = 0; mi < 2; mi++)
            #pragma unroll
            for (int ni = 0; ni < 2; ni++) {
                int r0 = wq * 32 + mi * 16 + (lane >> 2);
                int c0 = wn * 16 + ni * 8 + 2 * (lane & 3);
                *(float2*)&S[r0 * SSTR + c0] =
                    make_float2(accS[mi][ni][0] * scale, accS[mi][ni][1] * scale);
                *(float2*)&S[(r0 + 8) * SSTR + c0] =
                    make_float2(accS[mi][ni][2] * scale, accS[mi][ni][3] * scale);
            }
        __syncthreads();

        // ---- online softmax: 4 threads per row ----
        {
            const int r  = tid >> 2;
            const int c0 = (tid & 3) * 16;
            const bool diag = (jb == qb);
            float sv[16];
            float vmax = -1e30f;
            #pragma unroll
            for (int j = 0; j < 16; j++) {
                float x = S[r * SSTR + c0 + j];
                if (diag && (c0 + j) > r) x = -1e30f;
                sv[j] = x;
                vmax = fmaxf(vmax, x);
            }
            vmax = fmaxf(vmax, __shfl_xor_sync(0xffffffffu, vmax, 1));
            vmax = fmaxf(vmax, __shfl_xor_sync(0xffffffffu, vmax, 2));
            float m_old = mrow[r];
            float m_new = fmaxf(m_old, vmax);
            float rs = 0.f;
            #pragma unroll
            for (int j = 0; j < 16; j += 2) {
                float p0 = __expf(sv[j] - m_new);
                float p1 = __expf(sv[j + 1] - m_new);
                rs += p0 + p1;
                __half h0 = __float2half_rn(p0);
                __half h1 = __float2half_rn(p1);
                __half l0 = __float2half_rn(p0 - __half2float(h0));
                __half l1 = __float2half_rn(p1 - __half2float(h1));
                *(__half2*)&Phi[r * PSTR + c0 + j] = __halves2half2(h0, h1);
                *(__half2*)&Plo[r * PSTR + c0 + j] = __halves2half2(l0, l1);
            }
            rs += __shfl_xor_sync(0xffffffffu, rs, 1);
            rs += __shfl_xor_sync(0xffffffffu, rs, 2);
            if ((tid & 3) == 0) {
                float alpha = __expf(m_old - m_new);
                arow[r] = alpha;
                mrow[r] = m_new;
                lrow[r] = lrow[r] * alpha + rs;
            }
        }
        __syncthreads();

        // ---- rescale O by alpha ----
        {
            float alph[2][2];
            #pragma unroll
            for (int mi = 0; mi < 2; mi++) {
                int r0 = wq * 32 + mi * 16 + (lane >> 2);
                alph[mi][0] = arow[r0];
                alph[mi][1] = arow[r0 + 8];
            }
            #pragma unroll
            for (int mi = 0; mi < 2; mi++)
                #pragma unroll
                for (int ni = 0; ni < 4; ni++) {
                    accO[mi][ni][0] *= alph[mi][0];
                    accO[mi][ni][1] *= alph[mi][0];
                    accO[mi][ni][2] *= alph[mi][1];
                    accO[mi][ni][3] *= alph[mi][1];
                }
        }

        // ---- O += P V (fp16x2) ----
        #pragma unroll
        for (int kk = 0; kk < 4; kk++) {
            unsigned ph[2][4], pl[2][4], vh[4][2];
            const int arl = wq * 32 + (lane & 15);
            const int kcl = kk * 16 + (lane >> 4) * 8;
            ldsm_x4(smem_u32(&Phi[arl * PSTR + kcl]), ph[0]);
            ldsm_x4(smem_u32(&Phi[(arl + 16) * PSTR + kcl]), ph[1]);
            ldsm_x4(smem_u32(&Plo[arl * PSTR + kcl]), pl[0]);
            ldsm_x4(smem_u32(&Plo[(arl + 16) * PSTR + kcl]), pl[1]);
            const int krw = kk * 16 + ((lane >> 3) & 1) * 8 + (lane & 7);
            #pragma unroll
            for (int nb = 0; nb < 2; nb++) {
                const int ncl = wn * 32 + nb * 16 + (lane >> 4) * 8;
                unsigned r[4];
                ldsm_x4_t(smem_u32(&Vhi[krw * QVSTR + ncl]), r);
                vh[2 * nb][0] = r[0]; vh[2 * nb][1] = r[1];
                vh[2 * nb + 1][0] = r[2]; vh[2 * nb + 1][1] = r[3];
            }
            #pragma unroll
            for (int mi = 0; mi < 2; mi++)
                #pragma unroll
                for (int ni = 0; ni < 4; ni++) {
                    mma_f16(accO[mi][ni], ph[mi], vh[ni]);
                    mma_f16(accO[mi][ni], pl[mi], vh[ni]);
                }
        }
    }

    __syncthreads();
    #pragma unroll
    for (int mi = 0; mi < 2; mi++) {
        int r0 = wq * 32 + mi * 16 + (lane >> 2);
        float inv0 = 1.0f / lrow[r0];
        float inv1 = 1.0f / lrow[r0 + 8];
        #pragma unroll
        for (int ni = 0; ni < 4; ni++) {
            int c0 = h * D_HEAD + wn * 32 + ni * 8 + 2 * (lane & 3);
            *(float2*)(o + (size_t)(q0 + r0) * QD + c0) =
                make_float2(accO[mi][ni][0] * inv0, accO[mi][ni][1] * inv0);
            *(float2*)(o + (size_t)(q0 + r0 + 8) * QD + c0) =
                make_float2(accO[mi][ni][2] * inv1, accO[mi][ni][3] * inv1);
        }
    }
}

// ---------------------------------------------------------------------------
extern "C" void kernel_launch(void* const* d_in, const int* in_sizes, int n_in,
                              void* d_out, int out_size)
{
    const float* x  = (const float*)d_in[0];
    // d_in[1] = mask (tril) — causality hardcoded, ignored.
    const float* Wq = (const float*)d_in[2];
    const float* Wk = (const float*)d_in[3];
    const float* Wv = (const float*)d_in[4];
    const float* Wo = (const float*)d_in[5];
    float* out = (float*)d_out;

    float *q, *k, *v, *att;
    cudaGetSymbolAddress((void**)&q,   g_q);
    cudaGetSymbolAddress((void**)&k,   g_k);
    cudaGetSymbolAddress((void**)&v,   g_v);
    cudaGetSymbolAddress((void**)&att, g_att);

    cudaFuncSetAttribute(gemm_qkv_kernel,
                         cudaFuncAttributeMaxDynamicSharedMemorySize, GEMM_SMEM_BYTES);
    cudaFuncSetAttribute(gemm_fp16x2_kernel,
                         cudaFuncAttributeMaxDynamicSharedMemorySize, GEMM_SMEM_BYTES);
    cudaFuncSetAttribute(flash_mma_kernel,
                         cudaFuncAttributeMaxDynamicSharedMemorySize, FLASH_SMEM_BYTES);

    // 1. fused QKV projection (fp16x2 tensor cores)
    gemm_qkv_kernel<<<dim3(24, 32), 256, GEMM_SMEM_BYTES>>>(x, Wq, Wk, Wv, q, k, v);

    // 2. RoPE
    {
        int tq = T_SEQ * H_Q * (D_HEAD / 2);
        rope_kernel<<<(tq + 255) / 256, 256>>>(q, H_Q);
        int tk = T_SEQ * KVH_ * (D_HEAD / 2);
        rope_kernel<<<(tk + 255) / 256, 256>>>(k, KVH_);
    }

    // 3. flash attention (fp16x2 tensor cores)
    flash_mma_kernel<<<dim3(T_SEQ / BQ, H_Q), 256, FLASH_SMEM_BYTES>>>(q, k, v, att);

    // 4. output projection (fp16x2 tensor cores)
    gemm_fp16x2_kernel<<<dim3(C_DIM / 128, T_SEQ / 128), 256, GEMM_SMEM_BYTES>>>(
        T_SEQ, C_DIM, QD, att, Wo, out);
}

// round 11
// speedup vs baseline: 5.9344x; 1.1001x over previous
#include <cuda_runtime.h>
#include <cuda_fp16.h>
#include <stdint.h>
#include <math.h>

#define T_SEQ 4096
#define C_DIM 2048
#define H_Q   16
#define KVH_  4
#define D_HEAD 128
#define QD (H_Q * D_HEAD)    // 2048
#define KD (KVH_ * D_HEAD)   // 512

// Scratch (allocation-free rule: device globals)
__device__ float g_q[T_SEQ * QD];
__device__ float g_k[T_SEQ * KD];
__device__ float g_v[T_SEQ * KD];
__device__ float g_att[T_SEQ * QD];

__device__ __forceinline__ unsigned smem_u32(const void* p) {
    return (unsigned)__cvta_generic_to_shared(p);
}
__device__ __forceinline__ void ldsm_x4(unsigned addr, unsigned* r) {
    asm volatile("ldmatrix.sync.aligned.m8n8.x4.shared.b16 {%0,%1,%2,%3}, [%4];\n"
                 : "=r"(r[0]), "=r"(r[1]), "=r"(r[2]), "=r"(r[3]) : "r"(addr));
}
__device__ __forceinline__ void ldsm_x4_t(unsigned addr, unsigned* r) {
    asm volatile("ldmatrix.sync.aligned.m8n8.x4.trans.shared.b16 {%0,%1,%2,%3}, [%4];\n"
                 : "=r"(r[0]), "=r"(r[1]), "=r"(r[2]), "=r"(r[3]) : "r"(addr));
}
__device__ __forceinline__ void mma_f16(float* d, const unsigned* a, const unsigned* b) {
    asm volatile("mma.sync.aligned.m16n8k16.row.col.f32.f16.f16.f32 "
                 "{%0,%1,%2,%3}, {%4,%5,%6,%7}, {%8,%9}, {%0,%1,%2,%3};\n"
                 : "+f"(d[0]), "+f"(d[1]), "+f"(d[2]), "+f"(d[3])
                 : "r"(a[0]), "r"(a[1]), "r"(a[2]), "r"(a[3]),
                   "r"(b[0]), "r"(b[1]));
}
// split 4 fp32 into fp16 hi/lo planes
__device__ __forceinline__ void split_store4h(float4 v, __half* hi, __half* lo) {
    __half h0 = __float2half_rn(v.x);
    __half h1 = __float2half_rn(v.y);
    __half h2 = __float2half_rn(v.z);
    __half h3 = __float2half_rn(v.w);
    __half l0 = __float2half_rn(v.x - __half2float(h0));
    __half l1 = __float2half_rn(v.y - __half2float(h1));
    __half l2 = __float2half_rn(v.z - __half2float(h2));
    __half l3 = __float2half_rn(v.w - __half2float(h3));
    *(__half2*)(hi)     = __halves2half2(h0, h1);
    *(__half2*)(hi + 2) = __halves2half2(h2, h3);
    *(__half2*)(lo)     = __halves2half2(l0, l1);
    *(__half2*)(lo + 2) = __halves2half2(l2, l3);
}
// pack 4 fp32 into single fp16 plane
__device__ __forceinline__ void pack_store4h(float4 v, __half* dst) {
    *(__half2*)(dst)     = __halves2half2(__float2half_rn(v.x), __float2half_rn(v.y));
    *(__half2*)(dst + 2) = __halves2half2(__float2half_rn(v.z), __float2half_rn(v.w));
}

// ===========================================================================
// fp16x2 tensor-core GEMM: C[M,N] = A[M,K] @ B[K,N], row-major, fp32 in/out.
// A split hi/lo, B single plane. Block tile 128x128x32, 256 threads,
// 8 warps (2x4), 64x32 per warp. Double-buffered smem.
// Optional fused RoPE in the epilogue (rope != 0): rotates (even,odd) column
// pairs with angle t * theta^(-d2/64), t = output row, d2 = (col%128)/2.
// ===========================================================================
#define AS_STRIDE 40
#define BS_STRIDE 136
#define APL (128 * AS_STRIDE)   // 5120 halfs
#define BPL (32 * BS_STRIDE)    // 4352 halfs
#define BUF_ELEMS (2 * APL + BPL)              // 14592 halfs
#define GEMM_SMEM_BYTES (2 * BUF_ELEMS * 2)    // 58368 B

__device__ __forceinline__ void gemm_core(
    int N, int K, int rope,
    const float* __restrict__ A, const float* __restrict__ B,
    float* __restrict__ C, int bm0, int bn0, char* smraw)
{
    __half* bufs = (__half*)smraw;

    const int tid  = threadIdx.x;
    const int lane = tid & 31;
    const int wid  = tid >> 5;
    const int wm   = wid >> 2;
    const int wn   = wid & 3;

    const int ar = tid >> 3;
    const int ac = (tid & 7) * 4;
    const int br = tid >> 5;
    const int bc = (tid & 31) * 4;

    float acc[4][4][4];
    #pragma unroll
    for (int mi = 0; mi < 4; mi++)
        #pragma unroll
        for (int ni = 0; ni < 4; ni++)
            #pragma unroll
            for (int e = 0; e < 4; e++) acc[mi][ni][e] = 0.f;

    const int ktiles = K >> 5;

    float4 ra[4], rb[4];
    #pragma unroll
    for (int i = 0; i < 4; i++) {
        ra[i] = *(const float4*)(A + (size_t)(bm0 + ar + i * 32) * K + ac);
        rb[i] = *(const float4*)(B + (size_t)(br + i * 8) * N + bn0 + bc);
    }
    {
        __half* AsHi = bufs;
        __half* AsLo = AsHi + APL;
        __half* Bs   = AsLo + APL;
        #pragma unroll
        for (int i = 0; i < 4; i++) {
            int r = ar + i * 32;
            split_store4h(ra[i], &AsHi[r * AS_STRIDE + ac], &AsLo[r * AS_STRIDE + ac]);
            pack_store4h(rb[i], &Bs[(br + i * 8) * BS_STRIDE + bc]);
        }
    }
    __syncthreads();

    for (int kt = 0; kt < ktiles; kt++) {
        const bool has_next = (kt + 1 < ktiles);
        if (has_next) {
            int k0 = (kt + 1) << 5;
            #pragma unroll
            for (int i = 0; i < 4; i++) {
                ra[i] = *(const float4*)(A + (size_t)(bm0 + ar + i * 32) * K + k0 + ac);
                rb[i] = *(const float4*)(B + (size_t)(k0 + br + i * 8) * N + bn0 + bc);
            }
        }

        __half* AsHi = bufs + (kt & 1) * BUF_ELEMS;
        __half* AsLo = AsHi + APL;
        __half* Bs   = AsLo + APL;

        #pragma unroll
        for (int ks = 0; ks < 2; ks++) {
            const int k = ks * 16;
            unsigned ah[4][4], al[4][4], bh[4][2];

            const int arl = wm * 64 + (lane & 15);
            const int kcl = k + (lane >> 4) * 8;
            #pragma unroll
            for (int mi = 0; mi < 4; mi++) {
                ldsm_x4(smem_u32(&AsHi[(arl + mi * 16) * AS_STRIDE + kcl]), ah[mi]);
                ldsm_x4(smem_u32(&AsLo[(arl + mi * 16) * AS_STRIDE + kcl]), al[mi]);
            }
            const int krw = k + ((lane >> 3) & 1) * 8 + (lane & 7);
            #pragma unroll
            for (int nb = 0; nb < 2; nb++) {
                const int ncl = wn * 32 + nb * 16 + (lane >> 4) * 8;
                unsigned r[4];
                ldsm_x4_t(smem_u32(&Bs[krw * BS_STRIDE + ncl]), r);
                bh[2 * nb][0] = r[0]; bh[2 * nb][1] = r[1];
                bh[2 * nb + 1][0] = r[2]; bh[2 * nb + 1][1] = r[3];
            }

            #pragma unroll
            for (int mi = 0; mi < 4; mi++)
                #pragma unroll
                for (int ni = 0; ni < 4; ni++) {
                    mma_f16(acc[mi][ni], ah[mi], bh[ni]);
                    mma_f16(acc[mi][ni], al[mi], bh[ni]);
                }
        }

        if (has_next) {
            __half* nAsHi = bufs + ((kt + 1) & 1) * BUF_ELEMS;
            __half* nAsLo = nAsHi + APL;
            __half* nBs   = nAsLo + APL;
            #pragma unroll
            for (int i = 0; i < 4; i++) {
                int r = ar + i * 32;
                split_store4h(ra[i], &nAsHi[r * AS_STRIDE + ac], &nAsLo[r * AS_STRIDE + ac]);
                pack_store4h(rb[i], &nBs[(br + i * 8) * BS_STRIDE + bc]);
            }
        }
        __syncthreads();
    }

    const int gid = lane >> 2, tig = lane & 3;

    // fused RoPE: acc[mi][ni] holds cols (c0, c0+1) at rows r0 and r0+8 —
    // exactly the interleaved (even,odd) pairs the rotation needs.
    if (rope) {
        #pragma unroll
        for (int ni = 0; ni < 4; ni++) {
            int c0 = bn0 + wn * 32 + ni * 8 + tig * 2;
            int d2 = (c0 & 127) >> 1;
            float inv = (float)exp(-(double)d2 * 0.14391156831212787); // ln(1e4)/64
            #pragma unroll
            for (int mi = 0; mi < 4; mi++) {
                int t0 = bm0 + wm * 64 + mi * 16 + gid;
                float a0 = (float)t0 * inv;
                float a1 = (float)(t0 + 8) * inv;
                float c0f = cosf(a0), s0f = sinf(a0);
                float c1f = cosf(a1), s1f = sinf(a1);
                float x0 = acc[mi][ni][0], x1 = acc[mi][ni][1];
                acc[mi][ni][0] = x0 * c0f - x1 * s0f;
                acc[mi][ni][1] = x0 * s0f + x1 * c0f;
                x0 = acc[mi][ni][2]; x1 = acc[mi][ni][3];
                acc[mi][ni][2] = x0 * c1f - x1 * s1f;
                acc[mi][ni][3] = x0 * s1f + x1 * c1f;
            }
        }
    }

    #pragma unroll
    for (int mi = 0; mi < 4; mi++)
        #pragma unroll
        for (int ni = 0; ni < 4; ni++) {
            int r0 = bm0 + wm * 64 + mi * 16 + gid;
            int c0 = bn0 + wn * 32 + ni * 8 + tig * 2;
            *(float2*)(C + (size_t)r0 * N + c0) =
                make_float2(acc[mi][ni][0], acc[mi][ni][1]);
            *(float2*)(C + (size_t)(r0 + 8) * N + c0) =
                make_float2(acc[mi][ni][2], acc[mi][ni][3]);
        }
}

// Fused QKV projection: grid (24, 32). bx<16 -> Q (rope), <20 -> K (rope), else V.
__global__ __launch_bounds__(256) void gemm_qkv_kernel(
    const float* __restrict__ x,
    const float* __restrict__ Wq, const float* __restrict__ Wk,
    const float* __restrict__ Wv,
    float* __restrict__ q, float* __restrict__ k, float* __restrict__ v)
{
    extern __shared__ char smraw[];
    const int bx = blockIdx.x;
    const int bm0 = blockIdx.y * 128;
    if (bx < 16) {
        gemm_core(QD, C_DIM, 1, x, Wq, q, bm0, bx * 128, smraw);
    } else if (bx < 20) {
        gemm_core(KD, C_DIM, 1, x, Wk, k, bm0, (bx - 16) * 128, smraw);
    } else {
        gemm_core(KD, C_DIM, 0, x, Wv, v, bm0, (bx - 20) * 128, smraw);
    }
}

__global__ __launch_bounds__(256) void gemm_fp16x2_kernel(
    int M, int N, int K,
    const float* __restrict__ A, const float* __restrict__ B,
    float* __restrict__ C)
{
    extern __shared__ char smraw[];
    gemm_core(N, K, 0, A, B, C, blockIdx.y * 128, blockIdx.x * 128, smraw);
}

// ===========================================================================
// Flash attention, fp16x2 MMA, in-register softmax.
// Q split hi/lo, K/V/P single fp16 plane. P aliases K's smem (K dead after
// the S MMA). 64 q-rows x 1 head per CTA, 256 threads, warp grid 2(q) x 4(n).
// ===========================================================================
#define BQ 64
#define BKV 64
#define QVSTR 136
#define PSTR  72

#define SM_QHI 0
#define SM_QLO 8704
#define SM_KHI 17408
#define SM_PHI 17408              // aliases K (K dead after S MMA)
#define SM_VHI 26112
#define SM_HF_END 34816           // halfs
#define SMF_WRED 0                // 4 x 64 floats (max, then sums)
#define SMF_M    256
#define SMF_L    320
#define SMF_A    384
#define SMF_END  448
#define FLASH_SMEM_BYTES (SM_HF_END * 2 + SMF_END * 4)   // 71424 B

__global__ __launch_bounds__(256, 3) void flash_mma_kernel(
    const float* __restrict__ q, const float* __restrict__ k,
    const float* __restrict__ v, float* __restrict__ o)
{
    extern __shared__ char smraw[];
    __half* hf = (__half*)smraw;
    float*  fp = (float*)(smraw + SM_HF_END * 2);

    __half* Qhi = hf + SM_QHI;
    __half* Qlo = hf + SM_QLO;
    __half* Khi = hf + SM_KHI;
    __half* Phi = hf + SM_PHI;
    __half* Vhi = hf + SM_VHI;
    float* wred = fp + SMF_WRED;
    float* mrow = fp + SMF_M;
    float* lrow = fp + SMF_L;
    float* arow = fp + SMF_A;

    const int tid  = threadIdx.x;
    const int lane = tid & 31;
    const int wid  = tid >> 5;
    const int wq   = wid >> 2;
    const int wn   = wid & 3;
    const int qb   = gridDim.x - 1 - blockIdx.x;  // heavy blocks first
    const int h    = blockIdx.y;
    const int kvh  = h / (H_Q / KVH_);
    const int q0   = qb * BQ;
    const float scale = 0.08838834764831845f;

    for (int i = tid; i < BQ * 32; i += 256) {
        int r = i >> 5, c = (i & 31) * 4;
        float4 a4 = *(const float4*)(q + (size_t)(q0 + r) * QD + h * D_HEAD + c);
        split_store4h(a4, &Qhi[r * QVSTR + c], &Qlo[r * QVSTR + c]);
    }
    if (tid < BQ) { mrow[tid] = -1e30f; lrow[tid] = 0.f; }

    float accO[2][4][4];
    #pragma unroll
    for (int mi = 0; mi < 2; mi++)
        #pragma unroll
        for (int ni = 0; ni < 4; ni++)
            #pragma unroll
            for (int e = 0; e < 4; e++) accO[mi][ni][e] = 0.f;

    for (int jb = 0; jb <= qb; jb++) {
        __syncthreads();   // S1: K/V/P smem free, wred free, (iter0: Q/m/l visible)
        const int k0 = jb * BKV;
        for (int i = tid; i < BKV * 32; i += 256) {
            int r = i >> 5, c = (i & 31) * 4;
            float4 k4 = *(const float4*)(k + (size_t)(k0 + r) * KD + kvh * D_HEAD + c);
            float4 v4 = *(const float4*)(v + (size_t)(k0 + r) * KD + kvh * D_HEAD + c);
            pack_store4h(k4, &Khi[r * QVSTR + c]);
            pack_store4h(v4, &Vhi[r * QVSTR + c]);
        }
        __syncthreads();   // S2: tiles staged

        // ---- S = Q K^T (fp16x2), warp tile 32x16 ----
        float accS[2][2][4];
        #pragma unroll
        for (int mi = 0; mi < 2; mi++)
            #pragma unroll
            for (int ni = 0; ni < 2; ni++)
                #pragma unroll
                for (int e = 0; e < 4; e++) accS[mi][ni][e] = 0.f;

        #pragma unroll
        for (int kk = 0; kk < 8; kk++) {
            unsigned ah[2][4], al[2][4], bh[2][2];
            const int arl = wq * 32 + (lane & 15);
            const int kcl = kk * 16 + (lane >> 4) * 8;
            ldsm_x4(smem_u32(&Qhi[arl * QVSTR + kcl]), ah[0]);
            ldsm_x4(smem_u32(&Qhi[(arl + 16) * QVSTR + kcl]), ah[1]);
            ldsm_x4(smem_u32(&Qlo[arl * QVSTR + kcl]), al[0]);
            ldsm_x4(smem_u32(&Qlo[(arl + 16) * QVSTR + kcl]), al[1]);
            const int brl = wn * 16 + (lane & 15);
            {
                unsigned r[4];
                ldsm_x4(smem_u32(&Khi[brl * QVSTR + kcl]), r);
                bh[0][0] = r[0]; bh[0][1] = r[2];
                bh[1][0] = r[1]; bh[1][1] = r[3];
            }
            #pragma unroll
            for (int mi = 0; mi < 2; mi++)
                #pragma unroll
                for (int ni = 0; ni < 2; ni++) {
                    mma_f16(accS[mi][ni], ah[mi], bh[ni]);
                    mma_f16(accS[mi][ni], al[mi], bh[ni]);
                }
        }

        // ---- mask + scale + warp-local row max (in registers) ----
        const bool diag = (jb == qb);
        float mv[2][2];
        #pragma unroll
        for (int mi = 0; mi < 2; mi++)
            #pragma unroll
            for (int hf2 = 0; hf2 < 2; hf2++) {
                int row_g = q0 + wq * 32 + mi * 16 + (lane >> 2) + 8 * hf2;
                float mt = -1e30f;
                #pragma unroll
                for (int ni = 0; ni < 2; ni++)
                    #pragma unroll
                    for (int e = 0; e < 2; e++) {
                        int col_g = k0 + wn * 16 + ni * 8 + 2 * (lane & 3) + e;
                        float s = accS[mi][ni][2 * hf2 + e] * scale;
                        if (diag && col_g > row_g) s = -1e30f;
                        accS[mi][ni][2 * hf2 + e] = s;
                        mt = fmaxf(mt, s);
                    }
                mt = fmaxf(mt, __shfl_xor_sync(0xffffffffu, mt, 1));
                mt = fmaxf(mt, __shfl_xor_sync(0xffffffffu, mt, 2));
                mv[mi][hf2] = mt;
            }
        if ((lane & 3) == 0) {
            #pragma unroll
            for (int mi = 0; mi < 2; mi++)
                #pragma unroll
                for (int hf2 = 0; hf2 < 2; hf2++)
                    wred[wn * 64 + wq * 32 + mi * 16 + (lane >> 2) + 8 * hf2] = mv[mi][hf2];
        }
        __syncthreads();   // S3: warp maxes in wred

        if (tid < BQ) {
            float mo = mrow[tid];
            float mn = fmaxf(fmaxf(wred[tid], wred[64 + tid]),
                             fmaxf(wred[128 + tid], wred[192 + tid]));
            mn = fmaxf(mn, mo);
            mrow[tid] = mn;
            arow[tid] = __expf(mo - mn);
        }
        __syncthreads();   // S4: mrow/arow ready; wred reusable

        // ---- exp, write P (fp16) in ldsm layout, warp-partial row sums ----
        {
            float mn[2][2], st[2][2];
            #pragma unroll
            for (int mi = 0; mi < 2; mi++)
                #pragma unroll
                for (int hf2 = 0; hf2 < 2; hf2++) {
                    mn[mi][hf2] = mrow[wq * 32 + mi * 16 + (lane >> 2) + 8 * hf2];
                    st[mi][hf2] = 0.f;
                }
            #pragma unroll
            for (int mi = 0; mi < 2; mi++)
                #pragma unroll
                for (int ni = 0; ni < 2; ni++)
                    #pragma unroll
                    for (int hf2 = 0; hf2 < 2; hf2++) {
                        float p0 = __expf(accS[mi][ni][2 * hf2 + 0] - mn[mi][hf2]);
                        float p1 = __expf(accS[mi][ni][2 * hf2 + 1] - mn[mi][hf2]);
                        __half h0 = __float2half_rn(p0);
                        __half h1 = __float2half_rn(p1);
                        st[mi][hf2] += __half2float(h0) + __half2float(h1);
                        int rl = wq * 32 + mi * 16 + (lane >> 2) + 8 * hf2;
                        int cl = wn * 16 + ni * 8 + 2 * (lane & 3);
                        *(__half2*)&Phi[rl * PSTR + cl] = __halves2half2(h0, h1);
                    }
            #pragma unroll
            for (int mi = 0; mi < 2; mi++)
                #pragma unroll
                for (int hf2 = 0; hf2 < 2; hf2++) {
                    float s = st[mi][hf2];
                    s += __shfl_xor_sync(0xffffffffu, s, 1);
                    s += __shfl_xor_sync(0xffffffffu, s, 2);
                    st[mi][hf2] = s;
                }
            if ((lane & 3) == 0) {
                #pragma unroll
                for (int mi = 0; mi < 2; mi++)
                    #pragma unroll
                    for (int hf2 = 0; hf2 < 2; hf2++)
                        wred[wn * 64 + wq * 32 + mi * 16 + (lane >> 2) + 8 * hf2] = st[mi][hf2];
            }
        }
        // rescale O accumulators by alpha (arow valid since S4)
        {
            #pragma unroll
            for (int mi = 0; mi < 2; mi++) {
                float a0 = arow[wq * 32 + mi * 16 + (lane >> 2)];
                float a1 = arow[wq * 32 + mi * 16 + (lane >> 2) + 8];
                #pragma unroll
                for (int ni = 0; ni < 4; ni++) {
                    accO[mi][ni][0] *= a0;
                    accO[mi][ni][1] *= a0;
                    accO[mi][ni][2] *= a1;
                    accO[mi][ni][3] *= a1;
                }
            }
        }
        __syncthreads();   // S5: P + partial sums ready

        if (tid < BQ) {
            lrow[tid] = lrow[tid] * arow[tid] +
                        (wred[tid] + wred[64 + tid]) + (wred[128 + tid] + wred[192 + tid]);
        }

        // ---- O += P V (fp16, single plane), warp tile 32x32 ----
        #pragma unroll
        for (int kk = 0; kk < 4; kk++) {
            unsigned ph[2][4], vh[4][2];
            const int arl = wq * 32 + (lane & 15);
            const int kcl = kk * 16 + (lane >> 4) * 8;
            ldsm_x4(smem_u32(&Phi[arl * PSTR + kcl]), ph[0]);
            ldsm_x4(smem_u32(&Phi[(arl + 16) * PSTR + kcl]), ph[1]);
            const int krw = kk * 16 + ((lane >> 3) & 1) * 8 + (lane & 7);
            #pragma unroll
            for (int nb = 0; nb < 2; nb++) {
                const int ncl = wn * 32 + nb * 16 + (lane >> 4) * 8;
                unsigned r[4];
                ldsm_x4_t(smem_u32(&Vhi[krw * QVSTR + ncl]), r);
                vh[2 * nb][0] = r[0]; vh[2 * nb][1] = r[1];
                vh[2 * nb + 1][0] = r[2]; vh[2 * nb + 1][1] = r[3];
            }
            #pragma unroll
            for (int mi = 0; mi < 2; mi++)
                #pragma unroll
                for (int ni = 0; ni < 4; ni++)
                    mma_f16(accO[mi][ni], ph[mi], vh[ni]);
        }
    }

    __syncthreads();
    #pragma unroll
    for (int mi = 0; mi < 2; mi++) {
        int r0 = wq * 32 + mi * 16 + (lane >> 2);
        float inv0 = 1.0f / lrow[r0];
        float inv1 = 1.0f / lrow[r0 + 8];
        #pragma unroll
        for (int ni = 0; ni < 4; ni++) {
            int c0 = h * D_HEAD + wn * 32 + ni * 8 + 2 * (lane & 3);
            *(float2*)(o + (size_t)(q0 + r0) * QD + c0) =
                make_float2(accO[mi][ni][0] * inv0, accO[mi][ni][1] * inv0);
            *(float2*)(o + (size_t)(q0 + r0 + 8) * QD + c0) =
                make_float2(accO[mi][ni][2] * inv1, accO[mi][ni][3] * inv1);
        }
    }
}

// ---------------------------------------------------------------------------
extern "C" void kernel_launch(void* const* d_in, const int* in_sizes, int n_in,
                              void* d_out, int out_size)
{
    const float* x  = (const float*)d_in[0];
    // d_in[1] = mask (tril) — causality hardcoded, ignored.
    const float* Wq = (const float*)d_in[2];
    const float* Wk = (const float*)d_in[3];
    const float* Wv = (const float*)d_in[4];
    const float* Wo = (const float*)d_in[5];
    float* out = (float*)d_out;

    float *q, *k, *v, *att;
    cudaGetSymbolAddress((void**)&q,   g_q);
    cudaGetSymbolAddress((void**)&k,   g_k);
    cudaGetSymbolAddress((void**)&v,   g_v);
    cudaGetSymbolAddress((void**)&att, g_att);

    cudaFuncSetAttribute(gemm_qkv_kernel,
                         cudaFuncAttributeMaxDynamicSharedMemorySize, GEMM_SMEM_BYTES);
    cudaFuncSetAttribute(gemm_fp16x2_kernel,
                         cudaFuncAttributeMaxDynamicSharedMemorySize, GEMM_SMEM_BYTES);
    cudaFuncSetAttribute(flash_mma_kernel,
                         cudaFuncAttributeMaxDynamicSharedMemorySize, FLASH_SMEM_BYTES);

    // 1. fused QKV projection + RoPE (fp16x2 tensor cores)
    gemm_qkv_kernel<<<dim3(24, 32), 256, GEMM_SMEM_BYTES>>>(x, Wq, Wk, Wv, q, k, v);

    // 2. flash attention (fp16x2, in-register softmax)
    flash_mma_kernel<<<dim3(T_SEQ / BQ, H_Q), 256, FLASH_SMEM_BYTES>>>(q, k, v, att);

    // 3. output projection
    gemm_fp16x2_kernel<<<dim3(C_DIM / 128, T_SEQ / 128), 256, GEMM_SMEM_BYTES>>>(
        T_SEQ, C_DIM, QD, att, Wo, out);
}

// round 12
// speedup vs baseline: 6.1735x; 1.0403x over previous
#include <cuda_runtime.h>
#include <cuda_fp16.h>
#include <stdint.h>
#include <math.h>

#define T_SEQ 4096
#define C_DIM 2048
#define H_Q   16
#define KVH_  4
#define D_HEAD 128
#define QD (H_Q * D_HEAD)    // 2048
#define KD (KVH_ * D_HEAD)   // 512

// Scratch (allocation-free rule: device globals)
__device__ float g_q[T_SEQ * QD];
__device__ float g_k[T_SEQ * KD];
__device__ float g_v[T_SEQ * KD];
__device__ float g_att[T_SEQ * QD];

__device__ __forceinline__ unsigned smem_u32(const void* p) {
    return (unsigned)__cvta_generic_to_shared(p);
}
__device__ __forceinline__ void ldsm_x4(unsigned addr, unsigned* r) {
    asm volatile("ldmatrix.sync.aligned.m8n8.x4.shared.b16 {%0,%1,%2,%3}, [%4];\n"
                 : "=r"(r[0]), "=r"(r[1]), "=r"(r[2]), "=r"(r[3]) : "r"(addr));
}
__device__ __forceinline__ void ldsm_x4_t(unsigned addr, unsigned* r) {
    asm volatile("ldmatrix.sync.aligned.m8n8.x4.trans.shared.b16 {%0,%1,%2,%3}, [%4];\n"
                 : "=r"(r[0]), "=r"(r[1]), "=r"(r[2]), "=r"(r[3]) : "r"(addr));
}
__device__ __forceinline__ void mma_f16(float* d, const unsigned* a, const unsigned* b) {
    asm volatile("mma.sync.aligned.m16n8k16.row.col.f32.f16.f16.f32 "
                 "{%0,%1,%2,%3}, {%4,%5,%6,%7}, {%8,%9}, {%0,%1,%2,%3};\n"
                 : "+f"(d[0]), "+f"(d[1]), "+f"(d[2]), "+f"(d[3])
                 : "r"(a[0]), "r"(a[1]), "r"(a[2]), "r"(a[3]),
                   "r"(b[0]), "r"(b[1]));
}
// split 4 fp32 into fp16 hi/lo planes
__device__ __forceinline__ void split_store4h(float4 v, __half* hi, __half* lo) {
    __half h0 = __float2half_rn(v.x);
    __half h1 = __float2half_rn(v.y);
    __half h2 = __float2half_rn(v.z);
    __half h3 = __float2half_rn(v.w);
    __half l0 = __float2half_rn(v.x - __half2float(h0));
    __half l1 = __float2half_rn(v.y - __half2float(h1));
    __half l2 = __float2half_rn(v.z - __half2float(h2));
    __half l3 = __float2half_rn(v.w - __half2float(h3));
    *(__half2*)(hi)     = __halves2half2(h0, h1);
    *(__half2*)(hi + 2) = __halves2half2(h2, h3);
    *(__half2*)(lo)     = __halves2half2(l0, l1);
    *(__half2*)(lo + 2) = __halves2half2(l2, l3);
}
// pack 4 fp32 into single fp16 plane
__device__ __forceinline__ void pack_store4h(float4 v, __half* dst) {
    *(__half2*)(dst)     = __halves2half2(__float2half_rn(v.x), __float2half_rn(v.y));
    *(__half2*)(dst + 2) = __halves2half2(__float2half_rn(v.z), __float2half_rn(v.w));
}

// ===========================================================================
// fp16x2 tensor-core GEMM (unchanged from R11): C = A @ B, A split hi/lo,
// B single plane, 128x128x32 tile, double-buffered, optional fused RoPE.
// ===========================================================================
#define AS_STRIDE 40
#define BS_STRIDE 136
#define APL (128 * AS_STRIDE)
#define BPL (32 * BS_STRIDE)
#define BUF_ELEMS (2 * APL + BPL)
#define GEMM_SMEM_BYTES (2 * BUF_ELEMS * 2)

__device__ __forceinline__ void gemm_core(
    int N, int K, int rope,
    const float* __restrict__ A, const float* __restrict__ B,
    float* __restrict__ C, int bm0, int bn0, char* smraw)
{
    __half* bufs = (__half*)smraw;

    const int tid  = threadIdx.x;
    const int lane = tid & 31;
    const int wid  = tid >> 5;
    const int wm   = wid >> 2;
    const int wn   = wid & 3;

    const int ar = tid >> 3;
    const int ac = (tid & 7) * 4;
    const int br = tid >> 5;
    const int bc = (tid & 31) * 4;

    float acc[4][4][4];
    #pragma unroll
    for (int mi = 0; mi < 4; mi++)
        #pragma unroll
        for (int ni = 0; ni < 4; ni++)
            #pragma unroll
            for (int e = 0; e < 4; e++) acc[mi][ni][e] = 0.f;

    const int ktiles = K >> 5;

    float4 ra[4], rb[4];
    #pragma unroll
    for (int i = 0; i < 4; i++) {
        ra[i] = *(const float4*)(A + (size_t)(bm0 + ar + i * 32) * K + ac);
        rb[i] = *(const float4*)(B + (size_t)(br + i * 8) * N + bn0 + bc);
    }
    {
        __half* AsHi = bufs;
        __half* AsLo = AsHi + APL;
        __half* Bs   = AsLo + APL;
        #pragma unroll
        for (int i = 0; i < 4; i++) {
            int r = ar + i * 32;
            split_store4h(ra[i], &AsHi[r * AS_STRIDE + ac], &AsLo[r * AS_STRIDE + ac]);
            pack_store4h(rb[i], &Bs[(br + i * 8) * BS_STRIDE + bc]);
        }
    }
    __syncthreads();

    for (int kt = 0; kt < ktiles; kt++) {
        const bool has_next = (kt + 1 < ktiles);
        if (has_next) {
            int k0 = (kt + 1) << 5;
            #pragma unroll
            for (int i = 0; i < 4; i++) {
                ra[i] = *(const float4*)(A + (size_t)(bm0 + ar + i * 32) * K + k0 + ac);
                rb[i] = *(const float4*)(B + (size_t)(k0 + br + i * 8) * N + bn0 + bc);
            }
        }

        __half* AsHi = bufs + (kt & 1) * BUF_ELEMS;
        __half* AsLo = AsHi + APL;
        __half* Bs   = AsLo + APL;

        #pragma unroll
        for (int ks = 0; ks < 2; ks++) {
            const int k = ks * 16;
            unsigned ah[4][4], al[4][4], bh[4][2];

            const int arl = wm * 64 + (lane & 15);
            const int kcl = k + (lane >> 4) * 8;
            #pragma unroll
            for (int mi = 0; mi < 4; mi++) {
                ldsm_x4(smem_u32(&AsHi[(arl + mi * 16) * AS_STRIDE + kcl]), ah[mi]);
                ldsm_x4(smem_u32(&AsLo[(arl + mi * 16) * AS_STRIDE + kcl]), al[mi]);
            }
            const int krw = k + ((lane >> 3) & 1) * 8 + (lane & 7);
            #pragma unroll
            for (int nb = 0; nb < 2; nb++) {
                const int ncl = wn * 32 + nb * 16 + (lane >> 4) * 8;
                unsigned r[4];
                ldsm_x4_t(smem_u32(&Bs[krw * BS_STRIDE + ncl]), r);
                bh[2 * nb][0] = r[0]; bh[2 * nb][1] = r[1];
                bh[2 * nb + 1][0] = r[2]; bh[2 * nb + 1][1] = r[3];
            }

            #pragma unroll
            for (int mi = 0; mi < 4; mi++)
                #pragma unroll
                for (int ni = 0; ni < 4; ni++) {
                    mma_f16(acc[mi][ni], ah[mi], bh[ni]);
                    mma_f16(acc[mi][ni], al[mi], bh[ni]);
                }
        }

        if (has_next) {
            __half* nAsHi = bufs + ((kt + 1) & 1) * BUF_ELEMS;
            __half* nAsLo = nAsHi + APL;
            __half* nBs   = nAsLo + APL;
            #pragma unroll
            for (int i = 0; i < 4; i++) {
                int r = ar + i * 32;
                split_store4h(ra[i], &nAsHi[r * AS_STRIDE + ac], &nAsLo[r * AS_STRIDE + ac]);
                pack_store4h(rb[i], &nBs[(br + i * 8) * BS_STRIDE + bc]);
            }
        }
        __syncthreads();
    }

    const int gid = lane >> 2, tig = lane & 3;

    if (rope) {
        #pragma unroll
        for (int ni = 0; ni < 4; ni++) {
            int c0 = bn0 + wn * 32 + ni * 8 + tig * 2;
            int d2 = (c0 & 127) >> 1;
            float inv = (float)exp(-(double)d2 * 0.14391156831212787); // ln(1e4)/64
            #pragma unroll
            for (int mi = 0; mi < 4; mi++) {
                int t0 = bm0 + wm * 64 + mi * 16 + gid;
                float a0 = (float)t0 * inv;
                float a1 = (float)(t0 + 8) * inv;
                float c0f = cosf(a0), s0f = sinf(a0);
                float c1f = cosf(a1), s1f = sinf(a1);
                float x0 = acc[mi][ni][0], x1 = acc[mi][ni][1];
                acc[mi][ni][0] = x0 * c0f - x1 * s0f;
                acc[mi][ni][1] = x0 * s0f + x1 * c0f;
                x0 = acc[mi][ni][2]; x1 = acc[mi][ni][3];
                acc[mi][ni][2] = x0 * c1f - x1 * s1f;
                acc[mi][ni][3] = x0 * s1f + x1 * c1f;
            }
        }
    }

    #pragma unroll
    for (int mi = 0; mi < 4; mi++)
        #pragma unroll
        for (int ni = 0; ni < 4; ni++) {
            int r0 = bm0 + wm * 64 + mi * 16 + gid;
            int c0 = bn0 + wn * 32 + ni * 8 + tig * 2;
            *(float2*)(C + (size_t)r0 * N + c0) =
                make_float2(acc[mi][ni][0], acc[mi][ni][1]);
            *(float2*)(C + (size_t)(r0 + 8) * N + c0) =
                make_float2(acc[mi][ni][2], acc[mi][ni][3]);
        }
}

__global__ __launch_bounds__(256) void gemm_qkv_kernel(
    const float* __restrict__ x,
    const float* __restrict__ Wq, const float* __restrict__ Wk,
    const float* __restrict__ Wv,
    float* __restrict__ q, float* __restrict__ k, float* __restrict__ v)
{
    extern __shared__ char smraw[];
    const int bx = blockIdx.x;
    const int bm0 = blockIdx.y * 128;
    if (bx < 16) {
        gemm_core(QD, C_DIM, 1, x, Wq, q, bm0, bx * 128, smraw);
    } else if (bx < 20) {
        gemm_core(KD, C_DIM, 1, x, Wk, k, bm0, (bx - 16) * 128, smraw);
    } else {
        gemm_core(KD, C_DIM, 0, x, Wv, v, bm0, (bx - 20) * 128, smraw);
    }
}

__global__ __launch_bounds__(256) void gemm_fp16x2_kernel(
    int M, int N, int K,
    const float* __restrict__ A, const float* __restrict__ B,
    float* __restrict__ C)
{
    extern __shared__ char smraw[];
    gemm_core(N, K, 0, A, B, C, blockIdx.y * 128, blockIdx.x * 128, smraw);
}

// ===========================================================================
// Flash attention, fp16x2 MMA, in-register softmax, BKV=128.
// Q split hi/lo; K/V/P single fp16 plane. P aliases K's smem.
// 64 q-rows x 1 head per CTA, 256 threads, warp grid 2(q) x 4(n).
// S warp tile 32x32; PV warp tile 32x32 over d.
// ===========================================================================
#define BQ 64
#define BKV 128
#define QVSTR 136
#define PSTR  136

#define SM_QHI 0
#define SM_QLO 8704                       // 64*136
#define SM_KHI 17408
#define SM_PHI 17408                      // P (64x136) aliases K (dead after S MMA)
#define SM_VHI (17408 + 128 * QVSTR)      // 34816
#define SM_HF_END (SM_VHI + 128 * QVSTR)  // 52224 halfs
#define SMF_WRED 0                        // 4 x 64 floats (max, then sums)
#define SMF_M    256
#define SMF_L    320
#define SMF_A    384
#define SMF_END  448
#define FLASH_SMEM_BYTES (SM_HF_END * 2 + SMF_END * 4)   // 106240 B

__global__ __launch_bounds__(256, 2) void flash_mma_kernel(
    const float* __restrict__ q, const float* __restrict__ k,
    const float* __restrict__ v, float* __restrict__ o)
{
    extern __shared__ char smraw[];
    __half* hf = (__half*)smraw;
    float*  fp = (float*)(smraw + SM_HF_END * 2);

    __half* Qhi = hf + SM_QHI;
    __half* Qlo = hf + SM_QLO;
    __half* Khi = hf + SM_KHI;
    __half* Phi = hf + SM_PHI;
    __half* Vhi = hf + SM_VHI;
    float* wred = fp + SMF_WRED;
    float* mrow = fp + SMF_M;
    float* lrow = fp + SMF_L;
    float* arow = fp + SMF_A;

    const int tid  = threadIdx.x;
    const int lane = tid & 31;
    const int wid  = tid >> 5;
    const int wq   = wid >> 2;
    const int wn   = wid & 3;
    const int qb   = gridDim.x - 1 - blockIdx.x;  // heavy blocks first
    const int h    = blockIdx.y;
    const int kvh  = h / (H_Q / KVH_);
    const int q0   = qb * BQ;
    const float scale = 0.08838834764831845f;

    for (int i = tid; i < BQ * 32; i += 256) {
        int r = i >> 5, c = (i & 31) * 4;
        float4 a4 = *(const float4*)(q + (size_t)(q0 + r) * QD + h * D_HEAD + c);
        split_store4h(a4, &Qhi[r * QVSTR + c], &Qlo[r * QVSTR + c]);
    }
    if (tid < BQ) { mrow[tid] = -1e30f; lrow[tid] = 0.f; }

    float accO[2][4][4];
    #pragma unroll
    for (int mi = 0; mi < 2; mi++)
        #pragma unroll
        for (int ni = 0; ni < 4; ni++)
            #pragma unroll
            for (int e = 0; e < 4; e++) accO[mi][ni][e] = 0.f;

    const int ntiles = q0 / BKV + 1;   // causal: tiles fully below/at the diagonal
    for (int jt = 0; jt < ntiles; jt++) {
        __syncthreads();   // S1: K/V/P smem free, wred free, (iter0: Q/m/l visible)
        const int k0 = jt * BKV;
        for (int i = tid; i < BKV * 32; i += 256) {
            int r = i >> 5, c = (i & 31) * 4;
            float4 k4 = *(const float4*)(k + (size_t)(k0 + r) * KD + kvh * D_HEAD + c);
            float4 v4 = *(const float4*)(v + (size_t)(k0 + r) * KD + kvh * D_HEAD + c);
            pack_store4h(k4, &Khi[r * QVSTR + c]);
            pack_store4h(v4, &Vhi[r * QVSTR + c]);
        }
        __syncthreads();   // S2: tiles staged

        // ---- S = Q K^T (fp16x2), warp tile 32x32 ----
        float accS[2][4][4];
        #pragma unroll
        for (int mi = 0; mi < 2; mi++)
            #pragma unroll
            for (int ni = 0; ni < 4; ni++)
                #pragma unroll
                for (int e = 0; e < 4; e++) accS[mi][ni][e] = 0.f;

        #pragma unroll
        for (int kk = 0; kk < 8; kk++) {
            unsigned ah[2][4], al[2][4], bh[4][2];
            const int arl = wq * 32 + (lane & 15);
            const int kcl = kk * 16 + (lane >> 4) * 8;
            ldsm_x4(smem_u32(&Qhi[arl * QVSTR + kcl]), ah[0]);
            ldsm_x4(smem_u32(&Qhi[(arl + 16) * QVSTR + kcl]), ah[1]);
            ldsm_x4(smem_u32(&Qlo[arl * QVSTR + kcl]), al[0]);
            ldsm_x4(smem_u32(&Qlo[(arl + 16) * QVSTR + kcl]), al[1]);
            #pragma unroll
            for (int nb = 0; nb < 2; nb++) {
                const int brl = wn * 32 + nb * 16 + (lane & 15);
                unsigned r[4];
                ldsm_x4(smem_u32(&Khi[brl * QVSTR + kcl]), r);
                bh[2 * nb][0] = r[0]; bh[2 * nb][1] = r[2];
                bh[2 * nb + 1][0] = r[1]; bh[2 * nb + 1][1] = r[3];
            }
            #pragma unroll
            for (int mi = 0; mi < 2; mi++)
                #pragma unroll
                for (int ni = 0; ni < 4; ni++) {
                    mma_f16(accS[mi][ni], ah[mi], bh[ni]);
                    mma_f16(accS[mi][ni], al[mi], bh[ni]);
                }
        }

        // ---- mask + scale + warp-local row max (in registers) ----
        const bool diag = (jt == ntiles - 1);
        float mv[2][2];
        #pragma unroll
        for (int mi = 0; mi < 2; mi++)
            #pragma unroll
            for (int hf2 = 0; hf2 < 2; hf2++) {
                int row_g = q0 + wq * 32 + mi * 16 + (lane >> 2) + 8 * hf2;
                float mt = -1e30f;
                #pragma unroll
                for (int ni = 0; ni < 4; ni++)
                    #pragma unroll
                    for (int e = 0; e < 2; e++) {
                        int col_g = k0 + wn * 32 + ni * 8 + 2 * (lane & 3) + e;
                        float s = accS[mi][ni][2 * hf2 + e] * scale;
                        if (diag && col_g > row_g) s = -1e30f;
                        accS[mi][ni][2 * hf2 + e] = s;
                        mt = fmaxf(mt, s);
                    }
                mt = fmaxf(mt, __shfl_xor_sync(0xffffffffu, mt, 1));
                mt = fmaxf(mt, __shfl_xor_sync(0xffffffffu, mt, 2));
                mv[mi][hf2] = mt;
            }
        if ((lane & 3) == 0) {
            #pragma unroll
            for (int mi = 0; mi < 2; mi++)
                #pragma unroll
                for (int hf2 = 0; hf2 < 2; hf2++)
                    wred[wn * 64 + wq * 32 + mi * 16 + (lane >> 2) + 8 * hf2] = mv[mi][hf2];
        }
        __syncthreads();   // S3: warp maxes in wred

        if (tid < BQ) {
            float mo = mrow[tid];
            float mn = fmaxf(fmaxf(wred[tid], wred[64 + tid]),
                             fmaxf(wred[128 + tid], wred[192 + tid]));
            mn = fmaxf(mn, mo);
            mrow[tid] = mn;
            arow[tid] = __expf(mo - mn);
        }
        __syncthreads();   // S4: mrow/arow ready; wred reusable; K ldsm done -> P may overwrite

        // ---- exp, write P (fp16) in ldsm layout, warp-partial row sums ----
        {
            float mn[2][2], st[2][2];
            #pragma unroll
            for (int mi = 0; mi < 2; mi++)
                #pragma unroll
                for (int hf2 = 0; hf2 < 2; hf2++) {
                    mn[mi][hf2] = mrow[wq * 32 + mi * 16 + (lane >> 2) + 8 * hf2];
                    st[mi][hf2] = 0.f;
                }
            #pragma unroll
            for (int mi = 0; mi < 2; mi++)
                #pragma unroll
                for (int ni = 0; ni < 4; ni++)
                    #pragma unroll
                    for (int hf2 = 0; hf2 < 2; hf2++) {
                        float p0 = __expf(accS[mi][ni][2 * hf2 + 0] - mn[mi][hf2]);
                        float p1 = __expf(accS[mi][ni][2 * hf2 + 1] - mn[mi][hf2]);
                        __half h0 = __float2half_rn(p0);
                        __half h1 = __float2half_rn(p1);
                        st[mi][hf2] += __half2float(h0) + __half2float(h1);
                        int rl = wq * 32 + mi * 16 + (lane >> 2) + 8 * hf2;
                        int cl = wn * 32 + ni * 8 + 2 * (lane & 3);
                        *(__half2*)&Phi[rl * PSTR + cl] = __halves2half2(h0, h1);
                    }
            #pragma unroll
            for (int mi = 0; mi < 2; mi++)
                #pragma unroll
                for (int hf2 = 0; hf2 < 2; hf2++) {
                    float s = st[mi][hf2];
                    s += __shfl_xor_sync(0xffffffffu, s, 1);
                    s += __shfl_xor_sync(0xffffffffu, s, 2);
                    st[mi][hf2] = s;
                }
            if ((lane & 3) == 0) {
                #pragma unroll
                for (int mi = 0; mi < 2; mi++)
                    #pragma unroll
                    for (int hf2 = 0; hf2 < 2; hf2++)
                        wred[wn * 64 + wq * 32 + mi * 16 + (lane >> 2) + 8 * hf2] = st[mi][hf2];
            }
        }
        // rescale O accumulators by alpha (arow valid since S4)
        {
            #pragma unroll
            for (int mi = 0; mi < 2; mi++) {
                float a0 = arow[wq * 32 + mi * 16 + (lane >> 2)];
                float a1 = arow[wq * 32 + mi * 16 + (lane >> 2) + 8];
                #pragma unroll
                for (int ni = 0; ni < 4; ni++) {
                    accO[mi][ni][0] *= a0;
                    accO[mi][ni][1] *= a0;
                    accO[mi][ni][2] *= a1;
                    accO[mi][ni][3] *= a1;
                }
            }
        }
        __syncthreads();   // S5: P + partial sums ready

        if (tid < BQ) {
            lrow[tid] = lrow[tid] * arow[tid] +
                        (wred[tid] + wred[64 + tid]) + (wred[128 + tid] + wred[192 + tid]);
        }

        // ---- O += P V (fp16, single plane), warp tile 32x32 over d ----
        #pragma unroll
        for (int kk = 0; kk < 8; kk++) {
            unsigned ph[2][4], vh[4][2];
            const int arl = wq * 32 + (lane & 15);
            const int kcl = kk * 16 + (lane >> 4) * 8;
            ldsm_x4(smem_u32(&Phi[arl * PSTR + kcl]), ph[0]);
            ldsm_x4(smem_u32(&Phi[(arl + 16) * PSTR + kcl]), ph[1]);
            const int krw = kk * 16 + ((lane >> 3) & 1) * 8 + (lane & 7);
            #pragma unroll
            for (int nb = 0; nb < 2; nb++) {
                const int ncl = wn * 32 + nb * 16 + (lane >> 4) * 8;
                unsigned r[4];
                ldsm_x4_t(smem_u32(&Vhi[krw * QVSTR + ncl]), r);
                vh[2 * nb][0] = r[0]; vh[2 * nb][1] = r[1];
                vh[2 * nb + 1][0] = r[2]; vh[2 * nb + 1][1] = r[3];
            }
            #pragma unroll
            for (int mi = 0; mi < 2; mi++)
                #pragma unroll
                for (int ni = 0; ni < 4; ni++)
                    mma_f16(accO[mi][ni], ph[mi], vh[ni]);
        }
    }

    __syncthreads();
    #pragma unroll
    for (int mi = 0; mi < 2; mi++) {
        int r0 = wq * 32 + mi * 16 + (lane >> 2);
        float inv0 = 1.0f / lrow[r0];
        float inv1 = 1.0f / lrow[r0 + 8];
        #pragma unroll
        for (int ni = 0; ni < 4; ni++) {
            int c0 = h * D_HEAD + wn * 32 + ni * 8 + 2 * (lane & 3);
            *(float2*)(o + (size_t)(q0 + r0) * QD + c0) =
                make_float2(accO[mi][ni][0] * inv0, accO[mi][ni][1] * inv0);
            *(float2*)(o + (size_t)(q0 + r0 + 8) * QD + c0) =
                make_float2(accO[mi][ni][2] * inv1, accO[mi][ni][3] * inv1);
        }
    }
}

// ---------------------------------------------------------------------------
extern "C" void kernel_launch(void* const* d_in, const int* in_sizes, int n_in,
                              void* d_out, int out_size)
{
    const float* x  = (const float*)d_in[0];
    // d_in[1] = mask (tril) — causality hardcoded, ignored.
    const float* Wq = (const float*)d_in[2];
    const float* Wk = (const float*)d_in[3];
    const float* Wv = (const float*)d_in[4];
    const float* Wo = (const float*)d_in[5];
    float* out = (float*)d_out;

    float *q, *k, *v, *att;
    cudaGetSymbolAddress((void**)&q,   g_q);
    cudaGetSymbolAddress((void**)&k,   g_k);
    cudaGetSymbolAddress((void**)&v,   g_v);
    cudaGetSymbolAddress((void**)&att, g_att);

    cudaFuncSetAttribute(gemm_qkv_kernel,
                         cudaFuncAttributeMaxDynamicSharedMemorySize, GEMM_SMEM_BYTES);
    cudaFuncSetAttribute(gemm_fp16x2_kernel,
                         cudaFuncAttributeMaxDynamicSharedMemorySize, GEMM_SMEM_BYTES);
    cudaFuncSetAttribute(flash_mma_kernel,
                         cudaFuncAttributeMaxDynamicSharedMemorySize, FLASH_SMEM_BYTES);

    // 1. fused QKV projection + RoPE (fp16x2 tensor cores)
    gemm_qkv_kernel<<<dim3(24, 32), 256, GEMM_SMEM_BYTES>>>(x, Wq, Wk, Wv, q, k, v);

    // 2. flash attention (fp16x2, in-register softmax, BKV=128)
    flash_mma_kernel<<<dim3(T_SEQ / BQ, H_Q), 256, FLASH_SMEM_BYTES>>>(q, k, v, att);

    // 3. output projection
    gemm_fp16x2_kernel<<<dim3(C_DIM / 128, T_SEQ / 128), 256, GEMM_SMEM_BYTES>>>(
        T_SEQ, C_DIM, QD, att, Wo, out);
}

// round 13
// speedup vs baseline: 7.2401x; 1.1728x over previous
#include <cuda_runtime.h>
#include <cuda_fp16.h>
#include <stdint.h>
#include <math.h>

#define T_SEQ 4096
#define C_DIM 2048
#define H_Q   16
#define KVH_  4
#define D_HEAD 128
#define QD (H_Q * D_HEAD)    // 2048
#define KD (KVH_ * D_HEAD)   // 512

// Scratch (allocation-free rule: device globals)
__device__ float g_q[T_SEQ * QD];
__device__ float g_k[T_SEQ * KD];
__device__ float g_v[T_SEQ * KD];
__device__ float g_att[T_SEQ * QD];

__device__ __forceinline__ unsigned smem_u32(const void* p) {
    return (unsigned)__cvta_generic_to_shared(p);
}
__device__ __forceinline__ void ldsm_x4(unsigned addr, unsigned* r) {
    asm volatile("ldmatrix.sync.aligned.m8n8.x4.shared.b16 {%0,%1,%2,%3}, [%4];\n"
                 : "=r"(r[0]), "=r"(r[1]), "=r"(r[2]), "=r"(r[3]) : "r"(addr));
}
__device__ __forceinline__ void ldsm_x4_t(unsigned addr, unsigned* r) {
    asm volatile("ldmatrix.sync.aligned.m8n8.x4.trans.shared.b16 {%0,%1,%2,%3}, [%4];\n"
                 : "=r"(r[0]), "=r"(r[1]), "=r"(r[2]), "=r"(r[3]) : "r"(addr));
}
__device__ __forceinline__ void mma_f16(float* d, const unsigned* a, const unsigned* b) {
    asm volatile("mma.sync.aligned.m16n8k16.row.col.f32.f16.f16.f32 "
                 "{%0,%1,%2,%3}, {%4,%5,%6,%7}, {%8,%9}, {%0,%1,%2,%3};\n"
                 : "+f"(d[0]), "+f"(d[1]), "+f"(d[2]), "+f"(d[3])
                 : "r"(a[0]), "r"(a[1]), "r"(a[2]), "r"(a[3]),
                   "r"(b[0]), "r"(b[1]));
}
// split 4 fp32 into fp16 hi/lo planes (used by flash Q)
__device__ __forceinline__ void split_store4h(float4 v, __half* hi, __half* lo) {
    __half h0 = __float2half_rn(v.x);
    __half h1 = __float2half_rn(v.y);
    __half h2 = __float2half_rn(v.z);
    __half h3 = __float2half_rn(v.w);
    __half l0 = __float2half_rn(v.x - __half2float(h0));
    __half l1 = __float2half_rn(v.y - __half2float(h1));
    __half l2 = __float2half_rn(v.z - __half2float(h2));
    __half l3 = __float2half_rn(v.w - __half2float(h3));
    *(__half2*)(hi)     = __halves2half2(h0, h1);
    *(__half2*)(hi + 2) = __halves2half2(h2, h3);
    *(__half2*)(lo)     = __halves2half2(l0, l1);
    *(__half2*)(lo + 2) = __halves2half2(l2, l3);
}
// pack 4 fp32 into single fp16 plane
__device__ __forceinline__ void pack_store4h(float4 v, __half* dst) {
    *(__half2*)(dst)     = __halves2half2(__float2half_rn(v.x), __float2half_rn(v.y));
    *(__half2*)(dst + 2) = __halves2half2(__float2half_rn(v.z), __float2half_rn(v.w));
}

// ===========================================================================
// Pure-fp16 tensor-core GEMM: C = A @ B, both operands single fp16 plane.
// 128x128x32 block tile, 256 threads (2x4 warps, 64x32 per warp),
// double-buffered smem, optional fused RoPE epilogue.
// ===========================================================================
#define AS_STRIDE 40
#define BS_STRIDE 136
#define APL (128 * AS_STRIDE)            // 5120 halfs
#define BPL (32 * BS_STRIDE)             // 4352 halfs
#define BUF_ELEMS (APL + BPL)            // 9472 halfs
#define GEMM_SMEM_BYTES (2 * BUF_ELEMS * 2)   // 37888 B

__device__ __forceinline__ void gemm_core(
    int N, int K, int rope,
    const float* __restrict__ A, const float* __restrict__ B,
    float* __restrict__ C, int bm0, int bn0, char* smraw)
{
    __half* bufs = (__half*)smraw;

    const int tid  = threadIdx.x;
    const int lane = tid & 31;
    const int wid  = tid >> 5;
    const int wm   = wid >> 2;
    const int wn   = wid & 3;

    const int ar = tid >> 3;
    const int ac = (tid & 7) * 4;
    const int br = tid >> 5;
    const int bc = (tid & 31) * 4;

    float acc[4][4][4];
    #pragma unroll
    for (int mi = 0; mi < 4; mi++)
        #pragma unroll
        for (int ni = 0; ni < 4; ni++)
            #pragma unroll
            for (int e = 0; e < 4; e++) acc[mi][ni][e] = 0.f;

    const int ktiles = K >> 5;

    float4 ra[4], rb[4];
    #pragma unroll
    for (int i = 0; i < 4; i++) {
        ra[i] = *(const float4*)(A + (size_t)(bm0 + ar + i * 32) * K + ac);
        rb[i] = *(const float4*)(B + (size_t)(br + i * 8) * N + bn0 + bc);
    }
    {
        __half* As = bufs;
        __half* Bs = As + APL;
        #pragma unroll
        for (int i = 0; i < 4; i++) {
            pack_store4h(ra[i], &As[(ar + i * 32) * AS_STRIDE + ac]);
            pack_store4h(rb[i], &Bs[(br + i * 8) * BS_STRIDE + bc]);
        }
    }
    __syncthreads();

    for (int kt = 0; kt < ktiles; kt++) {
        const bool has_next = (kt + 1 < ktiles);
        if (has_next) {
            int k0 = (kt + 1) << 5;
            #pragma unroll
            for (int i = 0; i < 4; i++) {
                ra[i] = *(const float4*)(A + (size_t)(bm0 + ar + i * 32) * K + k0 + ac);
                rb[i] = *(const float4*)(B + (size_t)(k0 + br + i * 8) * N + bn0 + bc);
            }
        }

        __half* As = bufs + (kt & 1) * BUF_ELEMS;
        __half* Bs = As + APL;

        #pragma unroll
        for (int ks = 0; ks < 2; ks++) {
            const int k = ks * 16;
            unsigned ah[4][4], bh[4][2];

            const int arl = wm * 64 + (lane & 15);
            const int kcl = k + (lane >> 4) * 8;
            #pragma unroll
            for (int mi = 0; mi < 4; mi++)
                ldsm_x4(smem_u32(&As[(arl + mi * 16) * AS_STRIDE + kcl]), ah[mi]);
            const int krw = k + ((lane >> 3) & 1) * 8 + (lane & 7);
            #pragma unroll
            for (int nb = 0; nb < 2; nb++) {
                const int ncl = wn * 32 + nb * 16 + (lane >> 4) * 8;
                unsigned r[4];
                ldsm_x4_t(smem_u32(&Bs[krw * BS_STRIDE + ncl]), r);
                bh[2 * nb][0] = r[0]; bh[2 * nb][1] = r[1];
                bh[2 * nb + 1][0] = r[2]; bh[2 * nb + 1][1] = r[3];
            }

            #pragma unroll
            for (int mi = 0; mi < 4; mi++)
                #pragma unroll
                for (int ni = 0; ni < 4; ni++)
                    mma_f16(acc[mi][ni], ah[mi], bh[ni]);
        }

        if (has_next) {
            __half* nAs = bufs + ((kt + 1) & 1) * BUF_ELEMS;
            __half* nBs = nAs + APL;
            #pragma unroll
            for (int i = 0; i < 4; i++) {
                pack_store4h(ra[i], &nAs[(ar + i * 32) * AS_STRIDE + ac]);
                pack_store4h(rb[i], &nBs[(br + i * 8) * BS_STRIDE + bc]);
            }
        }
        __syncthreads();
    }

    const int gid = lane >> 2, tig = lane & 3;

    // fused RoPE: acc[mi][ni] holds cols (c0, c0+1) at rows r0 and r0+8 —
    // exactly the interleaved (even,odd) pairs the rotation needs.
    if (rope) {
        #pragma unroll
        for (int ni = 0; ni < 4; ni++) {
            int c0 = bn0 + wn * 32 + ni * 8 + tig * 2;
            int d2 = (c0 & 127) >> 1;
            float inv = (float)exp(-(double)d2 * 0.14391156831212787); // ln(1e4)/64
            #pragma unroll
            for (int mi = 0; mi < 4; mi++) {
                int t0 = bm0 + wm * 64 + mi * 16 + gid;
                float a0 = (float)t0 * inv;
                float a1 = (float)(t0 + 8) * inv;
                float c0f = cosf(a0), s0f = sinf(a0);
                float c1f = cosf(a1), s1f = sinf(a1);
                float x0 = acc[mi][ni][0], x1 = acc[mi][ni][1];
                acc[mi][ni][0] = x0 * c0f - x1 * s0f;
                acc[mi][ni][1] = x0 * s0f + x1 * c0f;
                x0 = acc[mi][ni][2]; x1 = acc[mi][ni][3];
                acc[mi][ni][2] = x0 * c1f - x1 * s1f;
                acc[mi][ni][3] = x0 * s1f + x1 * c1f;
            }
        }
    }

    #pragma unroll
    for (int mi = 0; mi < 4; mi++)
        #pragma unroll
        for (int ni = 0; ni < 4; ni++) {
            int r0 = bm0 + wm * 64 + mi * 16 + gid;
            int c0 = bn0 + wn * 32 + ni * 8 + tig * 2;
            *(float2*)(C + (size_t)r0 * N + c0) =
                make_float2(acc[mi][ni][0], acc[mi][ni][1]);
            *(float2*)(C + (size_t)(r0 + 8) * N + c0) =
                make_float2(acc[mi][ni][2], acc[mi][ni][3]);
        }
}

__global__ __launch_bounds__(256) void gemm_qkv_kernel(
    const float* __restrict__ x,
    const float* __restrict__ Wq, const float* __restrict__ Wk,
    const float* __restrict__ Wv,
    float* __restrict__ q, float* __restrict__ k, float* __restrict__ v)
{
    extern __shared__ char smraw[];
    const int bx = blockIdx.x;
    const int bm0 = blockIdx.y * 128;
    if (bx < 16) {
        gemm_core(QD, C_DIM, 1, x, Wq, q, bm0, bx * 128, smraw);
    } else if (bx < 20) {
        gemm_core(KD, C_DIM, 1, x, Wk, k, bm0, (bx - 16) * 128, smraw);
    } else {
        gemm_core(KD, C_DIM, 0, x, Wv, v, bm0, (bx - 20) * 128, smraw);
    }
}

__global__ __launch_bounds__(256) void gemm_fp16_kernel(
    int M, int N, int K,
    const float* __restrict__ A, const float* __restrict__ B,
    float* __restrict__ C)
{
    extern __shared__ char smraw[];
    gemm_core(N, K, 0, A, B, C, blockIdx.y * 128, blockIdx.x * 128, smraw);
}

// ===========================================================================
// Flash attention (unchanged from R12): fp16x2 MMA, in-register softmax,
// BKV=128, Q split hi/lo, K/V/P single plane, P aliases K smem.
// ===========================================================================
#define BQ 64
#define BKV 128
#define QVSTR 136
#define PSTR  136

#define SM_QHI 0
#define SM_QLO 8704
#define SM_KHI 17408
#define SM_PHI 17408
#define SM_VHI (17408 + 128 * QVSTR)
#define SM_HF_END (SM_VHI + 128 * QVSTR)
#define SMF_WRED 0
#define SMF_M    256
#define SMF_L    320
#define SMF_A    384
#define SMF_END  448
#define FLASH_SMEM_BYTES (SM_HF_END * 2 + SMF_END * 4)

__global__ __launch_bounds__(256, 2) void flash_mma_kernel(
    const float* __restrict__ q, const float* __restrict__ k,
    const float* __restrict__ v, float* __restrict__ o)
{
    extern __shared__ char smraw[];
    __half* hf = (__half*)smraw;
    float*  fp = (float*)(smraw + SM_HF_END * 2);

    __half* Qhi = hf + SM_QHI;
    __half* Qlo = hf + SM_QLO;
    __half* Khi = hf + SM_KHI;
    __half* Phi = hf + SM_PHI;
    __half* Vhi = hf + SM_VHI;
    float* wred = fp + SMF_WRED;
    float* mrow = fp + SMF_M;
    float* lrow = fp + SMF_L;
    float* arow = fp + SMF_A;

    const int tid  = threadIdx.x;
    const int lane = tid & 31;
    const int wid  = tid >> 5;
    const int wq   = wid >> 2;
    const int wn   = wid & 3;
    const int qb   = gridDim.x - 1 - blockIdx.x;
    const int h    = blockIdx.y;
    const int kvh  = h / (H_Q / KVH_);
    const int q0   = qb * BQ;
    const float scale = 0.08838834764831845f;

    for (int i = tid; i < BQ * 32; i += 256) {
        int r = i >> 5, c = (i & 31) * 4;
        float4 a4 = *(const float4*)(q + (size_t)(q0 + r) * QD + h * D_HEAD + c);
        split_store4h(a4, &Qhi[r * QVSTR + c], &Qlo[r * QVSTR + c]);
    }
    if (tid < BQ) { mrow[tid] = -1e30f; lrow[tid] = 0.f; }

    float accO[2][4][4];
    #pragma unroll
    for (int mi = 0; mi < 2; mi++)
        #pragma unroll
        for (int ni = 0; ni < 4; ni++)
            #pragma unroll
            for (int e = 0; e < 4; e++) accO[mi][ni][e] = 0.f;

    const int ntiles = q0 / BKV + 1;
    for (int jt = 0; jt < ntiles; jt++) {
        __syncthreads();
        const int k0 = jt * BKV;
        for (int i = tid; i < BKV * 32; i += 256) {
            int r = i >> 5, c = (i & 31) * 4;
            float4 k4 = *(const float4*)(k + (size_t)(k0 + r) * KD + kvh * D_HEAD + c);
            float4 v4 = *(const float4*)(v + (size_t)(k0 + r) * KD + kvh * D_HEAD + c);
            pack_store4h(k4, &Khi[r * QVSTR + c]);
            pack_store4h(v4, &Vhi[r * QVSTR + c]);
        }
        __syncthreads();

        float accS[2][4][4];
        #pragma unroll
        for (int mi = 0; mi < 2; mi++)
            #pragma unroll
            for (int ni = 0; ni < 4; ni++)
                #pragma unroll
                for (int e = 0; e < 4; e++) accS[mi][ni][e] = 0.f;

        #pragma unroll
        for (int kk = 0; kk < 8; kk++) {
            unsigned ah[2][4], al[2][4], bh[4][2];
            const int arl = wq * 32 + (lane & 15);
            const int kcl = kk * 16 + (lane >> 4) * 8;
            ldsm_x4(smem_u32(&Qhi[arl * QVSTR + kcl]), ah[0]);
            ldsm_x4(smem_u32(&Qhi[(arl + 16) * QVSTR + kcl]), ah[1]);
            ldsm_x4(smem_u32(&Qlo[arl * QVSTR + kcl]), al[0]);
            ldsm_x4(smem_u32(&Qlo[(arl + 16) * QVSTR + kcl]), al[1]);
            #pragma unroll
            for (int nb = 0; nb < 2; nb++) {
                const int brl = wn * 32 + nb * 16 + (lane & 15);
                unsigned r[4];
                ldsm_x4(smem_u32(&Khi[brl * QVSTR + kcl]), r);
                bh[2 * nb][0] = r[0]; bh[2 * nb][1] = r[2];
                bh[2 * nb + 1][0] = r[1]; bh[2 * nb + 1][1] = r[3];
            }
            #pragma unroll
            for (int mi = 0; mi < 2; mi++)
                #pragma unroll
                for (int ni = 0; ni < 4; ni++) {
                    mma_f16(accS[mi][ni], ah[mi], bh[ni]);
                    mma_f16(accS[mi][ni], al[mi], bh[ni]);
                }
        }

        const bool diag = (jt == ntiles - 1);
        float mv[2][2];
        #pragma unroll
        for (int mi = 0; mi < 2; mi++)
            #pragma unroll
            for (int hf2 = 0; hf2 < 2; hf2++) {
                int row_g = q0 + wq * 32 + mi * 16 + (lane >> 2) + 8 * hf2;
                float mt = -1e30f;
                #pragma unroll
                for (int ni = 0; ni < 4; ni++)
                    #pragma unroll
                    for (int e = 0; e < 2; e++) {
                        int col_g = k0 + wn * 32 + ni * 8 + 2 * (lane & 3) + e;
                        float s = accS[mi][ni][2 * hf2 + e] * scale;
                        if (diag && col_g > row_g) s = -1e30f;
                        accS[mi][ni][2 * hf2 + e] = s;
                        mt = fmaxf(mt, s);
                    }
                mt = fmaxf(mt, __shfl_xor_sync(0xffffffffu, mt, 1));
                mt = fmaxf(mt, __shfl_xor_sync(0xffffffffu, mt, 2));
                mv[mi][hf2] = mt;
            }
        if ((lane & 3) == 0) {
            #pragma unroll
            for (int mi = 0; mi < 2; mi++)
                #pragma unroll
                for (int hf2 = 0; hf2 < 2; hf2++)
                    wred[wn * 64 + wq * 32 + mi * 16 + (lane >> 2) + 8 * hf2] = mv[mi][hf2];
        }
        __syncthreads();

        if (tid < BQ) {
            float mo = mrow[tid];
            float mn = fmaxf(fmaxf(wred[tid], wred[64 + tid]),
                             fmaxf(wred[128 + tid], wred[192 + tid]));
            mn = fmaxf(mn, mo);
            mrow[tid] = mn;
            arow[tid] = __expf(mo - mn);
        }
        __syncthreads();

        {
            float mn[2][2], st[2][2];
            #pragma unroll
            for (int mi = 0; mi < 2; mi++)
                #pragma unroll
                for (int hf2 = 0; hf2 < 2; hf2++) {
                    mn[mi][hf2] = mrow[wq * 32 + mi * 16 + (lane >> 2) + 8 * hf2];
                    st[mi][hf2] = 0.f;
                }
            #pragma unroll
            for (int mi = 0; mi < 2; mi++)
                #pragma unroll
                for (int ni = 0; ni < 4; ni++)
                    #pragma unroll
                    for (int hf2 = 0; hf2 < 2; hf2++) {
                        float p0 = __expf(accS[mi][ni][2 * hf2 + 0] - mn[mi][hf2]);
                        float p1 = __expf(accS[mi][ni][2 * hf2 + 1] - mn[mi][hf2]);
                        __half h0 = __float2half_rn(p0);
                        __half h1 = __float2half_rn(p1);
                        st[mi][hf2] += __half2float(h0) + __half2float(h1);
                        int rl = wq * 32 + mi * 16 + (lane >> 2) + 8 * hf2;
                        int cl = wn * 32 + ni * 8 + 2 * (lane & 3);
                        *(__half2*)&Phi[rl * PSTR + cl] = __halves2half2(h0, h1);
                    }
            #pragma unroll
            for (int mi = 0; mi < 2; mi++)
                #pragma unroll
                for (int hf2 = 0; hf2 < 2; hf2++) {
                    float s = st[mi][hf2];
                    s += __shfl_xor_sync(0xffffffffu, s, 1);
                    s += __shfl_xor_sync(0xffffffffu, s, 2);
                    st[mi][hf2] = s;
                }
            if ((lane & 3) == 0) {
                #pragma unroll
                for (int mi = 0; mi < 2; mi++)
                    #pragma unroll
                    for (int hf2 = 0; hf2 < 2; hf2++)
                        wred[wn * 64 + wq * 32 + mi * 16 + (lane >> 2) + 8 * hf2] = st[mi][hf2];
            }
        }
        {
            #pragma unroll
            for (int mi = 0; mi < 2; mi++) {
                float a0 = arow[wq * 32 + mi * 16 + (lane >> 2)];
                float a1 = arow[wq * 32 + mi * 16 + (lane >> 2) + 8];
                #pragma unroll
                for (int ni = 0; ni < 4; ni++) {
                    accO[mi][ni][0] *= a0;
                    accO[mi][ni][1] *= a0;
                    accO[mi][ni][2] *= a1;
                    accO[mi][ni][3] *= a1;
                }
            }
        }
        __syncthreads();

        if (tid < BQ) {
            lrow[tid] = lrow[tid] * arow[tid] +
                        (wred[tid] + wred[64 + tid]) + (wred[128 + tid] + wred[192 + tid]);
        }

        #pragma unroll
        for (int kk = 0; kk < 8; kk++) {
            unsigned ph[2][4], vh[4][2];
            const int arl = wq * 32 + (lane & 15);
            const int kcl = kk * 16 + (lane >> 4) * 8;
            ldsm_x4(smem_u32(&Phi[arl * PSTR + kcl]), ph[0]);
            ldsm_x4(smem_u32(&Phi[(arl + 16) * PSTR + kcl]), ph[1]);
            const int krw = kk * 16 + ((lane >> 3) & 1) * 8 + (lane & 7);
            #pragma unroll
            for (int nb = 0; nb < 2; nb++) {
                const int ncl = wn * 32 + nb * 16 + (lane >> 4) * 8;
                unsigned r[4];
                ldsm_x4_t(smem_u32(&Vhi[krw * QVSTR + ncl]), r);
                vh[2 * nb][0] = r[0]; vh[2 * nb][1] = r[1];
                vh[2 * nb + 1][0] = r[2]; vh[2 * nb + 1][1] = r[3];
            }
            #pragma unroll
            for (int mi = 0; mi < 2; mi++)
                #pragma unroll
                for (int ni = 0; ni < 4; ni++)
                    mma_f16(accO[mi][ni], ph[mi], vh[ni]);
        }
    }

    __syncthreads();
    #pragma unroll
    for (int mi = 0; mi < 2; mi++) {
        int r0 = wq * 32 + mi * 16 + (lane >> 2);
        float inv0 = 1.0f / lrow[r0];
        float inv1 = 1.0f / lrow[r0 + 8];
        #pragma unroll
        for (int ni = 0; ni < 4; ni++) {
            int c0 = h * D_HEAD + wn * 32 + ni * 8 + 2 * (lane & 3);
            *(float2*)(o + (size_t)(q0 + r0) * QD + c0) =
                make_float2(accO[mi][ni][0] * inv0, accO[mi][ni][1] * inv0);
            *(float2*)(o + (size_t)(q0 + r0 + 8) * QD + c0) =
                make_float2(accO[mi][ni][2] * inv1, accO[mi][ni][3] * inv1);
        }
    }
}

// ---------------------------------------------------------------------------
extern "C" void kernel_launch(void* const* d_in, const int* in_sizes, int n_in,
                              void* d_out, int out_size)
{
    const float* x  = (const float*)d_in[0];
    // d_in[1] = mask (tril) — causality hardcoded, ignored.
    const float* Wq = (const float*)d_in[2];
    const float* Wk = (const float*)d_in[3];
    const float* Wv = (const float*)d_in[4];
    const float* Wo = (const float*)d_in[5];
    float* out = (float*)d_out;

    float *q, *k, *v, *att;
    cudaGetSymbolAddress((void**)&q,   g_q);
    cudaGetSymbolAddress((void**)&k,   g_k);
    cudaGetSymbolAddress((void**)&v,   g_v);
    cudaGetSymbolAddress((void**)&att, g_att);

    cudaFuncSetAttribute(gemm_qkv_kernel,
                         cudaFuncAttributeMaxDynamicSharedMemorySize, GEMM_SMEM_BYTES);
    cudaFuncSetAttribute(gemm_fp16_kernel,
                         cudaFuncAttributeMaxDynamicSharedMemorySize, GEMM_SMEM_BYTES);
    cudaFuncSetAttribute(flash_mma_kernel,
                         cudaFuncAttributeMaxDynamicSharedMemorySize, FLASH_SMEM_BYTES);

    // 1. fused QKV projection + RoPE (pure fp16 tensor cores)
    gemm_qkv_kernel<<<dim3(24, 32), 256, GEMM_SMEM_BYTES>>>(x, Wq, Wk, Wv, q, k, v);

    // 2. flash attention (fp16x2 Q-split, in-register softmax, BKV=128)
    flash_mma_kernel<<<dim3(T_SEQ / BQ, H_Q), 256, FLASH_SMEM_BYTES>>>(q, k, v, att);

    // 3. output projection (pure fp16)
    gemm_fp16_kernel<<<dim3(C_DIM / 128, T_SEQ / 128), 256, GEMM_SMEM_BYTES>>>(
        T_SEQ, C_DIM, QD, att, Wo, out);
}

// round 14
// speedup vs baseline: 8.4806x; 1.1713x over previous
#include <cuda_runtime.h>
#include <cuda_fp16.h>
#include <stdint.h>
#include <math.h>

#define T_SEQ 4096
#define C_DIM 2048
#define H_Q   16
#define KVH_  4
#define D_HEAD 128
#define QD (H_Q * D_HEAD)    // 2048
#define KD (KVH_ * D_HEAD)   // 512

// fp16 intermediates (allocation-free rule: device globals)
__device__ __half g_x16[T_SEQ * C_DIM];
__device__ __half g_wq16[C_DIM * QD];
__device__ __half g_wk16[C_DIM * KD];
__device__ __half g_wv16[C_DIM * KD];
__device__ __half g_wo16[QD * C_DIM];
__device__ __half g_qhi[T_SEQ * QD];
__device__ __half g_qlo[T_SEQ * QD];
__device__ __half g_k16[T_SEQ * KD];
__device__ __half g_v16[T_SEQ * KD];
__device__ __half g_att16[T_SEQ * QD];

__device__ __forceinline__ unsigned smem_u32(const void* p) {
    return (unsigned)__cvta_generic_to_shared(p);
}
__device__ __forceinline__ void ldsm_x4(unsigned addr, unsigned* r) {
    asm volatile("ldmatrix.sync.aligned.m8n8.x4.shared.b16 {%0,%1,%2,%3}, [%4];\n"
                 : "=r"(r[0]), "=r"(r[1]), "=r"(r[2]), "=r"(r[3]) : "r"(addr));
}
__device__ __forceinline__ void ldsm_x4_t(unsigned addr, unsigned* r) {
    asm volatile("ldmatrix.sync.aligned.m8n8.x4.trans.shared.b16 {%0,%1,%2,%3}, [%4];\n"
                 : "=r"(r[0]), "=r"(r[1]), "=r"(r[2]), "=r"(r[3]) : "r"(addr));
}
__device__ __forceinline__ void mma_f16(float* d, const unsigned* a, const unsigned* b) {
    asm volatile("mma.sync.aligned.m16n8k16.row.col.f32.f16.f16.f32 "
                 "{%0,%1,%2,%3}, {%4,%5,%6,%7}, {%8,%9}, {%0,%1,%2,%3};\n"
                 : "+f"(d[0]), "+f"(d[1]), "+f"(d[2]), "+f"(d[3])
                 : "r"(a[0]), "r"(a[1]), "r"(a[2]), "r"(a[3]),
                   "r"(b[0]), "r"(b[1]));
}
#define CP_ASYNC16(dst, src) \
    asm volatile("cp.async.ca.shared.global [%0], [%1], 16;\n" :: "r"(dst), "l"(src))
#define CP_ASYNC8(dst, src) \
    asm volatile("cp.async.ca.shared.global [%0], [%1], 8;\n" :: "r"(dst), "l"(src))
#define CP_COMMIT() asm volatile("cp.async.commit_group;\n" ::: "memory")
#define CP_WAIT0()  asm volatile("cp.async.wait_group 0;\n" ::: "memory")

__device__ __forceinline__ void pack_store4h(float4 v, __half* dst) {
    *(__half2*)(dst)     = __halves2half2(__float2half_rn(v.x), __float2half_rn(v.y));
    *(__half2*)(dst + 2) = __halves2half2(__float2half_rn(v.z), __float2half_rn(v.w));
}

// ---------------------------------------------------------------------------
// fp32 -> fp16 convert (one-time, per tensor)
// ---------------------------------------------------------------------------
__global__ void f2h_kernel(const float* __restrict__ in, __half* __restrict__ out, int n)
{
    int i = (blockIdx.x * blockDim.x + threadIdx.x) * 4;
    if (i < n) pack_store4h(*(const float4*)(in + i), out + i);
}

// ===========================================================================
// fp16 tensor-core GEMM, cp.async staging: C = A16 @ B16.
// 128x128x32 tile, 256 threads (2x4 warps), double-buffered.
// Epilogue: optional fused RoPE; store mode 0 = fp32 C, 1 = fp16 C1,
// 2 = fp16 hi/lo split (C1 = hi, C2 = lo).
// ===========================================================================
#define AS_STRIDE 40
#define BS_STRIDE 136
#define APL (128 * AS_STRIDE)            // 5120 halfs
#define BPL (32 * BS_STRIDE)             // 4352 halfs
#define BUF_ELEMS (APL + BPL)            // 9472 halfs
#define GEMM_SMEM_BYTES (2 * BUF_ELEMS * 2)   // 37888 B

__device__ __forceinline__ void gemm_issue_tile(
    const __half* __restrict__ A, const __half* __restrict__ B,
    int N, int K, int bm0, int bn0, int k0, __half* Asm, int tid)
{
    __half* Bsm = Asm + APL;
    // A: 128 rows x 32 halfs, 8B chunks (4 halfs), 1024 chunks
    #pragma unroll
    for (int it = 0; it < 4; it++) {
        int f = it * 256 + tid;
        int row = f >> 3, c = (f & 7) * 4;
        CP_ASYNC8(smem_u32(&Asm[row * AS_STRIDE + c]),
                  A + (size_t)(bm0 + row) * K + k0 + c);
    }
    // B: 32 rows x 128 halfs, 16B chunks (8 halfs), 512 chunks
    #pragma unroll
    for (int it = 0; it < 2; it++) {
        int f = it * 256 + tid;
        int row = f >> 4, c = (f & 15) * 8;
        CP_ASYNC16(smem_u32(&Bsm[row * BS_STRIDE + c]),
                   B + (size_t)(k0 + row) * N + bn0 + c);
    }
}

__device__ __forceinline__ void gemm_core_h(
    int N, int K, int rope, int mode,
    const __half* __restrict__ A, const __half* __restrict__ B,
    float* __restrict__ Cf, __half* __restrict__ C1, __half* __restrict__ C2,
    int bm0, int bn0, char* smraw)
{
    __half* bufs = (__half*)smraw;

    const int tid  = threadIdx.x;
    const int lane = tid & 31;
    const int wid  = tid >> 5;
    const int wm   = wid >> 2;
    const int wn   = wid & 3;

    float acc[4][4][4];
    #pragma unroll
    for (int mi = 0; mi < 4; mi++)
        #pragma unroll
        for (int ni = 0; ni < 4; ni++)
            #pragma unroll
            for (int e = 0; e < 4; e++) acc[mi][ni][e] = 0.f;

    const int ktiles = K >> 5;

    gemm_issue_tile(A, B, N, K, bm0, bn0, 0, bufs, tid);
    CP_COMMIT();

    for (int kt = 0; kt < ktiles; kt++) {
        CP_WAIT0();
        __syncthreads();   // tile kt visible; prior-iter reads of other buf done
        if (kt + 1 < ktiles) {
            gemm_issue_tile(A, B, N, K, bm0, bn0, (kt + 1) << 5,
                            bufs + ((kt + 1) & 1) * BUF_ELEMS, tid);
            CP_COMMIT();
        }

        __half* As = bufs + (kt & 1) * BUF_ELEMS;
        __half* Bs = As + APL;

        #pragma unroll
        for (int ks = 0; ks < 2; ks++) {
            const int k = ks * 16;
            unsigned ah[4][4], bh[4][2];

            const int arl = wm * 64 + (lane & 15);
            const int kcl = k + (lane >> 4) * 8;
            #pragma unroll
            for (int mi = 0; mi < 4; mi++)
                ldsm_x4(smem_u32(&As[(arl + mi * 16) * AS_STRIDE + kcl]), ah[mi]);
            const int krw = k + ((lane >> 3) & 1) * 8 + (lane & 7);
            #pragma unroll
            for (int nb = 0; nb < 2; nb++) {
                const int ncl = wn * 32 + nb * 16 + (lane >> 4) * 8;
                unsigned r[4];
                ldsm_x4_t(smem_u32(&Bs[krw * BS_STRIDE + ncl]), r);
                bh[2 * nb][0] = r[0]; bh[2 * nb][1] = r[1];
                bh[2 * nb + 1][0] = r[2]; bh[2 * nb + 1][1] = r[3];
            }

            #pragma unroll
            for (int mi = 0; mi < 4; mi++)
                #pragma unroll
                for (int ni = 0; ni < 4; ni++)
                    mma_f16(acc[mi][ni], ah[mi], bh[ni]);
        }
    }

    const int gid = lane >> 2, tig = lane & 3;

    if (rope) {
        #pragma unroll
        for (int ni = 0; ni < 4; ni++) {
            int c0 = bn0 + wn * 32 + ni * 8 + tig * 2;
            int d2 = (c0 & 127) >> 1;
            float inv = (float)exp(-(double)d2 * 0.14391156831212787); // ln(1e4)/64
            #pragma unroll
            for (int mi = 0; mi < 4; mi++) {
                int t0 = bm0 + wm * 64 + mi * 16 + gid;
                float a0 = (float)t0 * inv;
                float a1 = (float)(t0 + 8) * inv;
                float c0f = cosf(a0), s0f = sinf(a0);
                float c1f = cosf(a1), s1f = sinf(a1);
                float x0 = acc[mi][ni][0], x1 = acc[mi][ni][1];
                acc[mi][ni][0] = x0 * c0f - x1 * s0f;
                acc[mi][ni][1] = x0 * s0f + x1 * c0f;
                x0 = acc[mi][ni][2]; x1 = acc[mi][ni][3];
                acc[mi][ni][2] = x0 * c1f - x1 * s1f;
                acc[mi][ni][3] = x0 * s1f + x1 * c1f;
            }
        }
    }

    #pragma unroll
    for (int mi = 0; mi < 4; mi++)
        #pragma unroll
        for (int ni = 0; ni < 4; ni++) {
            int r0 = bm0 + wm * 64 + mi * 16 + gid;
            int c0 = bn0 + wn * 32 + ni * 8 + tig * 2;
            if (mode == 0) {
                *(float2*)(Cf + (size_t)r0 * N + c0) =
                    make_float2(acc[mi][ni][0], acc[mi][ni][1]);
                *(float2*)(Cf + (size_t)(r0 + 8) * N + c0) =
                    make_float2(acc[mi][ni][2], acc[mi][ni][3]);
            } else if (mode == 1) {
                *(__half2*)(C1 + (size_t)r0 * N + c0) = __halves2half2(
                    __float2half_rn(acc[mi][ni][0]), __float2half_rn(acc[mi][ni][1]));
                *(__half2*)(C1 + (size_t)(r0 + 8) * N + c0) = __halves2half2(
                    __float2half_rn(acc[mi][ni][2]), __float2half_rn(acc[mi][ni][3]));
            } else {
                __half h0 = __float2half_rn(acc[mi][ni][0]);
                __half h1 = __float2half_rn(acc[mi][ni][1]);
                __half h2 = __float2half_rn(acc[mi][ni][2]);
                __half h3 = __float2half_rn(acc[mi][ni][3]);
                *(__half2*)(C1 + (size_t)r0 * N + c0) = __halves2half2(h0, h1);
                *(__half2*)(C1 + (size_t)(r0 + 8) * N + c0) = __halves2half2(h2, h3);
                __half l0 = __float2half_rn(acc[mi][ni][0] - __half2float(h0));
                __half l1 = __float2half_rn(acc[mi][ni][1] - __half2float(h1));
                __half l2 = __float2half_rn(acc[mi][ni][2] - __half2float(h2));
                __half l3 = __float2half_rn(acc[mi][ni][3] - __half2float(h3));
                *(__half2*)(C2 + (size_t)r0 * N + c0) = __halves2half2(l0, l1);
                *(__half2*)(C2 + (size_t)(r0 + 8) * N + c0) = __halves2half2(l2, l3);
            }
        }
}

// Fused QKV + RoPE: grid (24, 32). bx<16 -> Q (hi/lo), <20 -> K, else V.
__global__ __launch_bounds__(256) void gemm_qkv_kernel(
    const __half* __restrict__ x16,
    const __half* __restrict__ wq16, const __half* __restrict__ wk16,
    const __half* __restrict__ wv16,
    __half* __restrict__ qhi, __half* __restrict__ qlo,
    __half* __restrict__ k16, __half* __restrict__ v16)
{
    extern __shared__ char smraw[];
    const int bx = blockIdx.x;
    const int bm0 = blockIdx.y * 128;
    if (bx < 16) {
        gemm_core_h(QD, C_DIM, 1, 2, x16, wq16, 0, qhi, qlo, bm0, bx * 128, smraw);
    } else if (bx < 20) {
        gemm_core_h(KD, C_DIM, 1, 1, x16, wk16, 0, k16, 0, bm0, (bx - 16) * 128, smraw);
    } else {
        gemm_core_h(KD, C_DIM, 0, 1, x16, wv16, 0, v16, 0, bm0, (bx - 20) * 128, smraw);
    }
}

// Output projection: fp16 in, fp32 out
__global__ __launch_bounds__(256) void gemm_out_kernel(
    const __half* __restrict__ att16, const __half* __restrict__ wo16,
    float* __restrict__ out)
{
    extern __shared__ char smraw[];
    gemm_core_h(C_DIM, QD, 0, 0, att16, wo16, out, 0, 0,
                blockIdx.y * 128, blockIdx.x * 128, smraw);
}

// ===========================================================================
// Flash attention: fp16 MMA, in-register softmax, BKV=128, cp.async staging.
// Q hi/lo planes, K/V/P single plane, P aliases K smem, writes fp16 att.
// ===========================================================================
#define BQ 64
#define BKV 128
#define QVSTR 136
#define PSTR  136

#define SM_QHI 0
#define SM_QLO 8704
#define SM_KHI 17408
#define SM_PHI 17408
#define SM_VHI (17408 + 128 * QVSTR)
#define SM_HF_END (SM_VHI + 128 * QVSTR)
#define SMF_WRED 0
#define SMF_M    256
#define SMF_L    320
#define SMF_A    384
#define SMF_END  448
#define FLASH_SMEM_BYTES (SM_HF_END * 2 + SMF_END * 4)

__global__ __launch_bounds__(256, 2) void flash_mma_kernel(
    const __half* __restrict__ qhi_g, const __half* __restrict__ qlo_g,
    const __half* __restrict__ k16, const __half* __restrict__ v16,
    __half* __restrict__ att16)
{
    extern __shared__ char smraw[];
    __half* hf = (__half*)smraw;
    float*  fp = (float*)(smraw + SM_HF_END * 2);

    __half* Qhi = hf + SM_QHI;
    __half* Qlo = hf + SM_QLO;
    __half* Khi = hf + SM_KHI;
    __half* Phi = hf + SM_PHI;
    __half* Vhi = hf + SM_VHI;
    float* wred = fp + SMF_WRED;
    float* mrow = fp + SMF_M;
    float* lrow = fp + SMF_L;
    float* arow = fp + SMF_A;

    const int tid  = threadIdx.x;
    const int lane = tid & 31;
    const int wid  = tid >> 5;
    const int wq   = wid >> 2;
    const int wn   = wid & 3;
    const int qb   = gridDim.x - 1 - blockIdx.x;
    const int h    = blockIdx.y;
    const int kvh  = h / (H_Q / KVH_);
    const int q0   = qb * BQ;
    const float scale = 0.08838834764831845f;

    // stage Q (hi/lo) via cp.async: 64 rows x 16 chunks x 2 planes
    #pragma unroll
    for (int it = 0; it < 4; it++) {
        int f = it * 256 + tid;
        int r = f >> 4, c = (f & 15) * 8;
        CP_ASYNC16(smem_u32(&Qhi[r * QVSTR + c]),
                   qhi_g + (size_t)(q0 + r) * QD + h * D_HEAD + c);
        CP_ASYNC16(smem_u32(&Qlo[r * QVSTR + c]),
                   qlo_g + (size_t)(q0 + r) * QD + h * D_HEAD + c);
    }
    CP_COMMIT();
    if (tid < BQ) { mrow[tid] = -1e30f; lrow[tid] = 0.f; }

    float accO[2][4][4];
    #pragma unroll
    for (int mi = 0; mi < 2; mi++)
        #pragma unroll
        for (int ni = 0; ni < 4; ni++)
            #pragma unroll
            for (int e = 0; e < 4; e++) accO[mi][ni][e] = 0.f;

    const int ntiles = q0 / BKV + 1;
    for (int jt = 0; jt < ntiles; jt++) {
        __syncthreads();   // S1: K/P and V smem free (PV of prev tile done)
        const int k0 = jt * BKV;
        #pragma unroll
        for (int it = 0; it < 8; it++) {
            int f = it * 256 + tid;
            int r = f >> 4, c = (f & 15) * 8;
            CP_ASYNC16(smem_u32(&Khi[r * QVSTR + c]),
                       k16 + (size_t)(k0 + r) * KD + kvh * D_HEAD + c);
            CP_ASYNC16(smem_u32(&Vhi[r * QVSTR + c]),
                       v16 + (size_t)(k0 + r) * KD + kvh * D_HEAD + c);
        }
        CP_COMMIT();
        CP_WAIT0();
        __syncthreads();   // S2: tiles (and Q on iter 0) staged

        // ---- S = Q K^T, warp tile 32x32 ----
        float accS[2][4][4];
        #pragma unroll
        for (int mi = 0; mi < 2; mi++)
            #pragma unroll
            for (int ni = 0; ni < 4; ni++)
                #pragma unroll
                for (int e = 0; e < 4; e++) accS[mi][ni][e] = 0.f;

        #pragma unroll
        for (int kk = 0; kk < 8; kk++) {
            unsigned ah[2][4], al[2][4], bh[4][2];
            const int arl = wq * 32 + (lane & 15);
            const int kcl = kk * 16 + (lane >> 4) * 8;
            ldsm_x4(smem_u32(&Qhi[arl * QVSTR + kcl]), ah[0]);
            ldsm_x4(smem_u32(&Qhi[(arl + 16) * QVSTR + kcl]), ah[1]);
            ldsm_x4(smem_u32(&Qlo[arl * QVSTR + kcl]), al[0]);
            ldsm_x4(smem_u32(&Qlo[(arl + 16) * QVSTR + kcl]), al[1]);
            #pragma unroll
            for (int nb = 0; nb < 2; nb++) {
                const int brl = wn * 32 + nb * 16 + (lane & 15);
                unsigned r[4];
                ldsm_x4(smem_u32(&Khi[brl * QVSTR + kcl]), r);
                bh[2 * nb][0] = r[0]; bh[2 * nb][1] = r[2];
                bh[2 * nb + 1][0] = r[1]; bh[2 * nb + 1][1] = r[3];
            }
            #pragma unroll
            for (int mi = 0; mi < 2; mi++)
                #pragma unroll
                for (int ni = 0; ni < 4; ni++) {
                    mma_f16(accS[mi][ni], ah[mi], bh[ni]);
                    mma_f16(accS[mi][ni], al[mi], bh[ni]);
                }
        }

        // ---- mask + scale + warp-local row max ----
        const bool diag = (jt == ntiles - 1);
        float mv[2][2];
        #pragma unroll
        for (int mi = 0; mi < 2; mi++)
            #pragma unroll
            for (int hf2 = 0; hf2 < 2; hf2++) {
                int row_g = q0 + wq * 32 + mi * 16 + (lane >> 2) + 8 * hf2;
                float mt = -1e30f;
                #pragma unroll
                for (int ni = 0; ni < 4; ni++)
                    #pragma unroll
                    for (int e = 0; e < 2; e++) {
                        int col_g = k0 + wn * 32 + ni * 8 + 2 * (lane & 3) + e;
                        float s = accS[mi][ni][2 * hf2 + e] * scale;
                        if (diag && col_g > row_g) s = -1e30f;
                        accS[mi][ni][2 * hf2 + e] = s;
                        mt = fmaxf(mt, s);
                    }
                mt = fmaxf(mt, __shfl_xor_sync(0xffffffffu, mt, 1));
                mt = fmaxf(mt, __shfl_xor_sync(0xffffffffu, mt, 2));
                mv[mi][hf2] = mt;
            }
        if ((lane & 3) == 0) {
            #pragma unroll
            for (int mi = 0; mi < 2; mi++)
                #pragma unroll
                for (int hf2 = 0; hf2 < 2; hf2++)
                    wred[wn * 64 + wq * 32 + mi * 16 + (lane >> 2) + 8 * hf2] = mv[mi][hf2];
        }
        __syncthreads();   // S3

        if (tid < BQ) {
            float mo = mrow[tid];
            float mn = fmaxf(fmaxf(wred[tid], wred[64 + tid]),
                             fmaxf(wred[128 + tid], wred[192 + tid]));
            mn = fmaxf(mn, mo);
            mrow[tid] = mn;
            arow[tid] = __expf(mo - mn);
        }
        __syncthreads();   // S4: K ldsm done -> P may overwrite

        // ---- exp, write P fp16 in ldsm layout, warp-partial sums ----
        {
            float mn[2][2], st[2][2];
            #pragma unroll
            for (int mi = 0; mi < 2; mi++)
                #pragma unroll
                for (int hf2 = 0; hf2 < 2; hf2++) {
                    mn[mi][hf2] = mrow[wq * 32 + mi * 16 + (lane >> 2) + 8 * hf2];
                    st[mi][hf2] = 0.f;
                }
            #pragma unroll
            for (int mi = 0; mi < 2; mi++)
                #pragma unroll
                for (int ni = 0; ni < 4; ni++)
                    #pragma unroll
                    for (int hf2 = 0; hf2 < 2; hf2++) {
                        float p0 = __expf(accS[mi][ni][2 * hf2 + 0] - mn[mi][hf2]);
                        float p1 = __expf(accS[mi][ni][2 * hf2 + 1] - mn[mi][hf2]);
                        __half h0 = __float2half_rn(p0);
                        __half h1 = __float2half_rn(p1);
                        st[mi][hf2] += __half2float(h0) + __half2float(h1);
                        int rl = wq * 32 + mi * 16 + (lane >> 2) + 8 * hf2;
                        int cl = wn * 32 + ni * 8 + 2 * (lane & 3);
                        *(__half2*)&Phi[rl * PSTR + cl] = __halves2half2(h0, h1);
                    }
            #pragma unroll
            for (int mi = 0; mi < 2; mi++)
                #pragma unroll
                for (int hf2 = 0; hf2 < 2; hf2++) {
                    float s = st[mi][hf2];
                    s += __shfl_xor_sync(0xffffffffu, s, 1);
                    s += __shfl_xor_sync(0xffffffffu, s, 2);
                    st[mi][hf2] = s;
                }
            if ((lane & 3) == 0) {
                #pragma unroll
                for (int mi = 0; mi < 2; mi++)
                    #pragma unroll
                    for (int hf2 = 0; hf2 < 2; hf2++)
                        wred[wn * 64 + wq * 32 + mi * 16 + (lane >> 2) + 8 * hf2] = st[mi][hf2];
            }
        }
        // rescale O by alpha
        {
            #pragma unroll
            for (int mi = 0; mi < 2; mi++) {
                float a0 = arow[wq * 32 + mi * 16 + (lane >> 2)];
                float a1 = arow[wq * 32 + mi * 16 + (lane >> 2) + 8];
                #pragma unroll
                for (int ni = 0; ni < 4; ni++) {
                    accO[mi][ni][0] *= a0;
                    accO[mi][ni][1] *= a0;
                    accO[mi][ni][2] *= a1;
                    accO[mi][ni][3] *= a1;
                }
            }
        }
        __syncthreads();   // S5: P + partial sums ready

        if (tid < BQ) {
            lrow[tid] = lrow[tid] * arow[tid] +
                        (wred[tid] + wred[64 + tid]) + (wred[128 + tid] + wred[192 + tid]);
        }

        // ---- O += P V, warp tile 32x32 over d ----
        #pragma unroll
        for (int kk = 0; kk < 8; kk++) {
            unsigned ph[2][4], vh[4][2];
            const int arl = wq * 32 + (lane & 15);
            const int kcl = kk * 16 + (lane >> 4) * 8;
            ldsm_x4(smem_u32(&Phi[arl * PSTR + kcl]), ph[0]);
            ldsm_x4(smem_u32(&Phi[(arl + 16) * PSTR + kcl]), ph[1]);
            const int krw = kk * 16 + ((lane >> 3) & 1) * 8 + (lane & 7);
            #pragma unroll
            for (int nb = 0; nb < 2; nb++) {
                const int ncl = wn * 32 + nb * 16 + (lane >> 4) * 8;
                unsigned r[4];
                ldsm_x4_t(smem_u32(&Vhi[krw * QVSTR + ncl]), r);
                vh[2 * nb][0] = r[0]; vh[2 * nb][1] = r[1];
                vh[2 * nb + 1][0] = r[2]; vh[2 * nb + 1][1] = r[3];
            }
            #pragma unroll
            for (int mi = 0; mi < 2; mi++)
                #pragma unroll
                for (int ni = 0; ni < 4; ni++)
                    mma_f16(accO[mi][ni], ph[mi], vh[ni]);
        }
    }

    __syncthreads();
    #pragma unroll
    for (int mi = 0; mi < 2; mi++) {
        int r0 = wq * 32 + mi * 16 + (lane >> 2);
        float inv0 = 1.0f / lrow[r0];
        float inv1 = 1.0f / lrow[r0 + 8];
        #pragma unroll
        for (int ni = 0; ni < 4; ni++) {
            int c0 = h * D_HEAD + wn * 32 + ni * 8 + 2 * (lane & 3);
            *(__half2*)(att16 + (size_t)(q0 + r0) * QD + c0) = __halves2half2(
                __float2half_rn(accO[mi][ni][0] * inv0),
                __float2half_rn(accO[mi][ni][1] * inv0));
            *(__half2*)(att16 + (size_t)(q0 + r0 + 8) * QD + c0) = __halves2half2(
                __float2half_rn(accO[mi][ni][2] * inv1),
                __float2half_rn(accO[mi][ni][3] * inv1));
        }
    }
}

// ---------------------------------------------------------------------------
extern "C" void kernel_launch(void* const* d_in, const int* in_sizes, int n_in,
                              void* d_out, int out_size)
{
    const float* x  = (const float*)d_in[0];
    // d_in[1] = mask (tril) — causality hardcoded, ignored.
    const float* Wq = (const float*)d_in[2];
    const float* Wk = (const float*)d_in[3];
    const float* Wv = (const float*)d_in[4];
    const float* Wo = (const float*)d_in[5];
    float* out = (float*)d_out;

    __half *x16, *wq16, *wk16, *wv16, *wo16, *qhi, *qlo, *k16, *v16, *att16;
    cudaGetSymbolAddress((void**)&x16,  g_x16);
    cudaGetSymbolAddress((void**)&wq16, g_wq16);
    cudaGetSymbolAddress((void**)&wk16, g_wk16);
    cudaGetSymbolAddress((void**)&wv16, g_wv16);
    cudaGetSymbolAddress((void**)&wo16, g_wo16);
    cudaGetSymbolAddress((void**)&qhi,  g_qhi);
    cudaGetSymbolAddress((void**)&qlo,  g_qlo);
    cudaGetSymbolAddress((void**)&k16,  g_k16);
    cudaGetSymbolAddress((void**)&v16,  g_v16);
    cudaGetSymbolAddress((void**)&att16, g_att16);

    cudaFuncSetAttribute(gemm_qkv_kernel,
                         cudaFuncAttributeMaxDynamicSharedMemorySize, GEMM_SMEM_BYTES);
    cudaFuncSetAttribute(gemm_out_kernel,
                         cudaFuncAttributeMaxDynamicSharedMemorySize, GEMM_SMEM_BYTES);
    cudaFuncSetAttribute(flash_mma_kernel,
                         cudaFuncAttributeMaxDynamicSharedMemorySize, FLASH_SMEM_BYTES);

    // 0. one-time fp32 -> fp16 conversions
    f2h_kernel<<<(T_SEQ * C_DIM / 4 + 255) / 256, 256>>>(x, x16, T_SEQ * C_DIM);
    f2h_kernel<<<(C_DIM * QD / 4 + 255) / 256, 256>>>(Wq, wq16, C_DIM * QD);
    f2h_kernel<<<(C_DIM * KD / 4 + 255) / 256, 256>>>(Wk, wk16, C_DIM * KD);
    f2h_kernel<<<(C_DIM * KD / 4 + 255) / 256, 256>>>(Wv, wv16, C_DIM * KD);
    f2h_kernel<<<(QD * C_DIM / 4 + 255) / 256, 256>>>(Wo, wo16, QD * C_DIM);

    // 1. fused QKV projection + RoPE (fp16 in, fp16 out)
    gemm_qkv_kernel<<<dim3(24, 32), 256, GEMM_SMEM_BYTES>>>(
        x16, wq16, wk16, wv16, qhi, qlo, k16, v16);

    // 2. flash attention (fp16 end-to-end, cp.async staging)
    flash_mma_kernel<<<dim3(T_SEQ / BQ, H_Q), 256, FLASH_SMEM_BYTES>>>(
        qhi, qlo, k16, v16, att16);

    // 3. output projection (fp16 in, fp32 out)
    gemm_out_kernel<<<dim3(C_DIM / 128, T_SEQ / 128), 256, GEMM_SMEM_BYTES>>>(
        att16, wo16, out);
}

// round 15
// speedup vs baseline: 8.9397x; 1.0541x over previous
#include <cuda_runtime.h>
#include <cuda_fp16.h>
#include <stdint.h>
#include <math.h>

#define T_SEQ 4096
#define C_DIM 2048
#define H_Q   16
#define KVH_  4
#define D_HEAD 128
#define QD (H_Q * D_HEAD)    // 2048
#define KD (KVH_ * D_HEAD)   // 512

// fp16 intermediates (allocation-free rule: device globals)
__device__ __half g_x16[T_SEQ * C_DIM];
__device__ __half g_wq16[C_DIM * QD];
__device__ __half g_wk16[C_DIM * KD];
__device__ __half g_wv16[C_DIM * KD];
__device__ __half g_wo16[QD * C_DIM];
__device__ __half g_qhi[T_SEQ * QD];
__device__ __half g_qlo[T_SEQ * QD];
__device__ __half g_k16[T_SEQ * KD];
__device__ __half g_v16[T_SEQ * KD];
__device__ __half g_att16[T_SEQ * QD];

__device__ __forceinline__ unsigned smem_u32(const void* p) {
    return (unsigned)__cvta_generic_to_shared(p);
}
__device__ __forceinline__ void ldsm_x4(unsigned addr, unsigned* r) {
    asm volatile("ldmatrix.sync.aligned.m8n8.x4.shared.b16 {%0,%1,%2,%3}, [%4];\n"
                 : "=r"(r[0]), "=r"(r[1]), "=r"(r[2]), "=r"(r[3]) : "r"(addr));
}
__device__ __forceinline__ void ldsm_x4_t(unsigned addr, unsigned* r) {
    asm volatile("ldmatrix.sync.aligned.m8n8.x4.trans.shared.b16 {%0,%1,%2,%3}, [%4];\n"
                 : "=r"(r[0]), "=r"(r[1]), "=r"(r[2]), "=r"(r[3]) : "r"(addr));
}
__device__ __forceinline__ void mma_f16(float* d, const unsigned* a, const unsigned* b) {
    asm volatile("mma.sync.aligned.m16n8k16.row.col.f32.f16.f16.f32 "
                 "{%0,%1,%2,%3}, {%4,%5,%6,%7}, {%8,%9}, {%0,%1,%2,%3};\n"
                 : "+f"(d[0]), "+f"(d[1]), "+f"(d[2]), "+f"(d[3])
                 : "r"(a[0]), "r"(a[1]), "r"(a[2]), "r"(a[3]),
                   "r"(b[0]), "r"(b[1]));
}
#define CP_ASYNC16(dst, src) \
    asm volatile("cp.async.ca.shared.global [%0], [%1], 16;\n" :: "r"(dst), "l"(src))
#define CP_ASYNC8(dst, src) \
    asm volatile("cp.async.ca.shared.global [%0], [%1], 8;\n" :: "r"(dst), "l"(src))
#define CP_COMMIT() asm volatile("cp.async.commit_group;\n" ::: "memory")
#define CP_WAIT0()  asm volatile("cp.async.wait_group 0;\n" ::: "memory")
#define CP_WAIT1()  asm volatile("cp.async.wait_group 1;\n" ::: "memory")

__device__ __forceinline__ void pack_store4h(float4 v, __half* dst) {
    *(__half2*)(dst)     = __halves2half2(__float2half_rn(v.x), __float2half_rn(v.y));
    *(__half2*)(dst + 2) = __halves2half2(__float2half_rn(v.z), __float2half_rn(v.w));
}

// ---------------------------------------------------------------------------
// fp32 -> fp16 convert (one-time, per tensor)
// ---------------------------------------------------------------------------
__global__ void f2h_kernel(const float* __restrict__ in, __half* __restrict__ out, int n)
{
    int i = (blockIdx.x * blockDim.x + threadIdx.x) * 4;
    if (i < n) pack_store4h(*(const float4*)(in + i), out + i);
}

// ===========================================================================
// fp16 tensor-core GEMM, cp.async staging (unchanged from R14).
// ===========================================================================
#define AS_STRIDE 40
#define BS_STRIDE 136
#define APL (128 * AS_STRIDE)
#define BPL (32 * BS_STRIDE)
#define BUF_ELEMS (APL + BPL)
#define GEMM_SMEM_BYTES (2 * BUF_ELEMS * 2)

__device__ __forceinline__ void gemm_issue_tile(
    const __half* __restrict__ A, const __half* __restrict__ B,
    int N, int K, int bm0, int bn0, int k0, __half* Asm, int tid)
{
    __half* Bsm = Asm + APL;
    #pragma unroll
    for (int it = 0; it < 4; it++) {
        int f = it * 256 + tid;
        int row = f >> 3, c = (f & 7) * 4;
        CP_ASYNC8(smem_u32(&Asm[row * AS_STRIDE + c]),
                  A + (size_t)(bm0 + row) * K + k0 + c);
    }
    #pragma unroll
    for (int it = 0; it < 2; it++) {
        int f = it * 256 + tid;
        int row = f >> 4, c = (f & 15) * 8;
        CP_ASYNC16(smem_u32(&Bsm[row * BS_STRIDE + c]),
                   B + (size_t)(k0 + row) * N + bn0 + c);
    }
}

__device__ __forceinline__ void gemm_core_h(
    int N, int K, int rope, int mode,
    const __half* __restrict__ A, const __half* __restrict__ B,
    float* __restrict__ Cf, __half* __restrict__ C1, __half* __restrict__ C2,
    int bm0, int bn0, char* smraw)
{
    __half* bufs = (__half*)smraw;

    const int tid  = threadIdx.x;
    const int lane = tid & 31;
    const int wid  = tid >> 5;
    const int wm   = wid >> 2;
    const int wn   = wid & 3;

    float acc[4][4][4];
    #pragma unroll
    for (int mi = 0; mi < 4; mi++)
        #pragma unroll
        for (int ni = 0; ni < 4; ni++)
            #pragma unroll
            for (int e = 0; e < 4; e++) acc[mi][ni][e] = 0.f;

    const int ktiles = K >> 5;

    gemm_issue_tile(A, B, N, K, bm0, bn0, 0, bufs, tid);
    CP_COMMIT();

    for (int kt = 0; kt < ktiles; kt++) {
        CP_WAIT0();
        __syncthreads();
        if (kt + 1 < ktiles) {
            gemm_issue_tile(A, B, N, K, bm0, bn0, (kt + 1) << 5,
                            bufs + ((kt + 1) & 1) * BUF_ELEMS, tid);
            CP_COMMIT();
        }

        __half* As = bufs + (kt & 1) * BUF_ELEMS;
        __half* Bs = As + APL;

        #pragma unroll
        for (int ks = 0; ks < 2; ks++) {
            const int k = ks * 16;
            unsigned ah[4][4], bh[4][2];

            const int arl = wm * 64 + (lane & 15);
            const int kcl = k + (lane >> 4) * 8;
            #pragma unroll
            for (int mi = 0; mi < 4; mi++)
                ldsm_x4(smem_u32(&As[(arl + mi * 16) * AS_STRIDE + kcl]), ah[mi]);
            const int krw = k + ((lane >> 3) & 1) * 8 + (lane & 7);
            #pragma unroll
            for (int nb = 0; nb < 2; nb++) {
                const int ncl = wn * 32 + nb * 16 + (lane >> 4) * 8;
                unsigned r[4];
                ldsm_x4_t(smem_u32(&Bs[krw * BS_STRIDE + ncl]), r);
                bh[2 * nb][0] = r[0]; bh[2 * nb][1] = r[1];
                bh[2 * nb + 1][0] = r[2]; bh[2 * nb + 1][1] = r[3];
            }

            #pragma unroll
            for (int mi = 0; mi < 4; mi++)
                #pragma unroll
                for (int ni = 0; ni < 4; ni++)
                    mma_f16(acc[mi][ni], ah[mi], bh[ni]);
        }
    }

    const int gid = lane >> 2, tig = lane & 3;

    if (rope) {
        #pragma unroll
        for (int ni = 0; ni < 4; ni++) {
            int c0 = bn0 + wn * 32 + ni * 8 + tig * 2;
            int d2 = (c0 & 127) >> 1;
            float inv = (float)exp(-(double)d2 * 0.14391156831212787); // ln(1e4)/64
            #pragma unroll
            for (int mi = 0; mi < 4; mi++) {
                int t0 = bm0 + wm * 64 + mi * 16 + gid;
                float a0 = (float)t0 * inv;
                float a1 = (float)(t0 + 8) * inv;
                float c0f = cosf(a0), s0f = sinf(a0);
                float c1f = cosf(a1), s1f = sinf(a1);
                float x0 = acc[mi][ni][0], x1 = acc[mi][ni][1];
                acc[mi][ni][0] = x0 * c0f - x1 * s0f;
                acc[mi][ni][1] = x0 * s0f + x1 * c0f;
                x0 = acc[mi][ni][2]; x1 = acc[mi][ni][3];
                acc[mi][ni][2] = x0 * c1f - x1 * s1f;
                acc[mi][ni][3] = x0 * s1f + x1 * c1f;
            }
        }
    }

    #pragma unroll
    for (int mi = 0; mi < 4; mi++)
        #pragma unroll
        for (int ni = 0; ni < 4; ni++) {
            int r0 = bm0 + wm * 64 + mi * 16 + gid;
            int c0 = bn0 + wn * 32 + ni * 8 + tig * 2;
            if (mode == 0) {
                *(float2*)(Cf + (size_t)r0 * N + c0) =
                    make_float2(acc[mi][ni][0], acc[mi][ni][1]);
                *(float2*)(Cf + (size_t)(r0 + 8) * N + c0) =
                    make_float2(acc[mi][ni][2], acc[mi][ni][3]);
            } else if (mode == 1) {
                *(__half2*)(C1 + (size_t)r0 * N + c0) = __halves2half2(
                    __float2half_rn(acc[mi][ni][0]), __float2half_rn(acc[mi][ni][1]));
                *(__half2*)(C1 + (size_t)(r0 + 8) * N + c0) = __halves2half2(
                    __float2half_rn(acc[mi][ni][2]), __float2half_rn(acc[mi][ni][3]));
            } else {
                __half h0 = __float2half_rn(acc[mi][ni][0]);
                __half h1 = __float2half_rn(acc[mi][ni][1]);
                __half h2 = __float2half_rn(acc[mi][ni][2]);
                __half h3 = __float2half_rn(acc[mi][ni][3]);
                *(__half2*)(C1 + (size_t)r0 * N + c0) = __halves2half2(h0, h1);
                *(__half2*)(C1 + (size_t)(r0 + 8) * N + c0) = __halves2half2(h2, h3);
                __half l0 = __float2half_rn(acc[mi][ni][0] - __half2float(h0));
                __half l1 = __float2half_rn(acc[mi][ni][1] - __half2float(h1));
                __half l2 = __float2half_rn(acc[mi][ni][2] - __half2float(h2));
                __half l3 = __float2half_rn(acc[mi][ni][3] - __half2float(h3));
                *(__half2*)(C2 + (size_t)r0 * N + c0) = __halves2half2(l0, l1);
                *(__half2*)(C2 + (size_t)(r0 + 8) * N + c0) = __halves2half2(l2, l3);
            }
        }
}

__global__ __launch_bounds__(256) void gemm_qkv_kernel(
    const __half* __restrict__ x16,
    const __half* __restrict__ wq16, const __half* __restrict__ wk16,
    const __half* __restrict__ wv16,
    __half* __restrict__ qhi, __half* __restrict__ qlo,
    __half* __restrict__ k16, __half* __restrict__ v16)
{
    extern __shared__ char smraw[];
    const int bx = blockIdx.x;
    const int bm0 = blockIdx.y * 128;
    if (bx < 16) {
        gemm_core_h(QD, C_DIM, 1, 2, x16, wq16, 0, qhi, qlo, bm0, bx * 128, smraw);
    } else if (bx < 20) {
        gemm_core_h(KD, C_DIM, 1, 1, x16, wk16, 0, k16, 0, bm0, (bx - 16) * 128, smraw);
    } else {
        gemm_core_h(KD, C_DIM, 0, 1, x16, wv16, 0, v16, 0, bm0, (bx - 20) * 128, smraw);
    }
}

__global__ __launch_bounds__(256) void gemm_out_kernel(
    const __half* __restrict__ att16, const __half* __restrict__ wo16,
    float* __restrict__ out)
{
    extern __shared__ char smraw[];
    gemm_core_h(C_DIM, QD, 0, 0, att16, wo16, out, 0, 0,
                blockIdx.y * 128, blockIdx.x * 128, smraw);
}

// ===========================================================================
// FA2-style flash: BQ=128, 8 warps, each warp owns 16 q-rows x full KV width.
// Q (hi/lo) register-resident; softmax fully warp-local (regs + quad shfl);
// P converted in-register from C-frag to A-frag (no smem). K/V double-buffered
// cp.async ring aliasing the Q staging area. 2 barriers per tile.
// ===========================================================================
#define FQ 128
#define FKV 64
#define FSTR 136
#define KVSEG (FKV * FSTR)                   // 8704 halfs
#define FLASH_SMEM_BYTES (4 * KVSEG * 2)     // 69632 B (== Q staging size)

__device__ __forceinline__ void flash_issue_kv(
    const __half* __restrict__ k16, const __half* __restrict__ v16,
    int k0, int kvh, __half* Ks, int tid)
{
    __half* Vs = Ks + KVSEG;
    #pragma unroll
    for (int it = 0; it < 4; it++) {
        int f = it * 256 + tid;
        int r = f >> 4, c = (f & 15) * 8;
        CP_ASYNC16(smem_u32(&Ks[r * FSTR + c]),
                   k16 + (size_t)(k0 + r) * KD + kvh * D_HEAD + c);
    }
    #pragma unroll
    for (int it = 0; it < 4; it++) {
        int f = it * 256 + tid;
        int r = f >> 4, c = (f & 15) * 8;
        CP_ASYNC16(smem_u32(&Vs[r * FSTR + c]),
                   v16 + (size_t)(k0 + r) * KD + kvh * D_HEAD + c);
    }
}

__global__ __launch_bounds__(256, 1) void flash_mma_kernel(
    const __half* __restrict__ qhi_g, const __half* __restrict__ qlo_g,
    const __half* __restrict__ k16, const __half* __restrict__ v16,
    __half* __restrict__ att16)
{
    extern __shared__ char smraw[];
    __half* sm = (__half*)smraw;

    const int tid  = threadIdx.x;
    const int lane = tid & 31;
    const int w    = tid >> 5;
    const int gid  = lane >> 2;
    const int tig  = lane & 3;
    const int qb   = gridDim.x - 1 - blockIdx.x;  // heavy blocks first
    const int h    = blockIdx.y;
    const int kvh  = h / (H_Q / KVH_);
    const int q0   = qb * FQ;
    const float scale = 0.08838834764831845f;

    // ---- stage Q (hi/lo) and load into registers ----
    {
        __half* Qhi = sm;
        __half* Qlo = sm + 128 * FSTR;
        #pragma unroll
        for (int it = 0; it < 8; it++) {
            int f = it * 256 + tid;
            int r = f >> 4, c = (f & 15) * 8;
            CP_ASYNC16(smem_u32(&Qhi[r * FSTR + c]),
                       qhi_g + (size_t)(q0 + r) * QD + h * D_HEAD + c);
            CP_ASYNC16(smem_u32(&Qlo[r * FSTR + c]),
                       qlo_g + (size_t)(q0 + r) * QD + h * D_HEAD + c);
        }
        CP_COMMIT();
        CP_WAIT0();
        __syncthreads();
    }
    unsigned qh[8][4], ql[8][4];
    {
        __half* Qhi = sm;
        __half* Qlo = sm + 128 * FSTR;
        const int arl = w * 16 + (lane & 15);
        #pragma unroll
        for (int kk = 0; kk < 8; kk++) {
            const int kcl = kk * 16 + (lane >> 4) * 8;
            ldsm_x4(smem_u32(&Qhi[arl * FSTR + kcl]), qh[kk]);
            ldsm_x4(smem_u32(&Qlo[arl * FSTR + kcl]), ql[kk]);
        }
    }
    __syncthreads();   // Q smem now free for the K/V ring

    float accO[16][4];
    #pragma unroll
    for (int df = 0; df < 16; df++)
        #pragma unroll
        for (int e = 0; e < 4; e++) accO[df][e] = 0.f;
    float m0 = -1e30f, m1 = -1e30f, l0 = 0.f, l1 = 0.f;

    const int row0 = q0 + w * 16 + gid;   // this thread's rows: row0, row0+8
    const int ntiles = 2 * qb + 2;

    flash_issue_kv(k16, v16, 0, kvh, sm, tid);
    CP_COMMIT();

    for (int jt = 0; jt < ntiles; jt++) {
        const int k0 = jt * FKV;
        const bool hasnext = (jt + 1 < ntiles);
        if (hasnext) {
            if (jt > 0) __syncthreads();   // all warps done reading buf[(jt+1)&1]
            flash_issue_kv(k16, v16, (jt + 1) * FKV, kvh,
                           sm + ((jt + 1) & 1) * 2 * KVSEG, tid);
            CP_COMMIT();
            CP_WAIT1();
        } else {
            CP_WAIT0();
        }
        __syncthreads();   // buf[jt&1] visible

        __half* Ks = sm + (jt & 1) * 2 * KVSEG;
        __half* Vs = Ks + KVSEG;

        // ---- S = Q K^T: 16 rows x 64 cols per warp ----
        float accS[8][4];
        #pragma unroll
        for (int nf = 0; nf < 8; nf++)
            #pragma unroll
            for (int e = 0; e < 4; e++) accS[nf][e] = 0.f;

        #pragma unroll
        for (int kk = 0; kk < 8; kk++) {
            const int kcl = kk * 16 + (lane >> 4) * 8;
            unsigned bh[8][2];
            #pragma unroll
            for (int nb = 0; nb < 4; nb++) {
                const int brl = nb * 16 + (lane & 15);
                unsigned r[4];
                ldsm_x4(smem_u32(&Ks[brl * FSTR + kcl]), r);
                bh[2 * nb][0] = r[0]; bh[2 * nb][1] = r[2];
                bh[2 * nb + 1][0] = r[1]; bh[2 * nb + 1][1] = r[3];
            }
            #pragma unroll
            for (int nf = 0; nf < 8; nf++) {
                mma_f16(accS[nf], qh[kk], bh[nf]);
                mma_f16(accS[nf], ql[kk], bh[nf]);
            }
        }

        // ---- warp-local softmax (registers + quad shfl) ----
        const bool needmask = (k0 + FKV - 1 > q0);
        float mt0 = -1e30f, mt1 = -1e30f;
        #pragma unroll
        for (int nf = 0; nf < 8; nf++)
            #pragma unroll
            for (int e = 0; e < 2; e++) {
                int col = k0 + nf * 8 + 2 * tig + e;
                float s = accS[nf][e] * scale;
                if (needmask && col > row0) s = -1e30f;
                accS[nf][e] = s;
                mt0 = fmaxf(mt0, s);
                float s2 = accS[nf][2 + e] * scale;
                if (needmask && col > row0 + 8) s2 = -1e30f;
                accS[nf][2 + e] = s2;
                mt1 = fmaxf(mt1, s2);
            }
        mt0 = fmaxf(mt0, __shfl_xor_sync(0xffffffffu, mt0, 1));
        mt0 = fmaxf(mt0, __shfl_xor_sync(0xffffffffu, mt0, 2));
        mt1 = fmaxf(mt1, __shfl_xor_sync(0xffffffffu, mt1, 1));
        mt1 = fmaxf(mt1, __shfl_xor_sync(0xffffffffu, mt1, 2));
        float mn0 = fmaxf(m0, mt0), mn1 = fmaxf(m1, mt1);
        float al0 = __expf(m0 - mn0), al1 = __expf(m1 - mn1);
        m0 = mn0; m1 = mn1;

        unsigned ph2[8][2];
        float s0 = 0.f, s1 = 0.f;
        #pragma unroll
        for (int nf = 0; nf < 8; nf++) {
            float p00 = __expf(accS[nf][0] - mn0);
            float p01 = __expf(accS[nf][1] - mn0);
            float p10 = __expf(accS[nf][2] - mn1);
            float p11 = __expf(accS[nf][3] - mn1);
            __half h00 = __float2half_rn(p00), h01 = __float2half_rn(p01);
            __half h10 = __float2half_rn(p10), h11 = __float2half_rn(p11);
            __half2 t0 = __halves2half2(h00, h01);
            __half2 t1 = __halves2half2(h10, h11);
            ph2[nf][0] = *(unsigned*)&t0;
            ph2[nf][1] = *(unsigned*)&t1;
            s0 += __half2float(h00) + __half2float(h01);
            s1 += __half2float(h10) + __half2float(h11);
        }
        s0 += __shfl_xor_sync(0xffffffffu, s0, 1);
        s0 += __shfl_xor_sync(0xffffffffu, s0, 2);
        s1 += __shfl_xor_sync(0xffffffffu, s1, 1);
        s1 += __shfl_xor_sync(0xffffffffu, s1, 2);
        l0 = l0 * al0 + s0;
        l1 = l1 * al1 + s1;

        #pragma unroll
        for (int df = 0; df < 16; df++) {
            accO[df][0] *= al0; accO[df][1] *= al0;
            accO[df][2] *= al1; accO[df][3] *= al1;
        }

        // ---- O += P V: P from C-frag -> A-frag in registers ----
        #pragma unroll
        for (int jk = 0; jk < 4; jk++) {
            unsigned pa[4] = { ph2[2 * jk][0], ph2[2 * jk][1],
                               ph2[2 * jk + 1][0], ph2[2 * jk + 1][1] };
            const int krw = jk * 16 + ((lane >> 3) & 1) * 8 + (lane & 7);
            #pragma unroll
            for (int nb = 0; nb < 8; nb++) {
                const int ncl = nb * 16 + (lane >> 4) * 8;
                unsigned r[4];
                ldsm_x4_t(smem_u32(&Vs[krw * FSTR + ncl]), r);
                unsigned b0[2] = { r[0], r[1] };
                unsigned b1[2] = { r[2], r[3] };
                mma_f16(accO[2 * nb], pa, b0);
                mma_f16(accO[2 * nb + 1], pa, b1);
            }
        }
    }

    // ---- epilogue: normalize, store fp16 att ----
    const float i0 = 1.0f / l0, i1 = 1.0f / l1;
    #pragma unroll
    for (int df = 0; df < 16; df++) {
        int c = h * D_HEAD + df * 8 + 2 * tig;
        *(__half2*)(att16 + (size_t)row0 * QD + c) = __halves2half2(
            __float2half_rn(accO[df][0] * i0), __float2half_rn(accO[df][1] * i0));
        *(__half2*)(att16 + (size_t)(row0 + 8) * QD + c) = __halves2half2(
            __float2half_rn(accO[df][2] * i1), __float2half_rn(accO[df][3] * i1));
    }
}

// ---------------------------------------------------------------------------
extern "C" void kernel_launch(void* const* d_in, const int* in_sizes, int n_in,
                              void* d_out, int out_size)
{
    const float* x  = (const float*)d_in[0];
    // d_in[1] = mask (tril) — causality hardcoded, ignored.
    const float* Wq = (const float*)d_in[2];
    const float* Wk = (const float*)d_in[3];
    const float* Wv = (const float*)d_in[4];
    const float* Wo = (const float*)d_in[5];
    float* out = (float*)d_out;

    __half *x16, *wq16, *wk16, *wv16, *wo16, *qhi, *qlo, *k16, *v16, *att16;
    cudaGetSymbolAddress((void**)&x16,  g_x16);
    cudaGetSymbolAddress((void**)&wq16, g_wq16);
    cudaGetSymbolAddress((void**)&wk16, g_wk16);
    cudaGetSymbolAddress((void**)&wv16, g_wv16);
    cudaGetSymbolAddress((void**)&wo16, g_wo16);
    cudaGetSymbolAddress((void**)&qhi,  g_qhi);
    cudaGetSymbolAddress((void**)&qlo,  g_qlo);
    cudaGetSymbolAddress((void**)&k16,  g_k16);
    cudaGetSymbolAddress((void**)&v16,  g_v16);
    cudaGetSymbolAddress((void**)&att16, g_att16);

    cudaFuncSetAttribute(gemm_qkv_kernel,
                         cudaFuncAttributeMaxDynamicSharedMemorySize, GEMM_SMEM_BYTES);
    cudaFuncSetAttribute(gemm_out_kernel,
                         cudaFuncAttributeMaxDynamicSharedMemorySize, GEMM_SMEM_BYTES);
    cudaFuncSetAttribute(flash_mma_kernel,
                         cudaFuncAttributeMaxDynamicSharedMemorySize, FLASH_SMEM_BYTES);

    // 0. one-time fp32 -> fp16 conversions
    f2h_kernel<<<(T_SEQ * C_DIM / 4 + 255) / 256, 256>>>(x, x16, T_SEQ * C_DIM);
    f2h_kernel<<<(C_DIM * QD / 4 + 255) / 256, 256>>>(Wq, wq16, C_DIM * QD);
    f2h_kernel<<<(C_DIM * KD / 4 + 255) / 256, 256>>>(Wk, wk16, C_DIM * KD);
    f2h_kernel<<<(C_DIM * KD / 4 + 255) / 256, 256>>>(Wv, wv16, C_DIM * KD);
    f2h_kernel<<<(QD * C_DIM / 4 + 255) / 256, 256>>>(Wo, wo16, QD * C_DIM);

    // 1. fused QKV projection + RoPE (fp16 in, fp16 out)
    gemm_qkv_kernel<<<dim3(24, 32), 256, GEMM_SMEM_BYTES>>>(
        x16, wq16, wk16, wv16, qhi, qlo, k16, v16);

    // 2. flash attention (FA2-style, register softmax, BQ=128)
    flash_mma_kernel<<<dim3(T_SEQ / FQ, H_Q), 256, FLASH_SMEM_BYTES>>>(
        qhi, qlo, k16, v16, att16);

    // 3. output projection (fp16 in, fp32 out)
    gemm_out_kernel<<<dim3(C_DIM / 128, T_SEQ / 128), 256, GEMM_SMEM_BYTES>>>(
        att16, wo16, out);
}

// round 17
// speedup vs baseline: 10.0470x; 1.1239x over previous
#include <cuda_runtime.h>
#include <cuda_fp16.h>
#include <stdint.h>
#include <math.h>

#define T_SEQ 4096
#define C_DIM 2048
#define H_Q   16
#define KVH_  4
#define D_HEAD 128
#define QD (H_Q * D_HEAD)    // 2048
#define KD (KVH_ * D_HEAD)   // 512

// fp16 intermediates (allocation-free rule: device globals)
__device__ __half g_x16[T_SEQ * C_DIM];
__device__ __half g_wq16[C_DIM * QD];
__device__ __half g_wk16[C_DIM * KD];
__device__ __half g_wv16[C_DIM * KD];
__device__ __half g_wo16[QD * C_DIM];
__device__ __half g_q16[T_SEQ * QD];
__device__ __half g_k16[T_SEQ * KD];
__device__ __half g_v16[T_SEQ * KD];
__device__ __half g_att16[T_SEQ * QD];

__device__ __forceinline__ unsigned smem_u32(const void* p) {
    return (unsigned)__cvta_generic_to_shared(p);
}
__device__ __forceinline__ void ldsm_x4(unsigned addr, unsigned* r) {
    asm volatile("ldmatrix.sync.aligned.m8n8.x4.shared.b16 {%0,%1,%2,%3}, [%4];\n"
                 : "=r"(r[0]), "=r"(r[1]), "=r"(r[2]), "=r"(r[3]) : "r"(addr));
}
__device__ __forceinline__ void ldsm_x4_t(unsigned addr, unsigned* r) {
    asm volatile("ldmatrix.sync.aligned.m8n8.x4.trans.shared.b16 {%0,%1,%2,%3}, [%4];\n"
                 : "=r"(r[0]), "=r"(r[1]), "=r"(r[2]), "=r"(r[3]) : "r"(addr));
}
__device__ __forceinline__ void mma_f16(float* d, const unsigned* a, const unsigned* b) {
    asm volatile("mma.sync.aligned.m16n8k16.row.col.f32.f16.f16.f32 "
                 "{%0,%1,%2,%3}, {%4,%5,%6,%7}, {%8,%9}, {%0,%1,%2,%3};\n"
                 : "+f"(d[0]), "+f"(d[1]), "+f"(d[2]), "+f"(d[3])
                 : "r"(a[0]), "r"(a[1]), "r"(a[2]), "r"(a[3]),
                   "r"(b[0]), "r"(b[1]));
}
#define CP_ASYNC16(dst, src) \
    asm volatile("cp.async.ca.shared.global [%0], [%1], 16;\n" :: "r"(dst), "l"(src))
#define CP_ASYNC8(dst, src) \
    asm volatile("cp.async.ca.shared.global [%0], [%1], 8;\n" :: "r"(dst), "l"(src))
#define CP_COMMIT() asm volatile("cp.async.commit_group;\n" ::: "memory")
#define CP_WAIT0()  asm volatile("cp.async.wait_group 0;\n" ::: "memory")
#define CP_WAIT1()  asm volatile("cp.async.wait_group 1;\n" ::: "memory")

__device__ __forceinline__ void pack_store4h(float4 v, __half* dst) {
    *(__half2*)(dst)     = __halves2half2(__float2half_rn(v.x), __float2half_rn(v.y));
    *(__half2*)(dst + 2) = __halves2half2(__float2half_rn(v.z), __float2half_rn(v.w));
}

// ---------------------------------------------------------------------------
// fp32 -> fp16 convert (one-time, per tensor)
// ---------------------------------------------------------------------------
__global__ void f2h_kernel(const float* __restrict__ in, __half* __restrict__ out, int n)
{
    int i = (blockIdx.x * blockDim.x + threadIdx.x) * 4;
    if (i < n) pack_store4h(*(const float4*)(in + i), out + i);
}

// ===========================================================================
// fp16 tensor-core GEMM, cp.async staging. mode 0 = fp32 out, 1 = fp16 out.
// 128x128x32 tile, 256 threads (2x4 warps), double-buffered, fused RoPE opt.
// ===========================================================================
#define AS_STRIDE 40
#define BS_STRIDE 136
#define APL (128 * AS_STRIDE)
#define BPL (32 * BS_STRIDE)
#define BUF_ELEMS (APL + BPL)
#define GEMM_SMEM_BYTES (2 * BUF_ELEMS * 2)

__device__ __forceinline__ void gemm_issue_tile(
    const __half* __restrict__ A, const __half* __restrict__ B,
    int N, int K, int bm0, int bn0, int k0, __half* Asm, int tid)
{
    __half* Bsm = Asm + APL;
    #pragma unroll
    for (int it = 0; it < 4; it++) {
        int f = it * 256 + tid;
        int row = f >> 3, c = (f & 7) * 4;
        CP_ASYNC8(smem_u32(&Asm[row * AS_STRIDE + c]),
                  A + (size_t)(bm0 + row) * K + k0 + c);
    }
    #pragma unroll
    for (int it = 0; it < 2; it++) {
        int f = it * 256 + tid;
        int row = f >> 4, c = (f & 15) * 8;
        CP_ASYNC16(smem_u32(&Bsm[row * BS_STRIDE + c]),
                   B + (size_t)(k0 + row) * N + bn0 + c);
    }
}

__device__ __forceinline__ void gemm_core_h(
    int N, int K, int rope, int mode,
    const __half* __restrict__ A, const __half* __restrict__ B,
    float* __restrict__ Cf, __half* __restrict__ C1,
    int bm0, int bn0, char* smraw)
{
    __half* bufs = (__half*)smraw;

    const int tid  = threadIdx.x;
    const int lane = tid & 31;
    const int wid  = tid >> 5;
    const int wm   = wid >> 2;
    const int wn   = wid & 3;

    float acc[4][4][4];
    #pragma unroll
    for (int mi = 0; mi < 4; mi++)
        #pragma unroll
        for (int ni = 0; ni < 4; ni++)
            #pragma unroll
            for (int e = 0; e < 4; e++) acc[mi][ni][e] = 0.f;

    const int ktiles = K >> 5;

    gemm_issue_tile(A, B, N, K, bm0, bn0, 0, bufs, tid);
    CP_COMMIT();

    for (int kt = 0; kt < ktiles; kt++) {
        CP_WAIT0();
        __syncthreads();
        if (kt + 1 < ktiles) {
            gemm_issue_tile(A, B, N, K, bm0, bn0, (kt + 1) << 5,
                            bufs + ((kt + 1) & 1) * BUF_ELEMS, tid);
            CP_COMMIT();
        }

        __half* As = bufs + (kt & 1) * BUF_ELEMS;
        __half* Bs = As + APL;

        #pragma unroll
        for (int ks = 0; ks < 2; ks++) {
            const int k = ks * 16;
            unsigned ah[4][4], bh[4][2];

            const int arl = wm * 64 + (lane & 15);
            const int kcl = k + (lane >> 4) * 8;
            #pragma unroll
            for (int mi = 0; mi < 4; mi++)
                ldsm_x4(smem_u32(&As[(arl + mi * 16) * AS_STRIDE + kcl]), ah[mi]);
            const int krw = k + ((lane >> 3) & 1) * 8 + (lane & 7);
            #pragma unroll
            for (int nb = 0; nb < 2; nb++) {
                const int ncl = wn * 32 + nb * 16 + (lane >> 4) * 8;
                unsigned r[4];
                ldsm_x4_t(smem_u32(&Bs[krw * BS_STRIDE + ncl]), r);
                bh[2 * nb][0] = r[0]; bh[2 * nb][1] = r[1];
                bh[2 * nb + 1][0] = r[2]; bh[2 * nb + 1][1] = r[3];
            }

            #pragma unroll
            for (int mi = 0; mi < 4; mi++)
                #pragma unroll
                for (int ni = 0; ni < 4; ni++)
                    mma_f16(acc[mi][ni], ah[mi], bh[ni]);
        }
    }

    const int gid = lane >> 2, tig = lane & 3;

    if (rope) {
        #pragma unroll
        for (int ni = 0; ni < 4; ni++) {
            int c0 = bn0 + wn * 32 + ni * 8 + tig * 2;
            int d2 = (c0 & 127) >> 1;
            float inv = (float)exp(-(double)d2 * 0.14391156831212787); // ln(1e4)/64
            #pragma unroll
            for (int mi = 0; mi < 4; mi++) {
                int t0 = bm0 + wm * 64 + mi * 16 + gid;
                float a0 = (float)t0 * inv;
                float a1 = (float)(t0 + 8) * inv;
                float c0f = cosf(a0), s0f = sinf(a0);
                float c1f = cosf(a1), s1f = sinf(a1);
                float x0 = acc[mi][ni][0], x1 = acc[mi][ni][1];
                acc[mi][ni][0] = x0 * c0f - x1 * s0f;
                acc[mi][ni][1] = x0 * s0f + x1 * c0f;
                x0 = acc[mi][ni][2]; x1 = acc[mi][ni][3];
                acc[mi][ni][2] = x0 * c1f - x1 * s1f;
                acc[mi][ni][3] = x0 * s1f + x1 * c1f;
            }
        }
    }

    #pragma unroll
    for (int mi = 0; mi < 4; mi++)
        #pragma unroll
        for (int ni = 0; ni < 4; ni++) {
            int r0 = bm0 + wm * 64 + mi * 16 + gid;
            int c0 = bn0 + wn * 32 + ni * 8 + tig * 2;
            if (mode == 0) {
                *(float2*)(Cf + (size_t)r0 * N + c0) =
                    make_float2(acc[mi][ni][0], acc[mi][ni][1]);
                *(float2*)(Cf + (size_t)(r0 + 8) * N + c0) =
                    make_float2(acc[mi][ni][2], acc[mi][ni][3]);
            } else {
                *(__half2*)(C1 + (size_t)r0 * N + c0) = __halves2half2(
                    __float2half_rn(acc[mi][ni][0]), __float2half_rn(acc[mi][ni][1]));
                *(__half2*)(C1 + (size_t)(r0 + 8) * N + c0) = __halves2half2(
                    __float2half_rn(acc[mi][ni][2]), __float2half_rn(acc[mi][ni][3]));
            }
        }
}

__global__ __launch_bounds__(256) void gemm_qkv_kernel(
    const __half* __restrict__ x16,
    const __half* __restrict__ wq16, const __half* __restrict__ wk16,
    const __half* __restrict__ wv16,
    __half* __restrict__ q16, __half* __restrict__ k16, __half* __restrict__ v16)
{
    extern __shared__ char smraw[];
    const int bx = blockIdx.x;
    const int bm0 = blockIdx.y * 128;
    if (bx < 16) {
        gemm_core_h(QD, C_DIM, 1, 1, x16, wq16, 0, q16, bm0, bx * 128, smraw);
    } else if (bx < 20) {
        gemm_core_h(KD, C_DIM, 1, 1, x16, wk16, 0, k16, bm0, (bx - 16) * 128, smraw);
    } else {
        gemm_core_h(KD, C_DIM, 0, 1, x16, wv16, 0, v16, bm0, (bx - 20) * 128, smraw);
    }
}

__global__ __launch_bounds__(256) void gemm_out_kernel(
    const __half* __restrict__ att16, const __half* __restrict__ wo16,
    float* __restrict__ out)
{
    extern __shared__ char smraw[];
    gemm_core_h(C_DIM, QD, 0, 0, att16, wo16, out, 0,
                blockIdx.y * 128, blockIdx.x * 128, smraw);
}

// ===========================================================================
// FA2-style flash, single-plane fp16 Q: BQ=128, 8 warps, warp owns 16 q-rows.
// Q register-resident; warp-local softmax; P C-frag->A-frag in registers;
// K/V double-buffered cp.async ring. 2 barriers per tile.
// ===========================================================================
#define FQ 128
#define FKV 64
#define FSTR 136
#define KVSEG (FKV * FSTR)                   // 8704 halfs
#define FLASH_SMEM_BYTES (4 * KVSEG * 2)     // 69632 B

__device__ __forceinline__ void flash_issue_kv(
    const __half* __restrict__ k16, const __half* __restrict__ v16,
    int k0, int kvh, __half* Ks, int tid)
{
    __half* Vs = Ks + KVSEG;
    #pragma unroll
    for (int it = 0; it < 4; it++) {
        int f = it * 256 + tid;
        int r = f >> 4, c = (f & 15) * 8;
        CP_ASYNC16(smem_u32(&Ks[r * FSTR + c]),
                   k16 + (size_t)(k0 + r) * KD + kvh * D_HEAD + c);
    }
    #pragma unroll
    for (int it = 0; it < 4; it++) {
        int f = it * 256 + tid;
        int r = f >> 4, c = (f & 15) * 8;
        CP_ASYNC16(smem_u32(&Vs[r * FSTR + c]),
                   v16 + (size_t)(k0 + r) * KD + kvh * D_HEAD + c);
    }
}

__global__ __launch_bounds__(256, 1) void flash_mma_kernel(
    const __half* __restrict__ q16, const __half* __restrict__ k16,
    const __half* __restrict__ v16, __half* __restrict__ att16)
{
    extern __shared__ char smraw[];
    __half* sm = (__half*)smraw;

    const int tid  = threadIdx.x;
    const int lane = tid & 31;
    const int w    = tid >> 5;
    const int gid  = lane >> 2;
    const int tig  = lane & 3;
    const int qb   = gridDim.x - 1 - blockIdx.x;  // heavy blocks first
    const int h    = blockIdx.y;
    const int kvh  = h / (H_Q / KVH_);
    const int q0   = qb * FQ;
    const float scale = 0.08838834764831845f;

    // ---- stage Q and load into registers ----
    {
        __half* Qs = sm;
        #pragma unroll
        for (int it = 0; it < 8; it++) {
            int f = it * 256 + tid;
            int r = f >> 4, c = (f & 15) * 8;
            CP_ASYNC16(smem_u32(&Qs[r * FSTR + c]),
                       q16 + (size_t)(q0 + r) * QD + h * D_HEAD + c);
        }
        CP_COMMIT();
        CP_WAIT0();
        __syncthreads();
    }
    unsigned qh[8][4];
    {
        __half* Qs = sm;
        const int arl = w * 16 + (lane & 15);
        #pragma unroll
        for (int kk = 0; kk < 8; kk++) {
            const int kcl = kk * 16 + (lane >> 4) * 8;
            ldsm_x4(smem_u32(&Qs[arl * FSTR + kcl]), qh[kk]);
        }
    }
    __syncthreads();   // Q smem now free for the K/V ring

    float accO[16][4];
    #pragma unroll
    for (int df = 0; df < 16; df++)
        #pragma unroll
        for (int e = 0; e < 4; e++) accO[df][e] = 0.f;
    float m0 = -1e30f, m1 = -1e30f, l0 = 0.f, l1 = 0.f;

    const int row0 = q0 + w * 16 + gid;   // this thread's rows: row0, row0+8
    const int ntiles = 2 * qb + 2;

    flash_issue_kv(k16, v16, 0, kvh, sm, tid);
    CP_COMMIT();

    for (int jt = 0; jt < ntiles; jt++) {
        const int k0 = jt * FKV;
        const bool hasnext = (jt + 1 < ntiles);
        if (hasnext) {
            if (jt > 0) __syncthreads();   // all warps done reading buf[(jt+1)&1]
            flash_issue_kv(k16, v16, (jt + 1) * FKV, kvh,
                           sm + ((jt + 1) & 1) * 2 * KVSEG, tid);
            CP_COMMIT();
            CP_WAIT1();
        } else {
            CP_WAIT0();
        }
        __syncthreads();   // buf[jt&1] visible

        __half* Ks = sm + (jt & 1) * 2 * KVSEG;
        __half* Vs = Ks + KVSEG;

        // ---- S = Q K^T: 16 rows x 64 cols per warp (single-plane Q) ----
        float accS[8][4];
        #pragma unroll
        for (int nf = 0; nf < 8; nf++)
            #pragma unroll
            for (int e = 0; e < 4; e++) accS[nf][e] = 0.f;

        #pragma unroll
        for (int kk = 0; kk < 8; kk++) {
            const int kcl = kk * 16 + (lane >> 4) * 8;
            unsigned bh[8][2];
            #pragma unroll
            for (int nb = 0; nb < 4; nb++) {
                const int brl = nb * 16 + (lane & 15);
                unsigned r[4];
                ldsm_x4(smem_u32(&Ks[brl * FSTR + kcl]), r);
                bh[2 * nb][0] = r[0]; bh[2 * nb][1] = r[2];
                bh[2 * nb + 1][0] = r[1]; bh[2 * nb + 1][1] = r[3];
            }
            #pragma unroll
            for (int nf = 0; nf < 8; nf++)
                mma_f16(accS[nf], qh[kk], bh[nf]);
        }

        // ---- warp-local softmax (registers + quad shfl) ----
        const bool needmask = (k0 + FKV - 1 > q0);
        float mt0 = -1e30f, mt1 = -1e30f;
        #pragma unroll
        for (int nf = 0; nf < 8; nf++)
            #pragma unroll
            for (int e = 0; e < 2; e++) {
                int col = k0 + nf * 8 + 2 * tig + e;
                float s = accS[nf][e] * scale;
                if (needmask && col > row0) s = -1e30f;
                accS[nf][e] = s;
                mt0 = fmaxf(mt0, s);
                float s2 = accS[nf][2 + e] * scale;
                if (needmask && col > row0 + 8) s2 = -1e30f;
                accS[nf][2 + e] = s2;
                mt1 = fmaxf(mt1, s2);
            }
        mt0 = fmaxf(mt0, __shfl_xor_sync(0xffffffffu, mt0, 1));
        mt0 = fmaxf(mt0, __shfl_xor_sync(0xffffffffu, mt0, 2));
        mt1 = fmaxf(mt1, __shfl_xor_sync(0xffffffffu, mt1, 1));
        mt1 = fmaxf(mt1, __shfl_xor_sync(0xffffffffu, mt1, 2));
        float mn0 = fmaxf(m0, mt0), mn1 = fmaxf(m1, mt1);
        float al0 = __expf(m0 - mn0), al1 = __expf(m1 - mn1);
        m0 = mn0; m1 = mn1;

        unsigned ph2[8][2];
        float s0 = 0.f, s1 = 0.f;
        #pragma unroll
        for (int nf = 0; nf < 8; nf++) {
            float p00 = __expf(accS[nf][0] - mn0);
            float p01 = __expf(accS[nf][1] - mn0);
            float p10 = __expf(accS[nf][2] - mn1);
            float p11 = __expf(accS[nf][3] - mn1);
            __half h00 = __float2half_rn(p00), h01 = __float2half_rn(p01);
            __half h10 = __float2half_rn(p10), h11 = __float2half_rn(p11);
            __half2 t0 = __halves2half2(h00, h01);
            __half2 t1 = __halves2half2(h10, h11);
            ph2[nf][0] = *(unsigned*)&t0;
            ph2[nf][1] = *(unsigned*)&t1;
            s0 += __half2float(h00) + __half2float(h01);
            s1 += __half2float(h10) + __half2float(h11);
        }
        s0 += __shfl_xor_sync(0xffffffffu, s0, 1);
        s0 += __shfl_xor_sync(0xffffffffu, s0, 2);
        s1 += __shfl_xor_sync(0xffffffffu, s1, 1);
        s1 += __shfl_xor_sync(0xffffffffu, s1, 2);
        l0 = l0 * al0 + s0;
        l1 = l1 * al1 + s1;

        #pragma unroll
        for (int df = 0; df < 16; df++) {
            accO[df][0] *= al0; accO[df][1] *= al0;
            accO[df][2] *= al1; accO[df][3] *= al1;
        }

        // ---- O += P V: P from C-frag -> A-frag in registers ----
        #pragma unroll
        for (int jk = 0; jk < 4; jk++) {
            unsigned pa[4] = { ph2[2 * jk][0], ph2[2 * jk][1],
                               ph2[2 * jk + 1][0], ph2[2 * jk + 1][1] };
            const int krw = jk * 16 + ((lane >> 3) & 1) * 8 + (lane & 7);
            #pragma unroll
            for (int nb = 0; nb < 8; nb++) {
                const int ncl = nb * 16 + (lane >> 4) * 8;
                unsigned r[4];
                ldsm_x4_t(smem_u32(&Vs[krw * FSTR + ncl]), r);
                unsigned b0[2] = { r[0], r[1] };
                unsigned b1[2] = { r[2], r[3] };
                mma_f16(accO[2 * nb], pa, b0);
                mma_f16(accO[2 * nb + 1], pa, b1);
            }
        }
    }

    // ---- epilogue: normalize, store fp16 att ----
    const float i0 = 1.0f / l0, i1 = 1.0f / l1;
    #pragma unroll
    for (int df = 0; df < 16; df++) {
        int c = h * D_HEAD + df * 8 + 2 * tig;
        *(__half2*)(att16 + (size_t)row0 * QD + c) = __halves2half2(
            __float2half_rn(accO[df][0] * i0), __float2half_rn(accO[df][1] * i0));
        *(__half2*)(att16 + (size_t)(row0 + 8) * QD + c) = __halves2half2(
            __float2half_rn(accO[df][2] * i1), __float2half_rn(accO[df][3] * i1));
    }
}

// ---------------------------------------------------------------------------
extern "C" void kernel_launch(void* const* d_in, const int* in_sizes, int n_in,
                              void* d_out, int out_size)
{
    const float* x  = (const float*)d_in[0];
    // d_in[1] = mask (tril) — causality hardcoded, ignored.
    const float* Wq = (const float*)d_in[2];
    const float* Wk = (const float*)d_in[3];
    const float* Wv = (const float*)d_in[4];
    const float* Wo = (const float*)d_in[5];
    float* out = (float*)d_out;

    __half *x16, *wq16, *wk16, *wv16, *wo16, *q16, *k16, *v16, *att16;
    cudaGetSymbolAddress((void**)&x16,  g_x16);
    cudaGetSymbolAddress((void**)&wq16, g_wq16);
    cudaGetSymbolAddress((void**)&wk16, g_wk16);
    cudaGetSymbolAddress((void**)&wv16, g_wv16);
    cudaGetSymbolAddress((void**)&wo16, g_wo16);
    cudaGetSymbolAddress((void**)&q16,  g_q16);
    cudaGetSymbolAddress((void**)&k16,  g_k16);
    cudaGetSymbolAddress((void**)&v16,  g_v16);
    cudaGetSymbolAddress((void**)&att16, g_att16);

    cudaFuncSetAttribute(gemm_qkv_kernel,
                         cudaFuncAttributeMaxDynamicSharedMemorySize, GEMM_SMEM_BYTES);
    cudaFuncSetAttribute(gemm_out_kernel,
                         cudaFuncAttributeMaxDynamicSharedMemorySize, GEMM_SMEM_BYTES);
    cudaFuncSetAttribute(flash_mma_kernel,
                         cudaFuncAttributeMaxDynamicSharedMemorySize, FLASH_SMEM_BYTES);

    // 0. one-time fp32 -> fp16 conversions
    f2h_kernel<<<(T_SEQ * C_DIM / 4 + 255) / 256, 256>>>(x, x16, T_SEQ * C_DIM);
    f2h_kernel<<<(C_DIM * QD / 4 + 255) / 256, 256>>>(Wq, wq16, C_DIM * QD);
    f2h_kernel<<<(C_DIM * KD / 4 + 255) / 256, 256>>>(Wk, wk16, C_DIM * KD);
    f2h_kernel<<<(C_DIM * KD / 4 + 255) / 256, 256>>>(Wv, wv16, C_DIM * KD);
    f2h_kernel<<<(QD * C_DIM / 4 + 255) / 256, 256>>>(Wo, wo16, QD * C_DIM);

    // 1. fused QKV projection + RoPE (fp16 in/out)
    gemm_qkv_kernel<<<dim3(24, 32), 256, GEMM_SMEM_BYTES>>>(
        x16, wq16, wk16, wv16, q16, k16, v16);

    // 2. flash attention (FA2-style, single-plane fp16 Q)
    flash_mma_kernel<<<dim3(T_SEQ / FQ, H_Q), 256, FLASH_SMEM_BYTES>>>(
        q16, k16, v16, att16);

    // 3. output projection (fp16 in, fp32 out)
    gemm_out_kernel<<<dim3(C_DIM / 128, T_SEQ / 128), 256, GEMM_SMEM_BYTES>>>(
        att16, wo16, out);
}